// round 1
// baseline (speedup 1.0000x reference)
#include <cuda_runtime.h>
#include <cstdint>

#define FULLMASK 0xffffffffu
#define MM 3
#define BB 64
#define DD 512
#define DQ 128
#define L2E 1.4426950408889634f
#define INV_SCALE 0.044194173824159216f   /* 1/sqrt(512) */

// ---------------- scratch (static __device__, no allocs) ----------------
__device__ float g_Y4[4 * MM * BB * DD];   // gemm1 split-K partials
__device__ float g_P [MM * BB * DD];       // proj = relu(LN(...))
__device__ float g_H4[4 * MM * BB * DQ];   // gemm2 partials
__device__ float g_HA[MM * BB * DQ];       // hidden = relu(...)
__device__ float g_CW[MM * BB * DD];       // cw pre-activation
__device__ float g_WF[MM * BB * DD];       // weighted features
__device__ float g_WFT[MM * DD * BB];      // wf transposed [i][d][b]
__device__ float g_S [MM * BB];            // row sums of wf[j]
__device__ float g_HS[MM * DD * DD];       // sum_b final' (L2E-scaled) per mode
__device__ float g_ACC1[MM * BB * DD];     // g*attended pass1
__device__ float g_ACC2[MM * BB * DD];     // g*attended pass2

__device__ __forceinline__ float ex2f_(float x) {
    float r; asm("ex2.approx.ftz.f32 %0, %1;" : "=f"(r) : "f"(x)); return r;
}
__device__ __forceinline__ float frcp_(float x) {
    float r; asm("rcp.approx.ftz.f32 %0, %1;" : "=f"(r) : "f"(x)); return r;
}
__device__ __forceinline__ float sigm_(float x) {
    return frcp_(1.0f + ex2f_(-x * L2E));
}

// ---------------- generic NT GEMM (C[b,n] = sum_k X[b,k]W[n,k]), split-K ----------------
// grid: (n_tiles, ksplit, MM), block 256.  BM=64, BN=64, BK=16.
__global__ void gemm_nt_kernel(const float* __restrict__ X, const float* __restrict__ W,
                               float* __restrict__ Cp, int N, int K, int KC)
{
    const int i  = blockIdx.z;
    const int n0 = blockIdx.x * 64;
    const int k0 = blockIdx.y * KC;
    const int tid = threadIdx.x;
    const int tx = tid & 15, ty = tid >> 4;

    __shared__ float As[16][64];
    __shared__ float Bs[16][64];

    const float* Xb = X + (size_t)i * BB * K;
    const float* Wb = W + (size_t)i * N  * K;

    float acc[4][4] = {};
    for (int kk = 0; kk < KC; kk += 16) {
        {
            int r  = tid >> 2;
            int c4 = (tid & 3) * 4;
            float4 xa = *(const float4*)&Xb[(size_t)r * K + k0 + kk + c4];
            As[c4+0][r] = xa.x; As[c4+1][r] = xa.y; As[c4+2][r] = xa.z; As[c4+3][r] = xa.w;
            float4 wa = *(const float4*)&Wb[(size_t)(n0 + r) * K + k0 + kk + c4];
            Bs[c4+0][r] = wa.x; Bs[c4+1][r] = wa.y; Bs[c4+2][r] = wa.z; Bs[c4+3][r] = wa.w;
        }
        __syncthreads();
        #pragma unroll
        for (int p = 0; p < 16; ++p) {
            float4 a4 = *(const float4*)&As[p][ty * 4];
            float4 b4 = *(const float4*)&Bs[p][tx * 4];
            float av[4] = {a4.x, a4.y, a4.z, a4.w};
            float bv[4] = {b4.x, b4.y, b4.z, b4.w};
            #pragma unroll
            for (int m2 = 0; m2 < 4; ++m2)
                #pragma unroll
                for (int n2 = 0; n2 < 4; ++n2)
                    acc[m2][n2] = fmaf(av[m2], bv[n2], acc[m2][n2]);
        }
        __syncthreads();
    }
    float* Cout = Cp + (size_t)blockIdx.y * (MM * BB * (size_t)N) + (size_t)i * BB * N;
    #pragma unroll
    for (int m2 = 0; m2 < 4; ++m2) {
        int b = ty * 4 + m2;
        float4 v = make_float4(acc[m2][0], acc[m2][1], acc[m2][2], acc[m2][3]);
        *(float4*)&Cout[(size_t)b * N + n0 + tx * 4] = v;
    }
}

// ---------------- LN + ReLU (sums 4 split-K partials + bias) ----------------
// grid: MM*BB blocks, 512 threads
__global__ void ln_relu_kernel(const float* __restrict__ pb,
                               const float* __restrict__ lg,
                               const float* __restrict__ lb)
{
    __shared__ float ss[16], sq[16];
    const int i = blockIdx.x >> 6, b = blockIdx.x & 63;
    const int e = threadIdx.x;
    const int warp = e >> 5, lane = e & 31;
    const size_t base = ((size_t)i * BB + b) * DD;

    float y = g_Y4[base + e] + g_Y4[MM*BB*DD + base + e]
            + g_Y4[2*MM*BB*DD + base + e] + g_Y4[3*MM*BB*DD + base + e]
            + pb[i * DD + e];

    float s = y, q = y * y;
    #pragma unroll
    for (int off = 16; off; off >>= 1) {
        s += __shfl_xor_sync(FULLMASK, s, off);
        q += __shfl_xor_sync(FULLMASK, q, off);
    }
    if (lane == 0) { ss[warp] = s; sq[warp] = q; }
    __syncthreads();
    if (warp == 0) {
        float s2 = ss[lane & 15], q2 = sq[lane & 15];
        #pragma unroll
        for (int off = 8; off; off >>= 1) {
            s2 += __shfl_xor_sync(FULLMASK, s2, off);
            q2 += __shfl_xor_sync(FULLMASK, q2, off);
        }
        if (lane == 0) { ss[0] = s2; sq[0] = q2; }
    }
    __syncthreads();
    float mu  = ss[0] * (1.0f / DD);
    float var = sq[0] * (1.0f / DD) - mu * mu;
    float rs  = rsqrtf(var + 1e-5f);
    float p = (y - mu) * rs * lg[i * DD + e] + lb[i * DD + e];
    g_P[base + e] = fmaxf(p, 0.0f);
}

// ---------------- hidden relu(sum partials + b1) ----------------
__global__ void hd_relu_kernel(const float* __restrict__ b1)
{
    int idx = blockIdx.x * blockDim.x + threadIdx.x;   // < MM*BB*DQ
    int i = idx / (BB * DQ);
    int m = idx & (DQ - 1);
    float h = g_H4[idx] + g_H4[MM*BB*DQ + idx] + g_H4[2*MM*BB*DQ + idx]
            + g_H4[3*MM*BB*DQ + idx] + b1[i * DQ + m];
    g_HA[idx] = fmaxf(h, 0.0f);
}

// ---------------- wf = P * sigmoid(CW + b2); also WFT and row sums S ----------------
// grid: MM*BB blocks, 256 threads
__global__ void wf_kernel(const float* __restrict__ b2)
{
    __shared__ float ss[8];
    const int i = blockIdx.x >> 6, b = blockIdx.x & 63;
    const int t = threadIdx.x;
    const int warp = t >> 5, lane = t & 31;
    float part = 0.0f;
    #pragma unroll
    for (int r = 0; r < 2; ++r) {
        int e = t + r * 256;
        size_t idx = ((size_t)i * BB + b) * DD + e;
        float pre = g_CW[idx] + b2[i * DD + e];
        float w = g_P[idx] * sigm_(pre);
        g_WF[idx] = w;
        g_WFT[((size_t)i * DD + e) * BB + b] = w;
        part += w;
    }
    #pragma unroll
    for (int off = 16; off; off >>= 1) part += __shfl_xor_sync(FULLMASK, part, off);
    if (lane == 0) ss[warp] = part;
    __syncthreads();
    if (t == 0) {
        float s = 0.0f;
        #pragma unroll
        for (int w = 0; w < 8; ++w) s += ss[w];
        g_S[i * BB + b] = s;
    }
}

// ---------------- fused pairwise attention ----------------
// grid: (32, MM), block 512 = 16 warps, each warp owns one d.
// pass==0: hist=0, accumulate HS (L2E-scaled batch sum of final), write ACC1
// pass==1: hist = HS/(64*5), write ACC2
__global__ void attn_kernel(const float* __restrict__ gamma,
                            const float* __restrict__ mbias,
                            const float* __restrict__ constraint,
                            int pass)
{
    const int i    = blockIdx.y;
    const int warp = threadIdx.x >> 5;
    const int lane = threadIdx.x & 31;
    const int d    = blockIdx.x * 16 + warp;

    int j;
    if (pass == 0) j = (i == 0) ? 1 : 0;
    else           j = (i == 2) ? 1 : 2;

    const float g  = sigm_(gamma[i * MM + j]);
    const float mb = mbias[i * MM + j];
    const float cL = constraint[i] * L2E;
    const float isc = INV_SCALE * L2E;

    const float* wft = g_WFT + ((size_t)i * DD + d) * BB;
    const float a0 = __ldg(&wft[lane]);
    const float a1 = __ldg(&wft[lane + 32]);
    const float s0 = __ldg(&g_S[j * BB + lane]);
    const float s1 = __ldg(&g_S[j * BB + lane + 32]);

    float hr[16];
    if (pass == 0) {
        #pragma unroll
        for (int q = 0; q < 16; ++q) hr[q] = 0.0f;
    } else {
        const float4* hsr = (const float4*)(g_HS + ((size_t)i * DD + d) * DD);
        #pragma unroll
        for (int k = 0; k < 4; ++k) {
            float4 h4 = __ldg(&hsr[k * 32 + lane]);
            hr[k*4+0] = h4.x * (1.0f / 320.0f);
            hr[k*4+1] = h4.y * (1.0f / 320.0f);
            hr[k*4+2] = h4.z * (1.0f / 320.0f);
            hr[k*4+3] = h4.w * (1.0f / 320.0f);
        }
    }

    const float4* wfj = (const float4*)(g_WF + (size_t)j * BB * DD);
    float* acc = (pass == 0) ? g_ACC1 : g_ACC2;

    for (int b = 0; b < BB; ++b) {
        float av = (b < 32) ? a0 : a1;
        float a  = __shfl_sync(FULLMASK, av, b & 31);
        float sv = (b < 32) ? s0 : s1;
        float sj = __shfl_sync(FULLMASK, sv, b & 31);
        float ap = a * isc;

        float se0 = 0.0f, se1 = 0.0f, dot0 = 0.0f, dot1 = 0.0f;
        const float4* vr = wfj + (size_t)b * 128;

        if (pass == 0) {
            #pragma unroll
            for (int k = 0; k < 4; ++k) {
                float4 v = __ldg(&vr[k * 32 + lane]);
                float vv[4] = {v.x, v.y, v.z, v.w};
                #pragma unroll
                for (int c = 0; c < 4; ++c) {
                    float cur = ap * vv[c];
                    float m = fminf(fmaxf(cur, -cL), cL);
                    float f = fmaf(0.8f, m, 0.2f * cur);
                    hr[k*4+c] += f;
                    float e = ex2f_(f);
                    if (c & 1) { se1 += e; dot1 = fmaf(e, vv[c], dot1); }
                    else       { se0 += e; dot0 = fmaf(e, vv[c], dot0); }
                }
            }
        } else {
            #pragma unroll
            for (int k = 0; k < 4; ++k) {
                float4 v = __ldg(&vr[k * 32 + lane]);
                float vv[4] = {v.x, v.y, v.z, v.w};
                #pragma unroll
                for (int c = 0; c < 4; ++c) {
                    float cur = ap * vv[c];
                    float u = cur - hr[k*4+c];
                    float m = fminf(fmaxf(u, -cL), cL);
                    float f = fmaf(0.2f, u, hr[k*4+c]);
                    f = fmaf(0.8f, m, f);
                    float e = ex2f_(f);
                    if (c & 1) { se1 += e; dot1 = fmaf(e, vv[c], dot1); }
                    else       { se0 += e; dot0 = fmaf(e, vv[c], dot0); }
                }
            }
        }
        float se = se0 + se1, dot = dot0 + dot1;
        #pragma unroll
        for (int off = 16; off; off >>= 1) {
            se  += __shfl_xor_sync(FULLMASK, se,  off);
            dot += __shfl_xor_sync(FULLMASK, dot, off);
        }
        if (lane == 0) {
            float att = dot * frcp_(se) + mb * sj;
            acc[((size_t)i * BB + b) * DD + d] = g * att;
        }
    }

    if (pass == 0) {
        float4* hs = (float4*)(g_HS + ((size_t)i * DD + d) * DD);
        #pragma unroll
        for (int k = 0; k < 4; ++k)
            hs[k * 32 + lane] = make_float4(hr[k*4+0], hr[k*4+1], hr[k*4+2], hr[k*4+3]);
    }
}

// ---------------- final combine + attention weights ----------------
__global__ void combine_kernel(float* __restrict__ out,
                               const float* __restrict__ gamma,
                               int out_size)
{
    int idx = blockIdx.x * blockDim.x + threadIdx.x;  // < 32768
    const int NBD = BB * DD;
    float w = (g_WF[idx] + g_WF[NBD + idx] + g_WF[2*NBD + idx]) * (1.0f / 3.0f);
    float a = (g_ACC1[idx] + g_ACC1[NBD + idx] + g_ACC1[2*NBD + idx]
             + g_ACC2[idx] + g_ACC2[NBD + idx] + g_ACC2[2*NBD + idx]) * (1.0f / 6.0f);
    out[idx] = w + a;

    if (idx < MM && out_size >= NBD + MM) {
        float sc[MM];
        #pragma unroll
        for (int ii = 0; ii < MM; ++ii) {
            int j1 = (ii == 0) ? 1 : 0;
            int j2 = (ii == 2) ? 1 : 2;
            sc[ii] = 0.5f * (sigm_(gamma[ii * MM + j1]) + sigm_(gamma[ii * MM + j2]));
        }
        float mx = fmaxf(sc[0], fmaxf(sc[1], sc[2]));
        float e0 = ex2f_((sc[0] - mx) * L2E);
        float e1 = ex2f_((sc[1] - mx) * L2E);
        float e2 = ex2f_((sc[2] - mx) * L2E);
        float inv = frcp_(e0 + e1 + e2);
        float ei = (idx == 0) ? e0 : ((idx == 1) ? e1 : e2);
        out[NBD + idx] = ei * inv;
    }
}

// ---------------- launch ----------------
extern "C" void kernel_launch(void* const* d_in, const int* in_sizes, int n_in,
                              void* d_out, int out_size)
{
    const float* x      = (const float*)d_in[0];
    const float* proj_W = (const float*)d_in[1];
    const float* proj_b = (const float*)d_in[2];
    const float* ln_g   = (const float*)d_in[3];
    const float* ln_b   = (const float*)d_in[4];
    const float* imp_W1 = (const float*)d_in[5];
    const float* imp_b1 = (const float*)d_in[6];
    const float* imp_W2 = (const float*)d_in[7];
    const float* imp_b2 = (const float*)d_in[8];
    const float* gamma  = (const float*)d_in[9];
    const float* mbias  = (const float*)d_in[10];
    const float* constr = (const float*)d_in[11];
    float* out = (float*)d_out;

    float *pY4, *pP, *pH4, *pHA, *pCW;
    cudaGetSymbolAddress((void**)&pY4, g_Y4);
    cudaGetSymbolAddress((void**)&pP,  g_P);
    cudaGetSymbolAddress((void**)&pH4, g_H4);
    cudaGetSymbolAddress((void**)&pHA, g_HA);
    cudaGetSymbolAddress((void**)&pCW, g_CW);

    // 1) y = x @ proj_W^T  (split-K 4)
    gemm_nt_kernel<<<dim3(8, 4, MM), 256>>>(x, proj_W, pY4, DD, DD, 128);
    // 2) proj = relu(LN(y + b))
    ln_relu_kernel<<<MM * BB, 512>>>(proj_b, ln_g, ln_b);
    // 3) hidden pre = proj @ W1^T (split-K 4)
    gemm_nt_kernel<<<dim3(2, 4, MM), 256>>>(pP, imp_W1, pH4, DQ, DD, 128);
    // 4) hidden = relu(pre + b1)
    hd_relu_kernel<<<(MM * BB * DQ) / 256, 256>>>(imp_b1);
    // 5) cw pre = hidden @ W2^T (K=128, no split)
    gemm_nt_kernel<<<dim3(8, 1, MM), 256>>>(pHA, imp_W2, pCW, DD, DQ, 128);
    // 6) wf = proj * sigmoid(cw + b2); transpose + row sums
    wf_kernel<<<MM * BB, 256>>>(imp_b2);
    // 7) pass 1 (first j per mode): attended + history
    attn_kernel<<<dim3(32, MM), 512>>>(gamma, mbias, constr, 0);
    // 8) pass 2 (second j per mode): uses history
    attn_kernel<<<dim3(32, MM), 512>>>(gamma, mbias, constr, 1);
    // 9) combine
    combine_kernel<<<64, 512>>>(out, gamma, out_size);
}

// round 2
// speedup vs baseline: 1.7916x; 1.7916x over previous
#include <cuda_runtime.h>
#include <cstdint>

#define FULLMASK 0xffffffffu
#define MM 3
#define BB 64
#define DD 512
#define DQ 128
#define L2E 1.4426950408889634f
#define INV_SCALE 0.044194173824159216f   /* 1/sqrt(512) */
#define NS1 8
#define NS2 8

// ---------------- scratch ----------------
__device__ float g_Y8[NS1 * MM * BB * DD];
__device__ float g_P [MM * BB * DD];
__device__ float g_H8[NS2 * MM * BB * DQ];
__device__ float g_CW[MM * BB * DD];
__device__ float g_WF[MM * BB * DD];
__device__ float g_WFT[MM * DD * BB];
__device__ float g_S [MM * BB];
__device__ float g_HS2[2 * MM * DD * DD];   // b-split partial history sums (log2-scaled)
__device__ float g_ACC1[MM * BB * DD];      // pass1 g*attended, [i][b][d]
__device__ float g_ACC2T[MM * DD * BB];     // pass2 g*attended, [i][d][b]

__device__ __forceinline__ float ex2f_(float x) {
    float r; asm("ex2.approx.ftz.f32 %0, %1;" : "=f"(r) : "f"(x)); return r;
}
__device__ __forceinline__ float frcp_(float x) {
    float r; asm("rcp.approx.ftz.f32 %0, %1;" : "=f"(r) : "f"(x)); return r;
}
__device__ __forceinline__ float sigm_(float x) {
    return frcp_(1.0f + ex2f_(-x * L2E));
}

// ---------------- generic NT GEMM (C[b,n] = sum_k X[b,k]W[n,k]), split-K ----------------
// grid: (n_tiles, ksplit, MM), block 256.  BM=64, BN=64, BK=16.
__global__ void gemm_nt_kernel(const float* __restrict__ X, const float* __restrict__ W,
                               float* __restrict__ Cp, int N, int K, int KC)
{
    const int i  = blockIdx.z;
    const int n0 = blockIdx.x * 64;
    const int k0 = blockIdx.y * KC;
    const int tid = threadIdx.x;
    const int tx = tid & 15, ty = tid >> 4;

    __shared__ float As[16][64];
    __shared__ float Bs[16][64];

    const float* Xb = X + (size_t)i * BB * K;
    const float* Wb = W + (size_t)i * N  * K;

    float acc[4][4] = {};
    for (int kk = 0; kk < KC; kk += 16) {
        {
            int r  = tid >> 2;
            int c4 = (tid & 3) * 4;
            float4 xa = *(const float4*)&Xb[(size_t)r * K + k0 + kk + c4];
            As[c4+0][r] = xa.x; As[c4+1][r] = xa.y; As[c4+2][r] = xa.z; As[c4+3][r] = xa.w;
            float4 wa = *(const float4*)&Wb[(size_t)(n0 + r) * K + k0 + kk + c4];
            Bs[c4+0][r] = wa.x; Bs[c4+1][r] = wa.y; Bs[c4+2][r] = wa.z; Bs[c4+3][r] = wa.w;
        }
        __syncthreads();
        #pragma unroll
        for (int p = 0; p < 16; ++p) {
            float4 a4 = *(const float4*)&As[p][ty * 4];
            float4 b4 = *(const float4*)&Bs[p][tx * 4];
            float av[4] = {a4.x, a4.y, a4.z, a4.w};
            float bv[4] = {b4.x, b4.y, b4.z, b4.w};
            #pragma unroll
            for (int m2 = 0; m2 < 4; ++m2)
                #pragma unroll
                for (int n2 = 0; n2 < 4; ++n2)
                    acc[m2][n2] = fmaf(av[m2], bv[n2], acc[m2][n2]);
        }
        __syncthreads();
    }
    float* Cout = Cp + (size_t)blockIdx.y * (MM * BB * (size_t)N) + (size_t)i * BB * N;
    #pragma unroll
    for (int m2 = 0; m2 < 4; ++m2) {
        int b = ty * 4 + m2;
        float4 v = make_float4(acc[m2][0], acc[m2][1], acc[m2][2], acc[m2][3]);
        *(float4*)&Cout[(size_t)b * N + n0 + tx * 4] = v;
    }
}

// ---------------- LN + ReLU (sums NS1 split-K partials + bias) ----------------
// grid: MM*BB blocks, 512 threads
__global__ void ln_relu_kernel(const float* __restrict__ pb,
                               const float* __restrict__ lg,
                               const float* __restrict__ lb)
{
    __shared__ float ss[16], sq[16];
    const int i = blockIdx.x >> 6, b = blockIdx.x & 63;
    const int e = threadIdx.x;
    const int warp = e >> 5, lane = e & 31;
    const size_t base = ((size_t)i * BB + b) * DD;

    float y = pb[i * DD + e];
    #pragma unroll
    for (int s = 0; s < NS1; ++s)
        y += g_Y8[(size_t)s * MM * BB * DD + base + e];

    float s = y, q = y * y;
    #pragma unroll
    for (int off = 16; off; off >>= 1) {
        s += __shfl_xor_sync(FULLMASK, s, off);
        q += __shfl_xor_sync(FULLMASK, q, off);
    }
    if (lane == 0) { ss[warp] = s; sq[warp] = q; }
    __syncthreads();
    if (warp == 0) {
        float s2 = ss[lane & 15], q2 = sq[lane & 15];
        #pragma unroll
        for (int off = 8; off; off >>= 1) {
            s2 += __shfl_xor_sync(FULLMASK, s2, off);
            q2 += __shfl_xor_sync(FULLMASK, q2, off);
        }
        if (lane == 0) { ss[0] = s2; sq[0] = q2; }
    }
    __syncthreads();
    float mu  = ss[0] * (1.0f / DD);
    float var = sq[0] * (1.0f / DD) - mu * mu;
    float rs  = rsqrtf(var + 1e-5f);
    float p = (y - mu) * rs * lg[i * DD + e] + lb[i * DD + e];
    g_P[base + e] = fmaxf(p, 0.0f);
}

// ---------------- cw GEMM: C[b,n] = sum_k relu(hpre[b,k]) W2[n,k] ----------------
// hpre assembled on the fly from NS2 split-K partials + b1.
// BM=64, BN=32, BK=16.  grid (16, 1, MM), block 256.
__global__ void gemm_cw_kernel(const float* __restrict__ W2, const float* __restrict__ b1)
{
    const int i  = blockIdx.z;
    const int n0 = blockIdx.x * 32;
    const int tid = threadIdx.x;
    const int tx = tid & 7, ty = tid >> 3;   // ty: 0..31 (2 b rows), tx: 0..7 (4 n cols)

    __shared__ float As[16][64];
    __shared__ float Bs[16][32];

    const float* Wb = W2 + (size_t)i * DD * DQ;

    float acc[2][4] = {};
    for (int kk = 0; kk < DQ; kk += 16) {
        {
            int r  = tid >> 2;           // 0..63 (b row)
            int c4 = (tid & 3) * 4;      // k within chunk
            size_t hb = ((size_t)i * BB + r) * DQ + kk + c4;
            float4 v = *(const float4*)&b1[i * DQ + kk + c4];
            #pragma unroll
            for (int s = 0; s < NS2; ++s) {
                float4 h = *(const float4*)&g_H8[(size_t)s * MM * BB * DQ + hb];
                v.x += h.x; v.y += h.y; v.z += h.z; v.w += h.w;
            }
            As[c4+0][r] = fmaxf(v.x, 0.0f); As[c4+1][r] = fmaxf(v.y, 0.0f);
            As[c4+2][r] = fmaxf(v.z, 0.0f); As[c4+3][r] = fmaxf(v.w, 0.0f);
            if (tid < 128) {
                int r2 = tid >> 2;       // 0..31 (n row)
                float4 w = *(const float4*)&Wb[(size_t)(n0 + r2) * DQ + kk + c4];
                Bs[c4+0][r2] = w.x; Bs[c4+1][r2] = w.y; Bs[c4+2][r2] = w.z; Bs[c4+3][r2] = w.w;
            }
        }
        __syncthreads();
        #pragma unroll
        for (int p = 0; p < 16; ++p) {
            float a0 = As[p][ty * 2], a1 = As[p][ty * 2 + 1];
            float4 b4 = *(const float4*)&Bs[p][tx * 4];
            float bv[4] = {b4.x, b4.y, b4.z, b4.w};
            #pragma unroll
            for (int n2 = 0; n2 < 4; ++n2) {
                acc[0][n2] = fmaf(a0, bv[n2], acc[0][n2]);
                acc[1][n2] = fmaf(a1, bv[n2], acc[1][n2]);
            }
        }
        __syncthreads();
    }
    #pragma unroll
    for (int m2 = 0; m2 < 2; ++m2) {
        int b = ty * 2 + m2;
        float4 v = make_float4(acc[m2][0], acc[m2][1], acc[m2][2], acc[m2][3]);
        *(float4*)&g_CW[((size_t)i * BB + b) * DD + n0 + tx * 4] = v;
    }
}

// ---------------- wf = P * sigmoid(CW + b2); also WFT and row sums S ----------------
// grid: MM*BB blocks, 256 threads
__global__ void wf_kernel(const float* __restrict__ b2)
{
    __shared__ float ss[8];
    const int i = blockIdx.x >> 6, b = blockIdx.x & 63;
    const int t = threadIdx.x;
    const int warp = t >> 5, lane = t & 31;
    float part = 0.0f;
    #pragma unroll
    for (int r = 0; r < 2; ++r) {
        int e = t + r * 256;
        size_t idx = ((size_t)i * BB + b) * DD + e;
        float pre = g_CW[idx] + b2[i * DD + e];
        float w = g_P[idx] * sigm_(pre);
        g_WF[idx] = w;
        g_WFT[((size_t)i * DD + e) * BB + b] = w;
        part += w;
    }
    #pragma unroll
    for (int off = 16; off; off >>= 1) part += __shfl_xor_sync(FULLMASK, part, off);
    if (lane == 0) ss[warp] = part;
    __syncthreads();
    if (t == 0) {
        float s = 0.0f;
        #pragma unroll
        for (int w = 0; w < 8; ++w) s += ss[w];
        g_S[i * BB + b] = s;
    }
}

// ---------------- attention pass 1 (hist = 0, accumulate HS partials) ----------------
// grid (64, 2, MM), block 256 = 8 warps; warp owns d, handles 32 b's (b-split).
// lanes split e 16-wide.
__global__ void attn0_kernel(const float* __restrict__ gamma,
                             const float* __restrict__ mbias,
                             const float* __restrict__ constraint)
{
    const int i    = blockIdx.z;
    const int warp = threadIdx.x >> 5;
    const int lane = threadIdx.x & 31;
    const int d    = blockIdx.x * 8 + warp;
    const int bs   = blockIdx.y * 32;
    const int j    = (i == 0) ? 1 : 0;

    const float g  = sigm_(gamma[i * MM + j]);
    const float mb = mbias[i * MM + j];
    const float cL = constraint[i] * L2E;
    const float isc = INV_SCALE * L2E;

    const float a0 = __ldg(&g_WFT[((size_t)i * DD + d) * BB + bs + lane]);
    const float s0 = __ldg(&g_S[j * BB + bs + lane]);

    float hr[16];
    #pragma unroll
    for (int q = 0; q < 16; ++q) hr[q] = 0.0f;

    for (int bi = 0; bi < 32; ++bi) {
        const int b = bs + bi;
        float a  = __shfl_sync(FULLMASK, a0, bi);
        float sj = __shfl_sync(FULLMASK, s0, bi);
        float ap = a * isc;

        float se0 = 0.0f, se1 = 0.0f, dot0 = 0.0f, dot1 = 0.0f;
        const float4* vr = (const float4*)(g_WF + ((size_t)j * BB + b) * DD);

        #pragma unroll
        for (int k = 0; k < 4; ++k) {
            float4 v = __ldg(&vr[k * 32 + lane]);
            float vv[4] = {v.x, v.y, v.z, v.w};
            #pragma unroll
            for (int c = 0; c < 4; ++c) {
                float cur = ap * vv[c];
                float m = fminf(fmaxf(cur, -cL), cL);
                float f = fmaf(0.8f, m, 0.2f * cur);
                hr[k*4+c] += f;
                float e = ex2f_(f);
                if (c & 1) { se1 += e; dot1 = fmaf(e, vv[c], dot1); }
                else       { se0 += e; dot0 = fmaf(e, vv[c], dot0); }
            }
        }
        float se = se0 + se1, dot = dot0 + dot1;
        #pragma unroll
        for (int off = 16; off; off >>= 1) {
            se  += __shfl_xor_sync(FULLMASK, se,  off);
            dot += __shfl_xor_sync(FULLMASK, dot, off);
        }
        if (lane == 0) {
            float att = dot * frcp_(se) + mb * sj;
            g_ACC1[((size_t)i * BB + b) * DD + d] = g * att;
        }
    }

    float4* hs = (float4*)(g_HS2 + (((size_t)blockIdx.y * MM + i) * DD + d) * DD);
    #pragma unroll
    for (int k = 0; k < 4; ++k)
        hs[k * 32 + lane] = make_float4(hr[k*4+0], hr[k*4+1], hr[k*4+2], hr[k*4+3]);
}

// ---------------- attention pass 2 (lane = b, shuffle-free) ----------------
// grid (64, 2, MM), block 256 = 8 warps; warp owns d + b-half; lane owns one b.
__global__ void attn2_kernel(const float* __restrict__ gamma,
                             const float* __restrict__ mbias,
                             const float* __restrict__ constraint)
{
    __shared__ float hsm[8 * 512];
    const int i    = blockIdx.z;
    const int warp = threadIdx.x >> 5;
    const int lane = threadIdx.x & 31;
    const int d    = blockIdx.x * 8 + warp;
    const int b    = blockIdx.y * 32 + lane;
    const int j    = (i == 2) ? 1 : 2;

    const float g  = sigm_(gamma[i * MM + j]);
    const float mb = mbias[i * MM + j];
    const float cL = constraint[i] * L2E;
    const float isc = INV_SCALE * L2E;

    // stage combined history (log2 domain, /320) into this warp's smem row
    {
        const float4* h0 = (const float4*)(g_HS2 + ((size_t)i * DD + d) * DD);
        const float4* h1 = (const float4*)(g_HS2 + (((size_t)MM + i) * DD + d) * DD);
        float4* hw = (float4*)(hsm + warp * 512);
        #pragma unroll
        for (int q = 0; q < 4; ++q) {
            float4 u = __ldg(&h0[q * 32 + lane]);
            float4 v = __ldg(&h1[q * 32 + lane]);
            hw[q * 32 + lane] = make_float4((u.x + v.x) * (1.0f/320.0f),
                                            (u.y + v.y) * (1.0f/320.0f),
                                            (u.z + v.z) * (1.0f/320.0f),
                                            (u.w + v.w) * (1.0f/320.0f));
        }
    }
    __syncwarp();

    const float ap = __ldg(&g_WFT[((size_t)i * DD + d) * BB + b]) * isc;
    const float sj = __ldg(&g_S[j * BB + b]);
    const float* vp = g_WFT + (size_t)j * DD * BB + b;
    const float4* hw = (const float4*)(hsm + warp * 512);

    float se0 = 0.0f, se1 = 0.0f, dot0 = 0.0f, dot1 = 0.0f;
    #pragma unroll 4
    for (int e4 = 0; e4 < 128; ++e4) {
        float4 h4 = hw[e4];                       // LDS.128 broadcast (warp-uniform)
        float hv[4] = {h4.x, h4.y, h4.z, h4.w};
        #pragma unroll
        for (int c = 0; c < 4; ++c) {
            float v = __ldg(vp + (size_t)(e4 * 4 + c) * BB);
            float u = fmaf(ap, v, -hv[c]);        // cur - h in one fma
            float m = fminf(fmaxf(u, -cL), cL);
            float t = fmaf(0.2f, u, hv[c]);
            float f = fmaf(0.8f, m, t);
            float e = ex2f_(f);
            if (c & 1) { se1 += e; dot1 = fmaf(e, v, dot1); }
            else       { se0 += e; dot0 = fmaf(e, v, dot0); }
        }
    }
    float se = se0 + se1, dot = dot0 + dot1;
    float att = dot * frcp_(se) + mb * sj;
    g_ACC2T[((size_t)i * DD + d) * BB + b] = g * att;
}

// ---------------- final combine + attention weights ----------------
__global__ void combine_kernel(float* __restrict__ out,
                               const float* __restrict__ gamma,
                               int out_size)
{
    int idx = blockIdx.x * blockDim.x + threadIdx.x;  // < 32768
    const int NBD = BB * DD;
    const int b = idx >> 9, d = idx & 511;
    float w = (g_WF[idx] + g_WF[NBD + idx] + g_WF[2*NBD + idx]) * (1.0f / 3.0f);
    float a = g_ACC1[idx] + g_ACC1[NBD + idx] + g_ACC1[2*NBD + idx];
    #pragma unroll
    for (int i = 0; i < MM; ++i)
        a += g_ACC2T[((size_t)i * DD + d) * BB + b];
    out[idx] = w + a * (1.0f / 6.0f);

    if (idx < MM && out_size >= NBD + MM) {
        float sc[MM];
        #pragma unroll
        for (int ii = 0; ii < MM; ++ii) {
            int j1 = (ii == 0) ? 1 : 0;
            int j2 = (ii == 2) ? 1 : 2;
            sc[ii] = 0.5f * (sigm_(gamma[ii * MM + j1]) + sigm_(gamma[ii * MM + j2]));
        }
        float mx = fmaxf(sc[0], fmaxf(sc[1], sc[2]));
        float e0 = ex2f_((sc[0] - mx) * L2E);
        float e1 = ex2f_((sc[1] - mx) * L2E);
        float e2 = ex2f_((sc[2] - mx) * L2E);
        float inv = frcp_(e0 + e1 + e2);
        float ei = (idx == 0) ? e0 : ((idx == 1) ? e1 : e2);
        out[NBD + idx] = ei * inv;
    }
}

// ---------------- launch ----------------
extern "C" void kernel_launch(void* const* d_in, const int* in_sizes, int n_in,
                              void* d_out, int out_size)
{
    const float* x      = (const float*)d_in[0];
    const float* proj_W = (const float*)d_in[1];
    const float* proj_b = (const float*)d_in[2];
    const float* ln_g   = (const float*)d_in[3];
    const float* ln_b   = (const float*)d_in[4];
    const float* imp_W1 = (const float*)d_in[5];
    const float* imp_b1 = (const float*)d_in[6];
    const float* imp_W2 = (const float*)d_in[7];
    const float* imp_b2 = (const float*)d_in[8];
    const float* gamma  = (const float*)d_in[9];
    const float* mbias  = (const float*)d_in[10];
    const float* constr = (const float*)d_in[11];
    float* out = (float*)d_out;

    float *pY8, *pP, *pH8;
    cudaGetSymbolAddress((void**)&pY8, g_Y8);
    cudaGetSymbolAddress((void**)&pP,  g_P);
    cudaGetSymbolAddress((void**)&pH8, g_H8);

    // 1) y = x @ proj_W^T (split-K 8, 192 blocks)
    gemm_nt_kernel<<<dim3(8, NS1, MM), 256>>>(x, proj_W, pY8, DD, DD, DD / NS1);
    // 2) proj = relu(LN(sum + b))
    ln_relu_kernel<<<MM * BB, 512>>>(proj_b, ln_g, ln_b);
    // 3) hidden pre = proj @ W1^T (split-K 8, 48 blocks)
    gemm_nt_kernel<<<dim3(2, NS2, MM), 256>>>(pP, imp_W1, pH8, DQ, DD, DD / NS2);
    // 4) cw = relu(hidden) @ W2^T with fused partial-sum+bias+relu load (48 blocks)
    gemm_cw_kernel<<<dim3(16, 1, MM), 256>>>(imp_W2, imp_b1);
    // 5) wf = proj * sigmoid(cw + b2); transpose + row sums
    wf_kernel<<<MM * BB, 256>>>(imp_b2);
    // 6) pass 1 (first j per mode), b-split 2 -> 384 blocks
    attn0_kernel<<<dim3(64, 2, MM), 256>>>(gamma, mbias, constr);
    // 7) pass 2 (second j per mode), lane=b shuffle-free, 384 blocks
    attn2_kernel<<<dim3(64, 2, MM), 256>>>(gamma, mbias, constr);
    // 8) combine
    combine_kernel<<<64, 512>>>(out, gamma, out_size);
}

// round 3
// speedup vs baseline: 1.8277x; 1.0202x over previous
#include <cuda_runtime.h>
#include <cstdint>

#define FULLMASK 0xffffffffu
#define MM 3
#define BB 64
#define DD 512
#define DQ 128
#define L2E 1.4426950408889634f
#define INV_SCALE 0.044194173824159216f   /* 1/sqrt(512) */
#define NS1 8

// ---------------- scratch ----------------
__device__ float g_Y8[NS1 * MM * BB * DD];
__device__ float g_P [MM * BB * DD];
__device__ float g_HA[MM * BB * DQ];       // hidden = relu(P@W1^T + b1)
__device__ float g_WF[MM * BB * DD];
__device__ float g_WFT[MM * DD * BB];
__device__ float g_S [MM * BB];
__device__ float g_A1[MM * BB * DD];       // pass1 g*attended [i][b][d]
__device__ float g_A2[MM * BB * DD];       // pass2 g*attended [i][b][d]

__device__ __forceinline__ float ex2f_(float x) {
    float r; asm("ex2.approx.ftz.f32 %0, %1;" : "=f"(r) : "f"(x)); return r;
}
__device__ __forceinline__ float frcp_(float x) {
    float r; asm("rcp.approx.ftz.f32 %0, %1;" : "=f"(r) : "f"(x)); return r;
}
__device__ __forceinline__ float sigm_(float x) {
    return frcp_(1.0f + ex2f_(-x * L2E));
}

// ---------------- GEMM1: y = x @ proj_W^T, split-K ----------------
// grid: (8 n-tiles, NS1, MM), block 256.  BM=64, BN=64, BK=16.
__global__ void gemm_nt_kernel(const float* __restrict__ X, const float* __restrict__ W,
                               float* __restrict__ Cp, int N, int K, int KC)
{
    const int i  = blockIdx.z;
    const int n0 = blockIdx.x * 64;
    const int k0 = blockIdx.y * KC;
    const int tid = threadIdx.x;
    const int tx = tid & 15, ty = tid >> 4;

    __shared__ float As[16][64];
    __shared__ float Bs[16][64];

    const float* Xb = X + (size_t)i * BB * K;
    const float* Wb = W + (size_t)i * N  * K;

    float acc[4][4] = {};
    for (int kk = 0; kk < KC; kk += 16) {
        {
            int r  = tid >> 2;
            int c4 = (tid & 3) * 4;
            float4 xa = *(const float4*)&Xb[(size_t)r * K + k0 + kk + c4];
            As[c4+0][r] = xa.x; As[c4+1][r] = xa.y; As[c4+2][r] = xa.z; As[c4+3][r] = xa.w;
            float4 wa = *(const float4*)&Wb[(size_t)(n0 + r) * K + k0 + kk + c4];
            Bs[c4+0][r] = wa.x; Bs[c4+1][r] = wa.y; Bs[c4+2][r] = wa.z; Bs[c4+3][r] = wa.w;
        }
        __syncthreads();
        #pragma unroll
        for (int p = 0; p < 16; ++p) {
            float4 a4 = *(const float4*)&As[p][ty * 4];
            float4 b4 = *(const float4*)&Bs[p][tx * 4];
            float av[4] = {a4.x, a4.y, a4.z, a4.w};
            float bv[4] = {b4.x, b4.y, b4.z, b4.w};
            #pragma unroll
            for (int m2 = 0; m2 < 4; ++m2)
                #pragma unroll
                for (int n2 = 0; n2 < 4; ++n2)
                    acc[m2][n2] = fmaf(av[m2], bv[n2], acc[m2][n2]);
        }
        __syncthreads();
    }
    float* Cout = Cp + (size_t)blockIdx.y * (MM * BB * (size_t)N) + (size_t)i * BB * N;
    #pragma unroll
    for (int m2 = 0; m2 < 4; ++m2) {
        int b = ty * 4 + m2;
        float4 v = make_float4(acc[m2][0], acc[m2][1], acc[m2][2], acc[m2][3]);
        *(float4*)&Cout[(size_t)b * N + n0 + tx * 4] = v;
    }
}

// ---------------- LN + ReLU (sums NS1 partials + bias); also zeroes g_S ----------------
__global__ void ln_relu_kernel(const float* __restrict__ pb,
                               const float* __restrict__ lg,
                               const float* __restrict__ lb)
{
    __shared__ float ss[16], sq[16];
    const int i = blockIdx.x >> 6, b = blockIdx.x & 63;
    const int e = threadIdx.x;
    const int warp = e >> 5, lane = e & 31;
    const size_t base = ((size_t)i * BB + b) * DD;

    if (blockIdx.x == 0 && e < MM * BB) g_S[e] = 0.0f;

    float y = pb[i * DD + e];
    #pragma unroll
    for (int s = 0; s < NS1; ++s)
        y += g_Y8[(size_t)s * MM * BB * DD + base + e];

    float s = y, q = y * y;
    #pragma unroll
    for (int off = 16; off; off >>= 1) {
        s += __shfl_xor_sync(FULLMASK, s, off);
        q += __shfl_xor_sync(FULLMASK, q, off);
    }
    if (lane == 0) { ss[warp] = s; sq[warp] = q; }
    __syncthreads();
    if (warp == 0) {
        float s2 = ss[lane & 15], q2 = sq[lane & 15];
        #pragma unroll
        for (int off = 8; off; off >>= 1) {
            s2 += __shfl_xor_sync(FULLMASK, s2, off);
            q2 += __shfl_xor_sync(FULLMASK, q2, off);
        }
        if (lane == 0) { ss[0] = s2; sq[0] = q2; }
    }
    __syncthreads();
    float mu  = ss[0] * (1.0f / DD);
    float var = sq[0] * (1.0f / DD) - mu * mu;
    float rs  = rsqrtf(var + 1e-5f);
    float p = (y - mu) * rs * lg[i * DD + e] + lb[i * DD + e];
    g_P[base + e] = fmaxf(p, 0.0f);
}

// ---------------- HA = relu(P @ W1^T + b1), full K ----------------
// grid (16, MM): blockIdx.x = bt(0..7) | nt(0..1)<<3.  block 128.
__global__ void gemm_hidden_kernel(const float* __restrict__ W1, const float* __restrict__ b1)
{
    const int i  = blockIdx.y;
    const int b0 = (blockIdx.x & 7) * 8;
    const int n0 = (blockIdx.x >> 3) * 64;
    const int tid = threadIdx.x;
    const int tx = tid & 15, ty = tid >> 4;   // ty: b row (0..7), tx: n4 group

    __shared__ __align__(16) float As[32][8];
    __shared__ __align__(16) float Bs[32][64];

    const float* Pb = g_P + (size_t)i * BB * DD;
    const float* Wb = W1 + (size_t)i * DQ * DD;

    float acc[4] = {};
    for (int k0 = 0; k0 < DD; k0 += 32) {
        if (tid < 64) {
            int r = tid >> 3, q = tid & 7;
            float4 v = *(const float4*)&Pb[(size_t)(b0 + r) * DD + k0 + q * 4];
            As[q*4+0][r] = v.x; As[q*4+1][r] = v.y; As[q*4+2][r] = v.z; As[q*4+3][r] = v.w;
        }
        #pragma unroll
        for (int q = 0; q < 4; ++q) {
            int idx = tid * 4 + q;           // 0..511 float4s
            int nr = idx >> 3, kq = idx & 7;
            float4 v = *(const float4*)&Wb[(size_t)(n0 + nr) * DD + k0 + kq * 4];
            Bs[kq*4+0][nr] = v.x; Bs[kq*4+1][nr] = v.y; Bs[kq*4+2][nr] = v.z; Bs[kq*4+3][nr] = v.w;
        }
        __syncthreads();
        #pragma unroll
        for (int k = 0; k < 32; ++k) {
            float a = As[k][ty];
            float4 w4 = *(const float4*)&Bs[k][tx * 4];
            acc[0] = fmaf(a, w4.x, acc[0]);
            acc[1] = fmaf(a, w4.y, acc[1]);
            acc[2] = fmaf(a, w4.z, acc[2]);
            acc[3] = fmaf(a, w4.w, acc[3]);
        }
        __syncthreads();
    }
    float4 o;
    o.x = fmaxf(acc[0] + b1[i*DQ + n0 + tx*4 + 0], 0.0f);
    o.y = fmaxf(acc[1] + b1[i*DQ + n0 + tx*4 + 1], 0.0f);
    o.z = fmaxf(acc[2] + b1[i*DQ + n0 + tx*4 + 2], 0.0f);
    o.w = fmaxf(acc[3] + b1[i*DQ + n0 + tx*4 + 3], 0.0f);
    *(float4*)&g_HA[((size_t)i * BB + b0 + ty) * DQ + n0 + tx * 4] = o;
}

// ---------------- CW = HA @ W2^T, fused wf epilogue ----------------
// grid (16 n-tiles, MM), block 256.  BM=64 (all b), BN=32, K=128 fully staged.
__global__ void gemm_cw_wf_kernel(const float* __restrict__ W2,
                                  const float* __restrict__ b2v)
{
    const int i  = blockIdx.y;
    const int n0 = blockIdx.x * 32;
    const int tid = threadIdx.x;
    const int tx = tid & 7, ty = tid >> 3;   // tx: n4 group (0..7), ty: b (0..31)

    __shared__ __align__(16) float As[DQ][64];   // 32 KB  [k][b]
    __shared__ __align__(16) float Bs[DQ][32];   // 16 KB  [k][n]

    // stage HA[i] (64x128) transposed
    #pragma unroll
    for (int q = 0; q < 8; ++q) {
        int idx = tid + q * 256;             // float4 index, 0..2047
        int b = idx >> 5, kq = idx & 31;
        float4 v = *(const float4*)&g_HA[((size_t)i * BB + b) * DQ + kq * 4];
        As[kq*4+0][b] = v.x; As[kq*4+1][b] = v.y; As[kq*4+2][b] = v.z; As[kq*4+3][b] = v.w;
    }
    // stage W2 tile (32x128) transposed
    #pragma unroll
    for (int q = 0; q < 4; ++q) {
        int idx = tid + q * 256;             // 0..1023
        int nr = idx >> 5, kq = idx & 31;
        float4 v = *(const float4*)&W2[((size_t)i * DD + n0 + nr) * DQ + kq * 4];
        Bs[kq*4+0][nr] = v.x; Bs[kq*4+1][nr] = v.y; Bs[kq*4+2][nr] = v.z; Bs[kq*4+3][nr] = v.w;
    }
    __syncthreads();

    float acc[2][4] = {};
    #pragma unroll 4
    for (int k = 0; k < DQ; ++k) {
        float a0 = As[k][ty];
        float a1 = As[k][ty + 32];
        float4 w4 = *(const float4*)&Bs[k][tx * 4];
        float wv[4] = {w4.x, w4.y, w4.z, w4.w};
        #pragma unroll
        for (int q = 0; q < 4; ++q) {
            acc[0][q] = fmaf(a0, wv[q], acc[0][q]);
            acc[1][q] = fmaf(a1, wv[q], acc[1][q]);
        }
    }

    const int lane = tid & 31;
    #pragma unroll
    for (int rr = 0; rr < 2; ++rr) {
        int b = ty + rr * 32;
        int n = n0 + tx * 4;
        float4 p4 = *(const float4*)&g_P[((size_t)i * BB + b) * DD + n];
        float pv[4] = {p4.x, p4.y, p4.z, p4.w};
        float w[4], srow = 0.0f;
        #pragma unroll
        for (int q = 0; q < 4; ++q) {
            float pre = acc[rr][q] + b2v[i * DD + n + q];
            w[q] = pv[q] * sigm_(pre);
            srow += w[q];
            g_WFT[((size_t)i * DD + n + q) * BB + b] = w[q];
        }
        *(float4*)&g_WF[((size_t)i * BB + b) * DD + n] = make_float4(w[0], w[1], w[2], w[3]);
        #pragma unroll
        for (int off = 4; off; off >>= 1)
            srow += __shfl_xor_sync(FULLMASK, srow, off);
        if (tx == 0) atomicAdd(&g_S[i * BB + b], srow);
    }
}

// ---------------- merged pairwise attention (both passes, hist in regs) ----------------
__shared__ __align__(16) float4 sv_attn[2][8][128];

template<int PASS>
__device__ __forceinline__ void run_pass(int i, int j, int d, int lane, int warp,
                                         float a0, float a1, float (&hr)[16],
                                         float cL, float isc, float g, float mb,
                                         float* __restrict__ accout)
{
    const float* wfj = g_WF + (size_t)j * BB * DD;
    const float s0 = __ldg(&g_S[j * BB + lane]);
    const float s1 = __ldg(&g_S[j * BB + 32 + lane]);

    // prologue: stage chunk 0 (rows warp, warp+4)
    #pragma unroll
    for (int rr = 0; rr < 2; ++rr) {
        int r = warp + rr * 4;
        #pragma unroll
        for (int q = 0; q < 4; ++q)
            sv_attn[0][r][q * 32 + lane] =
                *(const float4*)&wfj[(size_t)r * DD + (q * 32 + lane) * 4];
    }
    __syncthreads();

    for (int c = 0; c < 8; ++c) {
        const int buf = c & 1;
        float4 nx[2][4];
        if (c < 7) {
            #pragma unroll
            for (int rr = 0; rr < 2; ++rr) {
                int r = warp + rr * 4;
                #pragma unroll
                for (int q = 0; q < 4; ++q)
                    nx[rr][q] = *(const float4*)&wfj[(size_t)((c + 1) * 8 + r) * DD
                                                     + (q * 32 + lane) * 4];
            }
        }
        #pragma unroll
        for (int bi = 0; bi < 8; ++bi) {
            const int b = c * 8 + bi;
            float av = (b & 32) ? a1 : a0;
            float a  = __shfl_sync(FULLMASK, av, b & 31);
            float sjv = (b & 32) ? s1 : s0;
            float sj = __shfl_sync(FULLMASK, sjv, b & 31);
            float ap = a * isc;

            float se0 = 0.0f, se1 = 0.0f, dot0 = 0.0f, dot1 = 0.0f;
            #pragma unroll
            for (int k = 0; k < 4; ++k) {
                float4 v = sv_attn[buf][bi][k * 32 + lane];
                float vv[4] = {v.x, v.y, v.z, v.w};
                #pragma unroll
                for (int c2 = 0; c2 < 4; ++c2) {
                    float f;
                    if (PASS == 0) {
                        float cur = ap * vv[c2];
                        float m = fminf(fmaxf(cur, -cL), cL);
                        f = fmaf(0.8f, m, 0.2f * cur);
                        hr[k*4+c2] += f;
                    } else {
                        float h = hr[k*4+c2];
                        float u = fmaf(ap, vv[c2], -h);
                        float m = fminf(fmaxf(u, -cL), cL);
                        float t = fmaf(0.2f, u, h);
                        f = fmaf(0.8f, m, t);
                    }
                    float e = ex2f_(f);
                    if (c2 & 1) { se1 += e; dot1 = fmaf(e, vv[c2], dot1); }
                    else        { se0 += e; dot0 = fmaf(e, vv[c2], dot0); }
                }
            }
            float se = se0 + se1, dot = dot0 + dot1;
            #pragma unroll
            for (int off = 16; off; off >>= 1) {
                se  += __shfl_xor_sync(FULLMASK, se,  off);
                dot += __shfl_xor_sync(FULLMASK, dot, off);
            }
            if (lane == 0)
                accout[(size_t)b * DD + d] = g * (dot * frcp_(se) + mb * sj);
        }
        if (c < 7) {
            #pragma unroll
            for (int rr = 0; rr < 2; ++rr) {
                int r = warp + rr * 4;
                #pragma unroll
                for (int q = 0; q < 4; ++q)
                    sv_attn[buf ^ 1][r][q * 32 + lane] = nx[rr][q];
            }
        }
        __syncthreads();
    }
}

// grid (128, MM), block 128 (4 warps); warp owns one d across all 64 b, both passes.
__global__ void attn_kernel(const float* __restrict__ gamma,
                            const float* __restrict__ mbias,
                            const float* __restrict__ constraint)
{
    const int i    = blockIdx.y;
    const int warp = threadIdx.x >> 5;
    const int lane = threadIdx.x & 31;
    const int d    = blockIdx.x * 4 + warp;
    const int j1 = (i == 0) ? 1 : 0;
    const int j2 = (i == 2) ? 1 : 2;

    const float cL  = constraint[i] * L2E;
    const float isc = INV_SCALE * L2E;
    const float a0 = __ldg(&g_WFT[((size_t)i * DD + d) * BB + lane]);
    const float a1 = __ldg(&g_WFT[((size_t)i * DD + d) * BB + 32 + lane]);

    float hr[16];
    #pragma unroll
    for (int q = 0; q < 16; ++q) hr[q] = 0.0f;

    {
        const float g1 = sigm_(gamma[i * MM + j1]);
        const float m1 = mbias[i * MM + j1];
        run_pass<0>(i, j1, d, lane, warp, a0, a1, hr, cL, isc, g1, m1,
                    g_A1 + (size_t)i * BB * DD);
    }
    #pragma unroll
    for (int q = 0; q < 16; ++q) hr[q] *= (1.0f / 320.0f);
    {
        const float g2 = sigm_(gamma[i * MM + j2]);
        const float m2 = mbias[i * MM + j2];
        run_pass<1>(i, j2, d, lane, warp, a0, a1, hr, cL, isc, g2, m2,
                    g_A2 + (size_t)i * BB * DD);
    }
}

// ---------------- final combine + attention weights ----------------
__global__ void combine_kernel(float* __restrict__ out,
                               const float* __restrict__ gamma,
                               int out_size)
{
    int idx = blockIdx.x * blockDim.x + threadIdx.x;  // < 32768
    const int NBD = BB * DD;
    float w = (g_WF[idx] + g_WF[NBD + idx] + g_WF[2*NBD + idx]) * (1.0f / 3.0f);
    float a = g_A1[idx] + g_A1[NBD + idx] + g_A1[2*NBD + idx]
            + g_A2[idx] + g_A2[NBD + idx] + g_A2[2*NBD + idx];
    out[idx] = w + a * (1.0f / 6.0f);

    if (idx < MM && out_size >= NBD + MM) {
        float sc[MM];
        #pragma unroll
        for (int ii = 0; ii < MM; ++ii) {
            int j1 = (ii == 0) ? 1 : 0;
            int j2 = (ii == 2) ? 1 : 2;
            sc[ii] = 0.5f * (sigm_(gamma[ii * MM + j1]) + sigm_(gamma[ii * MM + j2]));
        }
        float mx = fmaxf(sc[0], fmaxf(sc[1], sc[2]));
        float e0 = ex2f_((sc[0] - mx) * L2E);
        float e1 = ex2f_((sc[1] - mx) * L2E);
        float e2 = ex2f_((sc[2] - mx) * L2E);
        float inv = frcp_(e0 + e1 + e2);
        float ei = (idx == 0) ? e0 : ((idx == 1) ? e1 : e2);
        out[NBD + idx] = ei * inv;
    }
}

// ---------------- launch ----------------
extern "C" void kernel_launch(void* const* d_in, const int* in_sizes, int n_in,
                              void* d_out, int out_size)
{
    const float* x      = (const float*)d_in[0];
    const float* proj_W = (const float*)d_in[1];
    const float* proj_b = (const float*)d_in[2];
    const float* ln_g   = (const float*)d_in[3];
    const float* ln_b   = (const float*)d_in[4];
    const float* imp_W1 = (const float*)d_in[5];
    const float* imp_b1 = (const float*)d_in[6];
    const float* imp_W2 = (const float*)d_in[7];
    const float* imp_b2 = (const float*)d_in[8];
    const float* gamma  = (const float*)d_in[9];
    const float* mbias  = (const float*)d_in[10];
    const float* constr = (const float*)d_in[11];
    float* out = (float*)d_out;

    float *pY8;
    cudaGetSymbolAddress((void**)&pY8, g_Y8);

    // 1) y = x @ proj_W^T (split-K 8, 192 blocks)
    gemm_nt_kernel<<<dim3(8, NS1, MM), 256>>>(x, proj_W, pY8, DD, DD, DD / NS1);
    // 2) proj = relu(LN(sum + b)); zero g_S
    ln_relu_kernel<<<MM * BB, 512>>>(proj_b, ln_g, ln_b);
    // 3) HA = relu(proj @ W1^T + b1), 48 blocks
    gemm_hidden_kernel<<<dim3(16, MM), 128>>>(imp_W1, imp_b1);
    // 4) CW = HA @ W2^T fused with wf epilogue (WF/WFT/S), 48 blocks
    gemm_cw_wf_kernel<<<dim3(16, MM), 256>>>(imp_W2, imp_b2);
    // 5) merged attention, both passes, 384 blocks
    attn_kernel<<<dim3(128, MM), 128>>>(gamma, mbias, constr);
    // 6) combine
    combine_kernel<<<64, 512>>>(out, gamma, out_size);
}

// round 5
// speedup vs baseline: 1.8685x; 1.0223x over previous
#include <cuda_runtime.h>
#include <cstdint>

#define FULLMASK 0xffffffffu
#define MM 3
#define BB 64
#define DD 512
#define DQ 128
#define L2E 1.4426950408889634f
#define INV_SCALE 0.044194173824159216f   /* 1/sqrt(512) */
#define NSPL 4
#define K1_BLOCKS (8 * NSPL * MM)   /* 96 <= 148, co-resident */

// ---------------- scratch ----------------
__device__ float g_Y4[NSPL * MM * BB * DD];
__device__ float g_P [MM * BB * DD];
__device__ float g_HA[MM * BB * DQ];
__device__ float g_WF[MM * BB * DD];
__device__ float g_WFT[MM * DD * BB];
__device__ float g_S [MM * BB];
__device__ float g_A1[MM * BB * DD];
__device__ float g_A2[MM * BB * DD];
__device__ unsigned g_bar1;   // monotonic grid-barrier counter

__device__ __forceinline__ float ex2f_(float x) {
    float r; asm("ex2.approx.ftz.f32 %0, %1;" : "=f"(r) : "f"(x)); return r;
}
__device__ __forceinline__ float frcp_(float x) {
    float r; asm("rcp.approx.ftz.f32 %0, %1;" : "=f"(r) : "f"(x)); return r;
}
__device__ __forceinline__ float sigm_(float x) {
    return frcp_(1.0f + ex2f_(-x * L2E));
}

// ================= K1: gemm1 (split-K 4) + grid barrier + LN/ReLU =================
// grid dim3(8, NSPL, MM) = 96 blocks, 256 threads.
__global__ void k1_gemm1_ln(const float* __restrict__ X, const float* __restrict__ W,
                            const float* __restrict__ pb, const float* __restrict__ lg,
                            const float* __restrict__ lb)
{
    __shared__ float As[16][64];
    __shared__ float Bs[16][64];
    __shared__ float red[18];

    const int i  = blockIdx.z;
    const int n0 = blockIdx.x * 64;
    const int k0 = blockIdx.y * 128;
    const int tid = threadIdx.x;
    const int tx = tid & 15, ty = tid >> 4;

    const float* Xb = X + (size_t)i * BB * DD;
    const float* Wb = W + (size_t)i * DD * DD;

    // ---- phase 1: GEMM partial ----
    float acc[4][4] = {};
    for (int kk = 0; kk < 128; kk += 16) {
        {
            int r  = tid >> 2;
            int c4 = (tid & 3) * 4;
            float4 xa = *(const float4*)&Xb[(size_t)r * DD + k0 + kk + c4];
            As[c4+0][r] = xa.x; As[c4+1][r] = xa.y; As[c4+2][r] = xa.z; As[c4+3][r] = xa.w;
            float4 wa = *(const float4*)&Wb[(size_t)(n0 + r) * DD + k0 + kk + c4];
            Bs[c4+0][r] = wa.x; Bs[c4+1][r] = wa.y; Bs[c4+2][r] = wa.z; Bs[c4+3][r] = wa.w;
        }
        __syncthreads();
        #pragma unroll
        for (int p = 0; p < 16; ++p) {
            float4 a4 = *(const float4*)&As[p][ty * 4];
            float4 b4 = *(const float4*)&Bs[p][tx * 4];
            float av[4] = {a4.x, a4.y, a4.z, a4.w};
            float bv[4] = {b4.x, b4.y, b4.z, b4.w};
            #pragma unroll
            for (int m2 = 0; m2 < 4; ++m2)
                #pragma unroll
                for (int n2 = 0; n2 < 4; ++n2)
                    acc[m2][n2] = fmaf(av[m2], bv[n2], acc[m2][n2]);
        }
        __syncthreads();
    }
    {
        float* Cout = g_Y4 + (size_t)blockIdx.y * (MM * BB * DD) + (size_t)i * BB * DD;
        #pragma unroll
        for (int m2 = 0; m2 < 4; ++m2) {
            int b = ty * 4 + m2;
            float4 v = make_float4(acc[m2][0], acc[m2][1], acc[m2][2], acc[m2][3]);
            *(float4*)&Cout[(size_t)b * DD + n0 + tx * 4] = v;
        }
    }

    // ---- grid barrier (all 96 blocks co-resident) ----
    __threadfence();
    __syncthreads();
    if (tid == 0) {
        unsigned old = atomicAdd(&g_bar1, 1u);
        unsigned target = (old / K1_BLOCKS + 1u) * K1_BLOCKS;
        while ((int)(*(volatile unsigned*)&g_bar1 - target) < 0) {
            __nanosleep(32);
        }
    }
    __syncthreads();

    // ---- phase 2: LN + ReLU, 2 rows per block ----
    const int flat = (blockIdx.z * NSPL + blockIdx.y) * 8 + blockIdx.x;
    const int warp = tid >> 5, lane = tid & 31;
    if (flat == 0 && tid < MM * BB) g_S[tid] = 0.0f;

    #pragma unroll
    for (int rr = 0; rr < 2; ++rr) {
        const int row = flat * 2 + rr;          // 0..191
        const int i2  = row >> 6;
        const size_t base = (size_t)row * DD;
        const int e0 = tid, e1 = tid + 256;

        float y0 = pb[i2 * DD + e0];
        float y1 = pb[i2 * DD + e1];
        #pragma unroll
        for (int s = 0; s < NSPL; ++s) {
            y0 += g_Y4[(size_t)s * MM * BB * DD + base + e0];
            y1 += g_Y4[(size_t)s * MM * BB * DD + base + e1];
        }
        float s = y0 + y1, q = y0 * y0 + y1 * y1;
        #pragma unroll
        for (int off = 16; off; off >>= 1) {
            s += __shfl_xor_sync(FULLMASK, s, off);
            q += __shfl_xor_sync(FULLMASK, q, off);
        }
        if (lane == 0) { red[warp] = s; red[8 + warp] = q; }
        __syncthreads();
        if (warp == 0) {
            float s2 = red[lane & 7], q2 = red[8 + (lane & 7)];
            #pragma unroll
            for (int off = 4; off; off >>= 1) {
                s2 += __shfl_xor_sync(FULLMASK, s2, off);
                q2 += __shfl_xor_sync(FULLMASK, q2, off);
            }
            if (lane == 0) { red[16] = s2; red[17] = q2; }
        }
        __syncthreads();
        float mu  = red[16] * (1.0f / DD);
        float var = red[17] * (1.0f / DD) - mu * mu;
        float rs  = rsqrtf(var + 1e-5f);
        float p0 = (y0 - mu) * rs * lg[i2 * DD + e0] + lb[i2 * DD + e0];
        float p1 = (y1 - mu) * rs * lg[i2 * DD + e1] + lb[i2 * DD + e1];
        g_P[base + e0] = fmaxf(p0, 0.0f);
        g_P[base + e1] = fmaxf(p1, 0.0f);
        __syncthreads();
    }
}

// ================= K2: HA = relu(P @ W1^T + b1) =================
// grid (16, MM): blockIdx.x = bt(0..7) | nt(0..1)<<3.  block 128.
__global__ void gemm_hidden_kernel(const float* __restrict__ W1, const float* __restrict__ b1)
{
    const int i  = blockIdx.y;
    const int b0 = (blockIdx.x & 7) * 8;
    const int n0 = (blockIdx.x >> 3) * 64;
    const int tid = threadIdx.x;
    const int tx = tid & 15, ty = tid >> 4;

    __shared__ __align__(16) float As[32][8];
    __shared__ __align__(16) float Bs[32][64];

    const float* Pb = g_P + (size_t)i * BB * DD;
    const float* Wb = W1 + (size_t)i * DQ * DD;

    float acc[4] = {};
    for (int k0 = 0; k0 < DD; k0 += 32) {
        if (tid < 64) {
            int r = tid >> 3, q = tid & 7;
            float4 v = *(const float4*)&Pb[(size_t)(b0 + r) * DD + k0 + q * 4];
            As[q*4+0][r] = v.x; As[q*4+1][r] = v.y; As[q*4+2][r] = v.z; As[q*4+3][r] = v.w;
        }
        #pragma unroll
        for (int q = 0; q < 4; ++q) {
            int idx = tid * 4 + q;
            int nr = idx >> 3, kq = idx & 7;
            float4 v = *(const float4*)&Wb[(size_t)(n0 + nr) * DD + k0 + kq * 4];
            Bs[kq*4+0][nr] = v.x; Bs[kq*4+1][nr] = v.y; Bs[kq*4+2][nr] = v.z; Bs[kq*4+3][nr] = v.w;
        }
        __syncthreads();
        #pragma unroll
        for (int k = 0; k < 32; ++k) {
            float a = As[k][ty];
            float4 w4 = *(const float4*)&Bs[k][tx * 4];
            acc[0] = fmaf(a, w4.x, acc[0]);
            acc[1] = fmaf(a, w4.y, acc[1]);
            acc[2] = fmaf(a, w4.z, acc[2]);
            acc[3] = fmaf(a, w4.w, acc[3]);
        }
        __syncthreads();
    }
    float4 o;
    o.x = fmaxf(acc[0] + b1[i*DQ + n0 + tx*4 + 0], 0.0f);
    o.y = fmaxf(acc[1] + b1[i*DQ + n0 + tx*4 + 1], 0.0f);
    o.z = fmaxf(acc[2] + b1[i*DQ + n0 + tx*4 + 2], 0.0f);
    o.w = fmaxf(acc[3] + b1[i*DQ + n0 + tx*4 + 3], 0.0f);
    *(float4*)&g_HA[((size_t)i * BB + b0 + ty) * DQ + n0 + tx * 4] = o;
}

// ================= K3: CW = HA @ W2^T + fused wf epilogue =================
// grid (16 n-tiles, MM), block 256.  A[b][k], Bs padded to 36 (16B-aligned rows).
__global__ void gemm_cw_wf_kernel(const float* __restrict__ W2,
                                  const float* __restrict__ b2v)
{
    const int i  = blockIdx.y;
    const int n0 = blockIdx.x * 32;
    const int tid = threadIdx.x;
    const int tx = tid & 7, ty = tid >> 3;   // tx: n4 group (0..7), ty: b (0..31)

    __shared__ __align__(16) float As2[64][DQ];      // [b][k] 32 KB
    __shared__ __align__(16) float Bs[DQ][36];       // [k][n] pad 36 -> 144B rows (16B aligned)

    // stage HA[i] directly (no transpose): coalesced, conflict-free
    #pragma unroll
    for (int q = 0; q < 8; ++q) {
        int idx = tid + q * 256;             // 0..2047 float4s
        int b = idx >> 5, kq = idx & 31;
        float4 v = *(const float4*)&g_HA[((size_t)i * BB + b) * DQ + kq * 4];
        *(float4*)&As2[b][kq * 4] = v;
    }
    // stage W2 tile transposed into padded Bs
    #pragma unroll
    for (int q = 0; q < 4; ++q) {
        int idx = tid + q * 256;             // 0..1023
        int nr = idx >> 5, kq = idx & 31;
        float4 v = *(const float4*)&W2[((size_t)i * DD + n0 + nr) * DQ + kq * 4];
        Bs[kq*4+0][nr] = v.x; Bs[kq*4+1][nr] = v.y; Bs[kq*4+2][nr] = v.z; Bs[kq*4+3][nr] = v.w;
    }
    __syncthreads();

    float acc[2][4] = {};
    #pragma unroll 8
    for (int k4 = 0; k4 < 32; ++k4) {
        float4 a0 = *(const float4*)&As2[ty][k4 * 4];
        float4 a1 = *(const float4*)&As2[ty + 32][k4 * 4];
        float av0[4] = {a0.x, a0.y, a0.z, a0.w};
        float av1[4] = {a1.x, a1.y, a1.z, a1.w};
        #pragma unroll
        for (int q = 0; q < 4; ++q) {
            float4 b4 = *(const float4*)&Bs[k4 * 4 + q][tx * 4];
            float bv[4] = {b4.x, b4.y, b4.z, b4.w};
            #pragma unroll
            for (int n2 = 0; n2 < 4; ++n2) {
                acc[0][n2] = fmaf(av0[q], bv[n2], acc[0][n2]);
                acc[1][n2] = fmaf(av1[q], bv[n2], acc[1][n2]);
            }
        }
    }

    #pragma unroll
    for (int rr = 0; rr < 2; ++rr) {
        int b = ty + rr * 32;
        int n = n0 + tx * 4;
        float4 p4 = *(const float4*)&g_P[((size_t)i * BB + b) * DD + n];
        float pv[4] = {p4.x, p4.y, p4.z, p4.w};
        float w[4], srow = 0.0f;
        #pragma unroll
        for (int q = 0; q < 4; ++q) {
            float pre = acc[rr][q] + b2v[i * DD + n + q];
            w[q] = pv[q] * sigm_(pre);
            srow += w[q];
            g_WFT[((size_t)i * DD + n + q) * BB + b] = w[q];
        }
        *(float4*)&g_WF[((size_t)i * BB + b) * DD + n] = make_float4(w[0], w[1], w[2], w[3]);
        #pragma unroll
        for (int off = 4; off; off >>= 1)
            srow += __shfl_xor_sync(FULLMASK, srow, off);
        if (tx == 0) atomicAdd(&g_S[i * BB + b], srow);
    }
}

// ================= K4: merged pairwise attention (both passes) =================
__shared__ __align__(16) float4 sv_attn[2][8][128];

template<int PASS>
__device__ __forceinline__ void run_pass(int i, int j, int d, int lane, int warp,
                                         float a0, float a1, float (&hr)[16],
                                         float cL, float isc, float g, float mb,
                                         float* __restrict__ accout)
{
    const float* wfj = g_WF + (size_t)j * BB * DD;
    const float s0 = __ldg(&g_S[j * BB + lane]);
    const float s1 = __ldg(&g_S[j * BB + 32 + lane]);

    #pragma unroll
    for (int rr = 0; rr < 2; ++rr) {
        int r = warp + rr * 4;
        #pragma unroll
        for (int q = 0; q < 4; ++q)
            sv_attn[0][r][q * 32 + lane] =
                *(const float4*)&wfj[(size_t)r * DD + (q * 32 + lane) * 4];
    }
    __syncthreads();

    for (int c = 0; c < 8; ++c) {
        const int buf = c & 1;
        float4 nx[2][4];
        if (c < 7) {
            #pragma unroll
            for (int rr = 0; rr < 2; ++rr) {
                int r = warp + rr * 4;
                #pragma unroll
                for (int q = 0; q < 4; ++q)
                    nx[rr][q] = *(const float4*)&wfj[(size_t)((c + 1) * 8 + r) * DD
                                                     + (q * 32 + lane) * 4];
            }
        }
        #pragma unroll
        for (int bi = 0; bi < 8; ++bi) {
            const int b = c * 8 + bi;
            float av = (b & 32) ? a1 : a0;
            float a  = __shfl_sync(FULLMASK, av, b & 31);
            float sjv = (b & 32) ? s1 : s0;
            float sj = __shfl_sync(FULLMASK, sjv, b & 31);
            float ap = a * isc;

            float se0 = 0.0f, se1 = 0.0f, dot0 = 0.0f, dot1 = 0.0f;
            #pragma unroll
            for (int k = 0; k < 4; ++k) {
                float4 v = sv_attn[buf][bi][k * 32 + lane];
                float vv[4] = {v.x, v.y, v.z, v.w};
                #pragma unroll
                for (int c2 = 0; c2 < 4; ++c2) {
                    float f;
                    if (PASS == 0) {
                        float cur = ap * vv[c2];
                        float m = fminf(fmaxf(cur, -cL), cL);
                        f = fmaf(0.8f, m, 0.2f * cur);
                        hr[k*4+c2] += f;
                    } else {
                        float h = hr[k*4+c2];
                        float u = fmaf(ap, vv[c2], -h);
                        float m = fminf(fmaxf(u, -cL), cL);
                        float t = fmaf(0.2f, u, h);
                        f = fmaf(0.8f, m, t);
                    }
                    float e = ex2f_(f);
                    if (c2 & 1) { se1 += e; dot1 = fmaf(e, vv[c2], dot1); }
                    else        { se0 += e; dot0 = fmaf(e, vv[c2], dot0); }
                }
            }
            float se = se0 + se1, dot = dot0 + dot1;
            #pragma unroll
            for (int off = 16; off; off >>= 1) {
                se  += __shfl_xor_sync(FULLMASK, se,  off);
                dot += __shfl_xor_sync(FULLMASK, dot, off);
            }
            if (lane == 0)
                accout[(size_t)b * DD + d] = g * (dot * frcp_(se) + mb * sj);
        }
        if (c < 7) {
            #pragma unroll
            for (int rr = 0; rr < 2; ++rr) {
                int r = warp + rr * 4;
                #pragma unroll
                for (int q = 0; q < 4; ++q)
                    sv_attn[buf ^ 1][r][q * 32 + lane] = nx[rr][q];
            }
        }
        __syncthreads();
    }
}

// grid (128, MM), block 128 (4 warps); warp owns one d across all 64 b, both passes.
__global__ void attn_kernel(const float* __restrict__ gamma,
                            const float* __restrict__ mbias,
                            const float* __restrict__ constraint)
{
    const int i    = blockIdx.y;
    const int warp = threadIdx.x >> 5;
    const int lane = threadIdx.x & 31;
    const int d    = blockIdx.x * 4 + warp;
    const int j1 = (i == 0) ? 1 : 0;
    const int j2 = (i == 2) ? 1 : 2;

    const float cL  = constraint[i] * L2E;
    const float isc = INV_SCALE * L2E;
    const float a0 = __ldg(&g_WFT[((size_t)i * DD + d) * BB + lane]);
    const float a1 = __ldg(&g_WFT[((size_t)i * DD + d) * BB + 32 + lane]);

    float hr[16];
    #pragma unroll
    for (int q = 0; q < 16; ++q) hr[q] = 0.0f;

    {
        const float g1 = sigm_(gamma[i * MM + j1]);
        const float m1 = mbias[i * MM + j1];
        run_pass<0>(i, j1, d, lane, warp, a0, a1, hr, cL, isc, g1, m1,
                    g_A1 + (size_t)i * BB * DD);
    }
    #pragma unroll
    for (int q = 0; q < 16; ++q) hr[q] *= (1.0f / 320.0f);
    {
        const float g2 = sigm_(gamma[i * MM + j2]);
        const float m2 = mbias[i * MM + j2];
        run_pass<1>(i, j2, d, lane, warp, a0, a1, hr, cL, isc, g2, m2,
                    g_A2 + (size_t)i * BB * DD);
    }
}

// ================= K5: combine + attention weights =================
__global__ void combine_kernel(float* __restrict__ out,
                               const float* __restrict__ gamma,
                               int out_size)
{
    int idx = blockIdx.x * blockDim.x + threadIdx.x;  // < 32768
    const int NBD = BB * DD;
    float w = (g_WF[idx] + g_WF[NBD + idx] + g_WF[2*NBD + idx]) * (1.0f / 3.0f);
    float a = g_A1[idx] + g_A1[NBD + idx] + g_A1[2*NBD + idx]
            + g_A2[idx] + g_A2[NBD + idx] + g_A2[2*NBD + idx];
    out[idx] = w + a * (1.0f / 6.0f);

    if (idx < MM && out_size >= NBD + MM) {
        float sc[MM];
        #pragma unroll
        for (int ii = 0; ii < MM; ++ii) {
            int j1 = (ii == 0) ? 1 : 0;
            int j2 = (ii == 2) ? 1 : 2;
            sc[ii] = 0.5f * (sigm_(gamma[ii * MM + j1]) + sigm_(gamma[ii * MM + j2]));
        }
        float mx = fmaxf(sc[0], fmaxf(sc[1], sc[2]));
        float e0 = ex2f_((sc[0] - mx) * L2E);
        float e1 = ex2f_((sc[1] - mx) * L2E);
        float e2 = ex2f_((sc[2] - mx) * L2E);
        float inv = frcp_(e0 + e1 + e2);
        float ei = (idx == 0) ? e0 : ((idx == 1) ? e1 : e2);
        out[NBD + idx] = ei * inv;
    }
}

// ================= launch =================
extern "C" void kernel_launch(void* const* d_in, const int* in_sizes, int n_in,
                              void* d_out, int out_size)
{
    const float* x      = (const float*)d_in[0];
    const float* proj_W = (const float*)d_in[1];
    const float* proj_b = (const float*)d_in[2];
    const float* ln_g   = (const float*)d_in[3];
    const float* ln_b   = (const float*)d_in[4];
    const float* imp_W1 = (const float*)d_in[5];
    const float* imp_b1 = (const float*)d_in[6];
    const float* imp_W2 = (const float*)d_in[7];
    const float* imp_b2 = (const float*)d_in[8];
    const float* gamma  = (const float*)d_in[9];
    const float* mbias  = (const float*)d_in[10];
    const float* constr = (const float*)d_in[11];
    float* out = (float*)d_out;

    // 1) y = x @ proj_W^T (split-K 4) + grid-sync + LN/ReLU  (96 co-resident blocks)
    k1_gemm1_ln<<<dim3(8, NSPL, MM), 256>>>(x, proj_W, proj_b, ln_g, ln_b);
    // 2) HA = relu(proj @ W1^T + b1), 48 blocks
    gemm_hidden_kernel<<<dim3(16, MM), 128>>>(imp_W1, imp_b1);
    // 3) CW = HA @ W2^T fused with wf epilogue (WF/WFT/S), 48 blocks
    gemm_cw_wf_kernel<<<dim3(16, MM), 256>>>(imp_W2, imp_b2);
    // 4) merged attention, both passes, 384 blocks  (4th launch -> ncu capture)
    attn_kernel<<<dim3(128, MM), 128>>>(gamma, mbias, constr);
    // 5) combine
    combine_kernel<<<64, 512>>>(out, gamma, out_size);
}

// round 6
// speedup vs baseline: 1.9683x; 1.0534x over previous
#include <cuda_runtime.h>
#include <cstdint>

#define FULLMASK 0xffffffffu
#define MM 3
#define BB 64
#define DD 512
#define DQ 128
#define L2E 1.4426950408889634f
#define INV_SCALE 0.044194173824159216f   /* 1/sqrt(512) */
#define NSPL 4
#define K1_BLOCKS (8 * NSPL * MM)   /* 96 <= 148, co-resident */

// ---------------- scratch ----------------
__device__ float g_Y4[NSPL * MM * BB * DD];
__device__ float g_P [MM * BB * DD];
__device__ float g_HA[MM * BB * DQ];
__device__ float g_WF[MM * BB * DD];
__device__ float g_WFT[MM * DD * BB];
__device__ float g_S [MM * BB];
__device__ float g_A1[MM * BB * DD];
__device__ float g_A2[MM * BB * DD];
__device__ unsigned g_bar1;   // monotonic grid-barrier counter

__device__ __forceinline__ float ex2f_(float x) {
    float r; asm("ex2.approx.ftz.f32 %0, %1;" : "=f"(r) : "f"(x)); return r;
}
__device__ __forceinline__ float frcp_(float x) {
    float r; asm("rcp.approx.ftz.f32 %0, %1;" : "=f"(r) : "f"(x)); return r;
}
__device__ __forceinline__ float sigm_(float x) {
    return frcp_(1.0f + ex2f_(-x * L2E));
}

// ================= K1: gemm1 (split-K 4) + grid barrier + LN/ReLU =================
// grid dim3(8, NSPL, MM) = 96 blocks, 256 threads.
__global__ void k1_gemm1_ln(const float* __restrict__ X, const float* __restrict__ W,
                            const float* __restrict__ pb, const float* __restrict__ lg,
                            const float* __restrict__ lb)
{
    __shared__ float As[16][64];
    __shared__ float Bs[16][64];
    __shared__ float red[18];

    const int i  = blockIdx.z;
    const int n0 = blockIdx.x * 64;
    const int k0 = blockIdx.y * 128;
    const int tid = threadIdx.x;
    const int tx = tid & 15, ty = tid >> 4;

    const float* Xb = X + (size_t)i * BB * DD;
    const float* Wb = W + (size_t)i * DD * DD;

    float acc[4][4] = {};
    for (int kk = 0; kk < 128; kk += 16) {
        {
            int r  = tid >> 2;
            int c4 = (tid & 3) * 4;
            float4 xa = *(const float4*)&Xb[(size_t)r * DD + k0 + kk + c4];
            As[c4+0][r] = xa.x; As[c4+1][r] = xa.y; As[c4+2][r] = xa.z; As[c4+3][r] = xa.w;
            float4 wa = *(const float4*)&Wb[(size_t)(n0 + r) * DD + k0 + kk + c4];
            Bs[c4+0][r] = wa.x; Bs[c4+1][r] = wa.y; Bs[c4+2][r] = wa.z; Bs[c4+3][r] = wa.w;
        }
        __syncthreads();
        #pragma unroll
        for (int p = 0; p < 16; ++p) {
            float4 a4 = *(const float4*)&As[p][ty * 4];
            float4 b4 = *(const float4*)&Bs[p][tx * 4];
            float av[4] = {a4.x, a4.y, a4.z, a4.w};
            float bv[4] = {b4.x, b4.y, b4.z, b4.w};
            #pragma unroll
            for (int m2 = 0; m2 < 4; ++m2)
                #pragma unroll
                for (int n2 = 0; n2 < 4; ++n2)
                    acc[m2][n2] = fmaf(av[m2], bv[n2], acc[m2][n2]);
        }
        __syncthreads();
    }
    {
        float* Cout = g_Y4 + (size_t)blockIdx.y * (MM * BB * DD) + (size_t)i * BB * DD;
        #pragma unroll
        for (int m2 = 0; m2 < 4; ++m2) {
            int b = ty * 4 + m2;
            float4 v = make_float4(acc[m2][0], acc[m2][1], acc[m2][2], acc[m2][3]);
            *(float4*)&Cout[(size_t)b * DD + n0 + tx * 4] = v;
        }
    }

    // ---- grid barrier (all 96 blocks co-resident) ----
    __threadfence();
    __syncthreads();
    if (tid == 0) {
        unsigned old = atomicAdd(&g_bar1, 1u);
        unsigned target = (old / K1_BLOCKS + 1u) * K1_BLOCKS;
        while ((int)(*(volatile unsigned*)&g_bar1 - target) < 0) {
            __nanosleep(32);
        }
    }
    __syncthreads();

    // ---- phase 2: LN + ReLU, 2 rows per block ----
    const int flat = (blockIdx.z * NSPL + blockIdx.y) * 8 + blockIdx.x;
    const int warp = tid >> 5, lane = tid & 31;
    if (flat == 0 && tid < MM * BB) g_S[tid] = 0.0f;

    #pragma unroll
    for (int rr = 0; rr < 2; ++rr) {
        const int row = flat * 2 + rr;          // 0..191
        const int i2  = row >> 6;
        const size_t base = (size_t)row * DD;
        const int e0 = tid, e1 = tid + 256;

        float y0 = pb[i2 * DD + e0];
        float y1 = pb[i2 * DD + e1];
        #pragma unroll
        for (int s = 0; s < NSPL; ++s) {
            y0 += g_Y4[(size_t)s * MM * BB * DD + base + e0];
            y1 += g_Y4[(size_t)s * MM * BB * DD + base + e1];
        }
        float s = y0 + y1, q = y0 * y0 + y1 * y1;
        #pragma unroll
        for (int off = 16; off; off >>= 1) {
            s += __shfl_xor_sync(FULLMASK, s, off);
            q += __shfl_xor_sync(FULLMASK, q, off);
        }
        if (lane == 0) { red[warp] = s; red[8 + warp] = q; }
        __syncthreads();
        if (warp == 0) {
            float s2 = red[lane & 7], q2 = red[8 + (lane & 7)];
            #pragma unroll
            for (int off = 4; off; off >>= 1) {
                s2 += __shfl_xor_sync(FULLMASK, s2, off);
                q2 += __shfl_xor_sync(FULLMASK, q2, off);
            }
            if (lane == 0) { red[16] = s2; red[17] = q2; }
        }
        __syncthreads();
        float mu  = red[16] * (1.0f / DD);
        float var = red[17] * (1.0f / DD) - mu * mu;
        float rs  = rsqrtf(var + 1e-5f);
        float p0 = (y0 - mu) * rs * lg[i2 * DD + e0] + lb[i2 * DD + e0];
        float p1 = (y1 - mu) * rs * lg[i2 * DD + e1] + lb[i2 * DD + e1];
        g_P[base + e0] = fmaxf(p0, 0.0f);
        g_P[base + e1] = fmaxf(p1, 0.0f);
        __syncthreads();
    }
}

// ================= K2: HA = relu(P @ W1^T + b1) =================
__global__ void gemm_hidden_kernel(const float* __restrict__ W1, const float* __restrict__ b1)
{
    const int i  = blockIdx.y;
    const int b0 = (blockIdx.x & 7) * 8;
    const int n0 = (blockIdx.x >> 3) * 64;
    const int tid = threadIdx.x;
    const int tx = tid & 15, ty = tid >> 4;

    __shared__ __align__(16) float As[32][8];
    __shared__ __align__(16) float Bs[32][64];

    const float* Pb = g_P + (size_t)i * BB * DD;
    const float* Wb = W1 + (size_t)i * DQ * DD;

    float acc[4] = {};
    for (int k0 = 0; k0 < DD; k0 += 32) {
        if (tid < 64) {
            int r = tid >> 3, q = tid & 7;
            float4 v = *(const float4*)&Pb[(size_t)(b0 + r) * DD + k0 + q * 4];
            As[q*4+0][r] = v.x; As[q*4+1][r] = v.y; As[q*4+2][r] = v.z; As[q*4+3][r] = v.w;
        }
        #pragma unroll
        for (int q = 0; q < 4; ++q) {
            int idx = tid * 4 + q;
            int nr = idx >> 3, kq = idx & 7;
            float4 v = *(const float4*)&Wb[(size_t)(n0 + nr) * DD + k0 + kq * 4];
            Bs[kq*4+0][nr] = v.x; Bs[kq*4+1][nr] = v.y; Bs[kq*4+2][nr] = v.z; Bs[kq*4+3][nr] = v.w;
        }
        __syncthreads();
        #pragma unroll
        for (int k = 0; k < 32; ++k) {
            float a = As[k][ty];
            float4 w4 = *(const float4*)&Bs[k][tx * 4];
            acc[0] = fmaf(a, w4.x, acc[0]);
            acc[1] = fmaf(a, w4.y, acc[1]);
            acc[2] = fmaf(a, w4.z, acc[2]);
            acc[3] = fmaf(a, w4.w, acc[3]);
        }
        __syncthreads();
    }
    float4 o;
    o.x = fmaxf(acc[0] + b1[i*DQ + n0 + tx*4 + 0], 0.0f);
    o.y = fmaxf(acc[1] + b1[i*DQ + n0 + tx*4 + 1], 0.0f);
    o.z = fmaxf(acc[2] + b1[i*DQ + n0 + tx*4 + 2], 0.0f);
    o.w = fmaxf(acc[3] + b1[i*DQ + n0 + tx*4 + 3], 0.0f);
    *(float4*)&g_HA[((size_t)i * BB + b0 + ty) * DQ + n0 + tx * 4] = o;
}

// ================= K3: CW = HA @ W2^T + fused wf epilogue =================
__global__ void gemm_cw_wf_kernel(const float* __restrict__ W2,
                                  const float* __restrict__ b2v)
{
    const int i  = blockIdx.y;
    const int n0 = blockIdx.x * 32;
    const int tid = threadIdx.x;
    const int tx = tid & 7, ty = tid >> 3;

    __shared__ __align__(16) float As2[64][DQ];
    __shared__ __align__(16) float Bs[DQ][36];

    #pragma unroll
    for (int q = 0; q < 8; ++q) {
        int idx = tid + q * 256;
        int b = idx >> 5, kq = idx & 31;
        float4 v = *(const float4*)&g_HA[((size_t)i * BB + b) * DQ + kq * 4];
        *(float4*)&As2[b][kq * 4] = v;
    }
    #pragma unroll
    for (int q = 0; q < 4; ++q) {
        int idx = tid + q * 256;
        int nr = idx >> 5, kq = idx & 31;
        float4 v = *(const float4*)&W2[((size_t)i * DD + n0 + nr) * DQ + kq * 4];
        Bs[kq*4+0][nr] = v.x; Bs[kq*4+1][nr] = v.y; Bs[kq*4+2][nr] = v.z; Bs[kq*4+3][nr] = v.w;
    }
    __syncthreads();

    float acc[2][4] = {};
    #pragma unroll 8
    for (int k4 = 0; k4 < 32; ++k4) {
        float4 a0 = *(const float4*)&As2[ty][k4 * 4];
        float4 a1 = *(const float4*)&As2[ty + 32][k4 * 4];
        float av0[4] = {a0.x, a0.y, a0.z, a0.w};
        float av1[4] = {a1.x, a1.y, a1.z, a1.w};
        #pragma unroll
        for (int q = 0; q < 4; ++q) {
            float4 b4 = *(const float4*)&Bs[k4 * 4 + q][tx * 4];
            float bv[4] = {b4.x, b4.y, b4.z, b4.w};
            #pragma unroll
            for (int n2 = 0; n2 < 4; ++n2) {
                acc[0][n2] = fmaf(av0[q], bv[n2], acc[0][n2]);
                acc[1][n2] = fmaf(av1[q], bv[n2], acc[1][n2]);
            }
        }
    }

    #pragma unroll
    for (int rr = 0; rr < 2; ++rr) {
        int b = ty + rr * 32;
        int n = n0 + tx * 4;
        float4 p4 = *(const float4*)&g_P[((size_t)i * BB + b) * DD + n];
        float pv[4] = {p4.x, p4.y, p4.z, p4.w};
        float w[4], srow = 0.0f;
        #pragma unroll
        for (int q = 0; q < 4; ++q) {
            float pre = acc[rr][q] + b2v[i * DD + n + q];
            w[q] = pv[q] * sigm_(pre);
            srow += w[q];
            g_WFT[((size_t)i * DD + n + q) * BB + b] = w[q];
        }
        *(float4*)&g_WF[((size_t)i * BB + b) * DD + n] = make_float4(w[0], w[1], w[2], w[3]);
        #pragma unroll
        for (int off = 4; off; off >>= 1)
            srow += __shfl_xor_sync(FULLMASK, srow, off);
        if (tx == 0) atomicAdd(&g_S[i * BB + b], srow);
    }
}

// ================= K4: merged pairwise attention (b-split warp pairs) =================
// block 256 = 8 warps: warp = d_local*2 + bhalf.  grid (128, MM).
// sv chunks: 8 rows (4 per half) x 512 floats, double buffered = 32 KB.

template<int PASS>
__device__ __forceinline__ void run_pass(float4 (*sv)[8][128],
                                         int j, int d, int lane, int warp, int bhalf,
                                         float a0, float (&hr)[16],
                                         float cL, float isc, float g, float mb,
                                         float* __restrict__ accout)
{
    const int tid = warp * 32 + lane;
    const int bs = bhalf * 32;
    const float* wfj = g_WF + (size_t)j * BB * DD;
    const float s0 = __ldg(&g_S[j * BB + bs + lane]);

    const float isc8 = isc * 0.8f, isc2 = isc * 0.2f, cL8 = cL * 0.8f;

    // prologue: stage chunk 0 (rows: half*32 + 0..3)
    #pragma unroll
    for (int q = 0; q < 4; ++q) {
        int idx = tid + q * 256;            // 0..1023 float4s
        int rl = idx >> 7, col = idx & 127; // rl: 0..7 (half*4 + r)
        int grow = (rl >> 2) * 32 + (rl & 3);
        sv[0][rl][col] = *(const float4*)&wfj[(size_t)grow * DD + col * 4];
    }
    __syncthreads();

    for (int c = 0; c < 8; ++c) {
        const int buf = c & 1;
        float4 nx[4];
        if (c < 7) {
            #pragma unroll
            for (int q = 0; q < 4; ++q) {
                int idx = tid + q * 256;
                int rl = idx >> 7, col = idx & 127;
                int grow = (rl >> 2) * 32 + (c + 1) * 4 + (rl & 3);
                nx[q] = *(const float4*)&wfj[(size_t)grow * DD + col * 4];
            }
        }
        #pragma unroll
        for (int bi = 0; bi < 4; ++bi) {
            const int bl = c * 4 + bi;              // local b (0..31)
            float a  = __shfl_sync(FULLMASK, a0, bl);
            float sj = __shfl_sync(FULLMASK, s0, bl);

            float se0 = 0.0f, se1 = 0.0f, dot0 = 0.0f, dot1 = 0.0f;
            const float4* vr = sv[buf][bhalf * 4 + bi];

            if (PASS == 0) {
                float ap8 = a * isc8, ap2 = a * isc2;
                #pragma unroll
                for (int k = 0; k < 4; ++k) {
                    float4 v = vr[k * 32 + lane];
                    float vv[4] = {v.x, v.y, v.z, v.w};
                    #pragma unroll
                    for (int c2 = 0; c2 < 4; ++c2) {
                        float cur8 = ap8 * vv[c2];
                        float m8 = fminf(fmaxf(cur8, -cL8), cL8);
                        float f = fmaf(ap2, vv[c2], m8);
                        hr[k*4+c2] += f;
                        float e = ex2f_(f);
                        if (c2 & 1) { se1 += e; dot1 = fmaf(e, vv[c2], dot1); }
                        else        { se0 += e; dot0 = fmaf(e, vv[c2], dot0); }
                    }
                }
            } else {
                float ap = a * isc;
                #pragma unroll
                for (int k = 0; k < 4; ++k) {
                    float4 v = vr[k * 32 + lane];
                    float vv[4] = {v.x, v.y, v.z, v.w};
                    #pragma unroll
                    for (int c2 = 0; c2 < 4; ++c2) {
                        float h = hr[k*4+c2];
                        float u = fmaf(ap, vv[c2], -h);
                        float m = fminf(fmaxf(u, -cL), cL);
                        float t = fmaf(0.2f, u, h);
                        float f = fmaf(0.8f, m, t);
                        float e = ex2f_(f);
                        if (c2 & 1) { se1 += e; dot1 = fmaf(e, vv[c2], dot1); }
                        else        { se0 += e; dot0 = fmaf(e, vv[c2], dot0); }
                    }
                }
            }
            float se = se0 + se1, dot = dot0 + dot1;
            #pragma unroll
            for (int off = 16; off; off >>= 1) {
                se  += __shfl_xor_sync(FULLMASK, se,  off);
                dot += __shfl_xor_sync(FULLMASK, dot, off);
            }
            if (lane == 0)
                accout[(size_t)(bs + bl) * DD + d] = g * (dot * frcp_(se) + mb * sj);
        }
        if (c < 7) {
            #pragma unroll
            for (int q = 0; q < 4; ++q) {
                int idx = tid + q * 256;
                int rl = idx >> 7, col = idx & 127;
                sv[buf ^ 1][rl][col] = nx[q];
            }
        }
        __syncthreads();
    }
}

__global__ __launch_bounds__(256) void attn_kernel(const float* __restrict__ gamma,
                            const float* __restrict__ mbias,
                            const float* __restrict__ constraint)
{
    __shared__ __align__(16) float4 sv[2][8][128];   // 32 KB
    const int i     = blockIdx.y;
    const int warp  = threadIdx.x >> 5;
    const int lane  = threadIdx.x & 31;
    const int bhalf = warp & 1;
    const int d     = blockIdx.x * 4 + (warp >> 1);
    const int j1 = (i == 0) ? 1 : 0;
    const int j2 = (i == 2) ? 1 : 2;

    const float cL  = constraint[i] * L2E;
    const float isc = INV_SCALE * L2E;
    const float a0 = __ldg(&g_WFT[((size_t)i * DD + d) * BB + bhalf * 32 + lane]);

    float hr[16];
    #pragma unroll
    for (int q = 0; q < 16; ++q) hr[q] = 0.0f;

    {
        const float g1 = sigm_(gamma[i * MM + j1]);
        const float m1 = mbias[i * MM + j1];
        run_pass<0>(sv, j1, d, lane, warp, bhalf, a0, hr, cL, isc, g1, m1,
                    g_A1 + (size_t)i * BB * DD);
    }

    // ---- exchange hr across the warp pair (reuse sv buffer) ----
    __syncthreads();
    float* hx = (float*)sv;                     // 8 warps x 512 floats = 16 KB
    #pragma unroll
    for (int k = 0; k < 4; ++k)
        *(float4*)&hx[warp * 512 + (k * 32 + lane) * 4] =
            make_float4(hr[k*4+0], hr[k*4+1], hr[k*4+2], hr[k*4+3]);
    __syncthreads();
    {
        const int p = warp ^ 1;
        #pragma unroll
        for (int k = 0; k < 4; ++k) {
            float4 hp = *(const float4*)&hx[p * 512 + (k * 32 + lane) * 4];
            hr[k*4+0] = (hr[k*4+0] + hp.x) * (1.0f / 320.0f);
            hr[k*4+1] = (hr[k*4+1] + hp.y) * (1.0f / 320.0f);
            hr[k*4+2] = (hr[k*4+2] + hp.z) * (1.0f / 320.0f);
            hr[k*4+3] = (hr[k*4+3] + hp.w) * (1.0f / 320.0f);
        }
    }
    __syncthreads();

    {
        const float g2 = sigm_(gamma[i * MM + j2]);
        const float m2 = mbias[i * MM + j2];
        run_pass<1>(sv, j2, d, lane, warp, bhalf, a0, hr, cL, isc, g2, m2,
                    g_A2 + (size_t)i * BB * DD);
    }
}

// ================= K5: combine + attention weights =================
__global__ void combine_kernel(float* __restrict__ out,
                               const float* __restrict__ gamma,
                               int out_size)
{
    int idx = blockIdx.x * blockDim.x + threadIdx.x;  // < 32768
    const int NBD = BB * DD;
    float w = (g_WF[idx] + g_WF[NBD + idx] + g_WF[2*NBD + idx]) * (1.0f / 3.0f);
    float a = g_A1[idx] + g_A1[NBD + idx] + g_A1[2*NBD + idx]
            + g_A2[idx] + g_A2[NBD + idx] + g_A2[2*NBD + idx];
    out[idx] = w + a * (1.0f / 6.0f);

    if (idx < MM && out_size >= NBD + MM) {
        float sc[MM];
        #pragma unroll
        for (int ii = 0; ii < MM; ++ii) {
            int j1 = (ii == 0) ? 1 : 0;
            int j2 = (ii == 2) ? 1 : 2;
            sc[ii] = 0.5f * (sigm_(gamma[ii * MM + j1]) + sigm_(gamma[ii * MM + j2]));
        }
        float mx = fmaxf(sc[0], fmaxf(sc[1], sc[2]));
        float e0 = ex2f_((sc[0] - mx) * L2E);
        float e1 = ex2f_((sc[1] - mx) * L2E);
        float e2 = ex2f_((sc[2] - mx) * L2E);
        float inv = frcp_(e0 + e1 + e2);
        float ei = (idx == 0) ? e0 : ((idx == 1) ? e1 : e2);
        out[NBD + idx] = ei * inv;
    }
}

// ================= launch =================
extern "C" void kernel_launch(void* const* d_in, const int* in_sizes, int n_in,
                              void* d_out, int out_size)
{
    const float* x      = (const float*)d_in[0];
    const float* proj_W = (const float*)d_in[1];
    const float* proj_b = (const float*)d_in[2];
    const float* ln_g   = (const float*)d_in[3];
    const float* ln_b   = (const float*)d_in[4];
    const float* imp_W1 = (const float*)d_in[5];
    const float* imp_b1 = (const float*)d_in[6];
    const float* imp_W2 = (const float*)d_in[7];
    const float* imp_b2 = (const float*)d_in[8];
    const float* gamma  = (const float*)d_in[9];
    const float* mbias  = (const float*)d_in[10];
    const float* constr = (const float*)d_in[11];
    float* out = (float*)d_out;

    // 1) y = x @ proj_W^T (split-K 4) + grid-sync + LN/ReLU
    k1_gemm1_ln<<<dim3(8, NSPL, MM), 256>>>(x, proj_W, proj_b, ln_g, ln_b);
    // 2) HA = relu(proj @ W1^T + b1)
    gemm_hidden_kernel<<<dim3(16, MM), 128>>>(imp_W1, imp_b1);
    // 3) CW = HA @ W2^T fused with wf epilogue
    gemm_cw_wf_kernel<<<dim3(16, MM), 256>>>(imp_W2, imp_b2);
    // 4) merged attention, b-split warp pairs, 384 blocks x 256 thr (profiled slot)
    attn_kernel<<<dim3(128, MM), 256>>>(gamma, mbias, constr);
    // 5) combine
    combine_kernel<<<64, 512>>>(out, gamma, out_size);
}

// round 7
// speedup vs baseline: 2.0047x; 1.0185x over previous
#include <cuda_runtime.h>
#include <cstdint>

#define FULLMASK 0xffffffffu
#define MM 3
#define BB 64
#define DD 512
#define DQ 128
#define L2E 1.4426950408889634f
#define INV_SCALE 0.044194173824159216f   /* 1/sqrt(512) */
#define NSPL 4
#define K1_BLOCKS (8 * NSPL * MM)   /* 96 <= 148, co-resident */

// ---------------- scratch ----------------
__device__ float g_Y4[NSPL * MM * BB * DD];
__device__ float g_P [MM * BB * DD];
__device__ float g_HA[MM * BB * DQ];
__device__ float g_WF[MM * BB * DD];
__device__ float g_WFT[MM * DD * BB];
__device__ float g_S [MM * BB];
__device__ float g_A1[MM * BB * DD];
__device__ float g_A2[MM * BB * DD];
__device__ unsigned g_bar1;   // monotonic grid-barrier counter

__device__ __forceinline__ float ex2f_(float x) {
    float r; asm("ex2.approx.ftz.f32 %0, %1;" : "=f"(r) : "f"(x)); return r;
}
__device__ __forceinline__ float frcp_(float x) {
    float r; asm("rcp.approx.ftz.f32 %0, %1;" : "=f"(r) : "f"(x)); return r;
}
__device__ __forceinline__ float sigm_(float x) {
    return frcp_(1.0f + ex2f_(-x * L2E));
}

// ================= K1: gemm1 (split-K 4) + grid barrier + LN/ReLU =================
__global__ void k1_gemm1_ln(const float* __restrict__ X, const float* __restrict__ W,
                            const float* __restrict__ pb, const float* __restrict__ lg,
                            const float* __restrict__ lb)
{
    __shared__ float As[16][64];
    __shared__ float Bs[16][64];
    __shared__ float red[18];

    const int i  = blockIdx.z;
    const int n0 = blockIdx.x * 64;
    const int k0 = blockIdx.y * 128;
    const int tid = threadIdx.x;
    const int tx = tid & 15, ty = tid >> 4;

    const float* Xb = X + (size_t)i * BB * DD;
    const float* Wb = W + (size_t)i * DD * DD;

    float acc[4][4] = {};
    for (int kk = 0; kk < 128; kk += 16) {
        {
            int r  = tid >> 2;
            int c4 = (tid & 3) * 4;
            float4 xa = *(const float4*)&Xb[(size_t)r * DD + k0 + kk + c4];
            As[c4+0][r] = xa.x; As[c4+1][r] = xa.y; As[c4+2][r] = xa.z; As[c4+3][r] = xa.w;
            float4 wa = *(const float4*)&Wb[(size_t)(n0 + r) * DD + k0 + kk + c4];
            Bs[c4+0][r] = wa.x; Bs[c4+1][r] = wa.y; Bs[c4+2][r] = wa.z; Bs[c4+3][r] = wa.w;
        }
        __syncthreads();
        #pragma unroll
        for (int p = 0; p < 16; ++p) {
            float4 a4 = *(const float4*)&As[p][ty * 4];
            float4 b4 = *(const float4*)&Bs[p][tx * 4];
            float av[4] = {a4.x, a4.y, a4.z, a4.w};
            float bv[4] = {b4.x, b4.y, b4.z, b4.w};
            #pragma unroll
            for (int m2 = 0; m2 < 4; ++m2)
                #pragma unroll
                for (int n2 = 0; n2 < 4; ++n2)
                    acc[m2][n2] = fmaf(av[m2], bv[n2], acc[m2][n2]);
        }
        __syncthreads();
    }
    {
        float* Cout = g_Y4 + (size_t)blockIdx.y * (MM * BB * DD) + (size_t)i * BB * DD;
        #pragma unroll
        for (int m2 = 0; m2 < 4; ++m2) {
            int b = ty * 4 + m2;
            float4 v = make_float4(acc[m2][0], acc[m2][1], acc[m2][2], acc[m2][3]);
            *(float4*)&Cout[(size_t)b * DD + n0 + tx * 4] = v;
        }
    }

    // ---- grid barrier (all 96 blocks co-resident) ----
    __threadfence();
    __syncthreads();
    if (tid == 0) {
        unsigned old = atomicAdd(&g_bar1, 1u);
        unsigned target = (old / K1_BLOCKS + 1u) * K1_BLOCKS;
        while ((int)(*(volatile unsigned*)&g_bar1 - target) < 0) {
            __nanosleep(32);
        }
    }
    __syncthreads();

    // ---- phase 2: LN + ReLU, 2 rows per block ----
    const int flat = (blockIdx.z * NSPL + blockIdx.y) * 8 + blockIdx.x;
    const int warp = tid >> 5, lane = tid & 31;
    if (flat == 0 && tid < MM * BB) g_S[tid] = 0.0f;

    #pragma unroll
    for (int rr = 0; rr < 2; ++rr) {
        const int row = flat * 2 + rr;          // 0..191
        const int i2  = row >> 6;
        const size_t base = (size_t)row * DD;
        const int e0 = tid, e1 = tid + 256;

        float y0 = pb[i2 * DD + e0];
        float y1 = pb[i2 * DD + e1];
        #pragma unroll
        for (int s = 0; s < NSPL; ++s) {
            y0 += g_Y4[(size_t)s * MM * BB * DD + base + e0];
            y1 += g_Y4[(size_t)s * MM * BB * DD + base + e1];
        }
        float s = y0 + y1, q = y0 * y0 + y1 * y1;
        #pragma unroll
        for (int off = 16; off; off >>= 1) {
            s += __shfl_xor_sync(FULLMASK, s, off);
            q += __shfl_xor_sync(FULLMASK, q, off);
        }
        if (lane == 0) { red[warp] = s; red[8 + warp] = q; }
        __syncthreads();
        if (warp == 0) {
            float s2 = red[lane & 7], q2 = red[8 + (lane & 7)];
            #pragma unroll
            for (int off = 4; off; off >>= 1) {
                s2 += __shfl_xor_sync(FULLMASK, s2, off);
                q2 += __shfl_xor_sync(FULLMASK, q2, off);
            }
            if (lane == 0) { red[16] = s2; red[17] = q2; }
        }
        __syncthreads();
        float mu  = red[16] * (1.0f / DD);
        float var = red[17] * (1.0f / DD) - mu * mu;
        float rs  = rsqrtf(var + 1e-5f);
        float p0 = (y0 - mu) * rs * lg[i2 * DD + e0] + lb[i2 * DD + e0];
        float p1 = (y1 - mu) * rs * lg[i2 * DD + e1] + lb[i2 * DD + e1];
        g_P[base + e0] = fmaxf(p0, 0.0f);
        g_P[base + e1] = fmaxf(p1, 0.0f);
        __syncthreads();
    }
}

// ================= K2: HA = relu(P @ W1^T + b1) =================
__global__ void gemm_hidden_kernel(const float* __restrict__ W1, const float* __restrict__ b1)
{
    const int i  = blockIdx.y;
    const int b0 = (blockIdx.x & 7) * 8;
    const int n0 = (blockIdx.x >> 3) * 64;
    const int tid = threadIdx.x;
    const int tx = tid & 15, ty = tid >> 4;

    __shared__ __align__(16) float As[32][8];
    __shared__ __align__(16) float Bs[32][64];

    const float* Pb = g_P + (size_t)i * BB * DD;
    const float* Wb = W1 + (size_t)i * DQ * DD;

    float acc[4] = {};
    for (int k0 = 0; k0 < DD; k0 += 32) {
        if (tid < 64) {
            int r = tid >> 3, q = tid & 7;
            float4 v = *(const float4*)&Pb[(size_t)(b0 + r) * DD + k0 + q * 4];
            As[q*4+0][r] = v.x; As[q*4+1][r] = v.y; As[q*4+2][r] = v.z; As[q*4+3][r] = v.w;
        }
        #pragma unroll
        for (int q = 0; q < 4; ++q) {
            int idx = tid * 4 + q;
            int nr = idx >> 3, kq = idx & 7;
            float4 v = *(const float4*)&Wb[(size_t)(n0 + nr) * DD + k0 + kq * 4];
            Bs[kq*4+0][nr] = v.x; Bs[kq*4+1][nr] = v.y; Bs[kq*4+2][nr] = v.z; Bs[kq*4+3][nr] = v.w;
        }
        __syncthreads();
        #pragma unroll
        for (int k = 0; k < 32; ++k) {
            float a = As[k][ty];
            float4 w4 = *(const float4*)&Bs[k][tx * 4];
            acc[0] = fmaf(a, w4.x, acc[0]);
            acc[1] = fmaf(a, w4.y, acc[1]);
            acc[2] = fmaf(a, w4.z, acc[2]);
            acc[3] = fmaf(a, w4.w, acc[3]);
        }
        __syncthreads();
    }
    float4 o;
    o.x = fmaxf(acc[0] + b1[i*DQ + n0 + tx*4 + 0], 0.0f);
    o.y = fmaxf(acc[1] + b1[i*DQ + n0 + tx*4 + 1], 0.0f);
    o.z = fmaxf(acc[2] + b1[i*DQ + n0 + tx*4 + 2], 0.0f);
    o.w = fmaxf(acc[3] + b1[i*DQ + n0 + tx*4 + 3], 0.0f);
    *(float4*)&g_HA[((size_t)i * BB + b0 + ty) * DQ + n0 + tx * 4] = o;
}

// ================= K3: CW = HA @ W2^T + fused wf epilogue =================
__global__ void gemm_cw_wf_kernel(const float* __restrict__ W2,
                                  const float* __restrict__ b2v)
{
    const int i  = blockIdx.y;
    const int n0 = blockIdx.x * 32;
    const int tid = threadIdx.x;
    const int tx = tid & 7, ty = tid >> 3;

    __shared__ __align__(16) float As2[64][DQ];
    __shared__ __align__(16) float Bs[DQ][36];

    #pragma unroll
    for (int q = 0; q < 8; ++q) {
        int idx = tid + q * 256;
        int b = idx >> 5, kq = idx & 31;
        float4 v = *(const float4*)&g_HA[((size_t)i * BB + b) * DQ + kq * 4];
        *(float4*)&As2[b][kq * 4] = v;
    }
    #pragma unroll
    for (int q = 0; q < 4; ++q) {
        int idx = tid + q * 256;
        int nr = idx >> 5, kq = idx & 31;
        float4 v = *(const float4*)&W2[((size_t)i * DD + n0 + nr) * DQ + kq * 4];
        Bs[kq*4+0][nr] = v.x; Bs[kq*4+1][nr] = v.y; Bs[kq*4+2][nr] = v.z; Bs[kq*4+3][nr] = v.w;
    }
    __syncthreads();

    float acc[2][4] = {};
    #pragma unroll 8
    for (int k4 = 0; k4 < 32; ++k4) {
        float4 a0 = *(const float4*)&As2[ty][k4 * 4];
        float4 a1 = *(const float4*)&As2[ty + 32][k4 * 4];
        float av0[4] = {a0.x, a0.y, a0.z, a0.w};
        float av1[4] = {a1.x, a1.y, a1.z, a1.w};
        #pragma unroll
        for (int q = 0; q < 4; ++q) {
            float4 b4 = *(const float4*)&Bs[k4 * 4 + q][tx * 4];
            float bv[4] = {b4.x, b4.y, b4.z, b4.w};
            #pragma unroll
            for (int n2 = 0; n2 < 4; ++n2) {
                acc[0][n2] = fmaf(av0[q], bv[n2], acc[0][n2]);
                acc[1][n2] = fmaf(av1[q], bv[n2], acc[1][n2]);
            }
        }
    }

    #pragma unroll
    for (int rr = 0; rr < 2; ++rr) {
        int b = ty + rr * 32;
        int n = n0 + tx * 4;
        float4 p4 = *(const float4*)&g_P[((size_t)i * BB + b) * DD + n];
        float pv[4] = {p4.x, p4.y, p4.z, p4.w};
        float w[4], srow = 0.0f;
        #pragma unroll
        for (int q = 0; q < 4; ++q) {
            float pre = acc[rr][q] + b2v[i * DD + n + q];
            w[q] = pv[q] * sigm_(pre);
            srow += w[q];
            g_WFT[((size_t)i * DD + n + q) * BB + b] = w[q];
        }
        *(float4*)&g_WF[((size_t)i * BB + b) * DD + n] = make_float4(w[0], w[1], w[2], w[3]);
        #pragma unroll
        for (int off = 4; off; off >>= 1)
            srow += __shfl_xor_sync(FULLMASK, srow, off);
        if (tx == 0) atomicAdd(&g_S[i * BB + b], srow);
    }
}

// ================= K4: merged pairwise attention (deferred smem reductions) =================
// block 256 = 8 warps: warp = d_local*2 + bhalf.  grid (128, MM).

template<int PASS>
__device__ __forceinline__ void run_pass(float4 (*sv)[8][128],
                                         float (*pw)[36],            // this warp's partials [8][36]
                                         int j, int d, int lane, int warp, int bhalf,
                                         float a0, float (&hr)[16],
                                         float cL, float isc, float g, float mb,
                                         float* __restrict__ accout)
{
    const int tid = warp * 32 + lane;
    const int bs = bhalf * 32;
    const float* wfj = g_WF + (size_t)j * BB * DD;
    const float isc8 = isc * 0.8f, isc2 = isc * 0.2f, cL8 = cL * 0.8f;

    // prologue: stage chunk 0
    #pragma unroll
    for (int q = 0; q < 4; ++q) {
        int idx = tid + q * 256;
        int rl = idx >> 7, col = idx & 127;
        int grow = (rl >> 2) * 32 + (rl & 3);
        sv[0][rl][col] = *(const float4*)&wfj[(size_t)grow * DD + col * 4];
    }
    __syncthreads();

    for (int c = 0; c < 8; ++c) {
        const int buf = c & 1;
        float4 nx[4];
        if (c < 7) {
            #pragma unroll
            for (int q = 0; q < 4; ++q) {
                int idx = tid + q * 256;
                int rl = idx >> 7, col = idx & 127;
                int grow = (rl >> 2) * 32 + (c + 1) * 4 + (rl & 3);
                nx[q] = *(const float4*)&wfj[(size_t)grow * DD + col * 4];
            }
        }
        #pragma unroll
        for (int bi = 0; bi < 4; ++bi) {
            const int bl = c * 4 + bi;              // local b (0..31)
            float a  = __shfl_sync(FULLMASK, a0, bl);

            float se0 = 0.0f, se1 = 0.0f, dot0 = 0.0f, dot1 = 0.0f;
            const float4* vr = sv[buf][bhalf * 4 + bi];

            if (PASS == 0) {
                float ap8 = a * isc8, ap2 = a * isc2;
                #pragma unroll
                for (int k = 0; k < 4; ++k) {
                    float4 v = vr[k * 32 + lane];
                    float vv[4] = {v.x, v.y, v.z, v.w};
                    #pragma unroll
                    for (int c2 = 0; c2 < 4; ++c2) {
                        float cur8 = ap8 * vv[c2];
                        float m8 = fminf(fmaxf(cur8, -cL8), cL8);
                        float f = fmaf(ap2, vv[c2], m8);
                        hr[k*4+c2] += f;
                        float e = ex2f_(f);
                        if (c2 & 1) { se1 += e; dot1 = fmaf(e, vv[c2], dot1); }
                        else        { se0 += e; dot0 = fmaf(e, vv[c2], dot0); }
                    }
                }
            } else {
                float ap = a * isc;
                #pragma unroll
                for (int k = 0; k < 4; ++k) {
                    float4 v = vr[k * 32 + lane];
                    float vv[4] = {v.x, v.y, v.z, v.w};
                    #pragma unroll
                    for (int c2 = 0; c2 < 4; ++c2) {
                        float h = hr[k*4+c2];
                        float u = fmaf(ap, vv[c2], -h);
                        float m = fminf(fmaxf(u, -cL), cL);
                        float t = fmaf(0.2f, u, h);
                        float f = fmaf(0.8f, m, t);
                        float e = ex2f_(f);
                        if (c2 & 1) { se1 += e; dot1 = fmaf(e, vv[c2], dot1); }
                        else        { se0 += e; dot0 = fmaf(e, vv[c2], dot0); }
                    }
                }
            }
            pw[bi * 2 + 0][lane] = se0 + se1;      // conflict-free STS.32
            pw[bi * 2 + 1][lane] = dot0 + dot1;
        }
        __syncwarp();
        // deferred reduction: 8 lanes, one 32-float row each (rows padded to 36)
        if (lane < 8) {
            const float4* pr = (const float4*)pw[lane];
            float4 p0 = pr[0], p1 = pr[1], p2 = pr[2], p3 = pr[3];
            float4 p4 = pr[4], p5 = pr[5], p6 = pr[6], p7 = pr[7];
            p0.x += p1.x; p0.y += p1.y; p0.z += p1.z; p0.w += p1.w;
            p2.x += p3.x; p2.y += p3.y; p2.z += p3.z; p2.w += p3.w;
            p4.x += p5.x; p4.y += p5.y; p4.z += p5.z; p4.w += p5.w;
            p6.x += p7.x; p6.y += p7.y; p6.z += p7.z; p6.w += p7.w;
            p0.x += p2.x; p0.y += p2.y; p0.z += p2.z; p0.w += p2.w;
            p4.x += p6.x; p4.y += p6.y; p4.z += p6.z; p4.w += p6.w;
            float val = (p0.x + p4.x) + (p0.y + p4.y) + (p0.z + p4.z) + (p0.w + p4.w);
            float sev = __shfl_sync(0xFFu, val, lane & ~1);   // even lane's se
            if (lane & 1) {
                int bl = c * 4 + (lane >> 1);
                float sj = __ldg(&g_S[j * BB + bs + bl]);
                accout[(size_t)(bs + bl) * DD + d] = g * (val * frcp_(sev) + mb * sj);
            }
        }
        if (c < 7) {
            #pragma unroll
            for (int q = 0; q < 4; ++q) {
                int idx = tid + q * 256;
                int rl = idx >> 7, col = idx & 127;
                sv[buf ^ 1][rl][col] = nx[q];
            }
        }
        __syncthreads();
    }
}

__global__ __launch_bounds__(256) void attn_kernel(const float* __restrict__ gamma,
                            const float* __restrict__ mbias,
                            const float* __restrict__ constraint)
{
    __shared__ __align__(16) float4 sv[2][8][128];      // 32 KB staging
    __shared__ __align__(16) float s_part[8][8][36];    // 9 KB partials
    const int i     = blockIdx.y;
    const int warp  = threadIdx.x >> 5;
    const int lane  = threadIdx.x & 31;
    const int bhalf = warp & 1;
    const int d     = blockIdx.x * 4 + (warp >> 1);
    const int j1 = (i == 0) ? 1 : 0;
    const int j2 = (i == 2) ? 1 : 2;

    const float cL  = constraint[i] * L2E;
    const float isc = INV_SCALE * L2E;
    const float a0 = __ldg(&g_WFT[((size_t)i * DD + d) * BB + bhalf * 32 + lane]);

    float hr[16];
    #pragma unroll
    for (int q = 0; q < 16; ++q) hr[q] = 0.0f;

    {
        const float g1 = sigm_(gamma[i * MM + j1]);
        const float m1 = mbias[i * MM + j1];
        run_pass<0>(sv, s_part[warp], j1, d, lane, warp, bhalf, a0, hr, cL, isc, g1, m1,
                    g_A1 + (size_t)i * BB * DD);
    }

    // ---- exchange hr across the warp pair (reuse sv buffer) ----
    __syncthreads();
    float* hx = (float*)sv;
    #pragma unroll
    for (int k = 0; k < 4; ++k)
        *(float4*)&hx[warp * 512 + (k * 32 + lane) * 4] =
            make_float4(hr[k*4+0], hr[k*4+1], hr[k*4+2], hr[k*4+3]);
    __syncthreads();
    {
        const int p = warp ^ 1;
        #pragma unroll
        for (int k = 0; k < 4; ++k) {
            float4 hp = *(const float4*)&hx[p * 512 + (k * 32 + lane) * 4];
            hr[k*4+0] = (hr[k*4+0] + hp.x) * (1.0f / 320.0f);
            hr[k*4+1] = (hr[k*4+1] + hp.y) * (1.0f / 320.0f);
            hr[k*4+2] = (hr[k*4+2] + hp.z) * (1.0f / 320.0f);
            hr[k*4+3] = (hr[k*4+3] + hp.w) * (1.0f / 320.0f);
        }
    }
    __syncthreads();

    {
        const float g2 = sigm_(gamma[i * MM + j2]);
        const float m2 = mbias[i * MM + j2];
        run_pass<1>(sv, s_part[warp], j2, d, lane, warp, bhalf, a0, hr, cL, isc, g2, m2,
                    g_A2 + (size_t)i * BB * DD);
    }
}

// ================= K5: combine + attention weights =================
__global__ void combine_kernel(float* __restrict__ out,
                               const float* __restrict__ gamma,
                               int out_size)
{
    int idx = blockIdx.x * blockDim.x + threadIdx.x;  // < 32768
    const int NBD = BB * DD;
    float w = (g_WF[idx] + g_WF[NBD + idx] + g_WF[2*NBD + idx]) * (1.0f / 3.0f);
    float a = g_A1[idx] + g_A1[NBD + idx] + g_A1[2*NBD + idx]
            + g_A2[idx] + g_A2[NBD + idx] + g_A2[2*NBD + idx];
    out[idx] = w + a * (1.0f / 6.0f);

    if (idx < MM && out_size >= NBD + MM) {
        float sc[MM];
        #pragma unroll
        for (int ii = 0; ii < MM; ++ii) {
            int j1 = (ii == 0) ? 1 : 0;
            int j2 = (ii == 2) ? 1 : 2;
            sc[ii] = 0.5f * (sigm_(gamma[ii * MM + j1]) + sigm_(gamma[ii * MM + j2]));
        }
        float mx = fmaxf(sc[0], fmaxf(sc[1], sc[2]));
        float e0 = ex2f_((sc[0] - mx) * L2E);
        float e1 = ex2f_((sc[1] - mx) * L2E);
        float e2 = ex2f_((sc[2] - mx) * L2E);
        float inv = frcp_(e0 + e1 + e2);
        float ei = (idx == 0) ? e0 : ((idx == 1) ? e1 : e2);
        out[NBD + idx] = ei * inv;
    }
}

// ================= launch =================
extern "C" void kernel_launch(void* const* d_in, const int* in_sizes, int n_in,
                              void* d_out, int out_size)
{
    const float* x      = (const float*)d_in[0];
    const float* proj_W = (const float*)d_in[1];
    const float* proj_b = (const float*)d_in[2];
    const float* ln_g   = (const float*)d_in[3];
    const float* ln_b   = (const float*)d_in[4];
    const float* imp_W1 = (const float*)d_in[5];
    const float* imp_b1 = (const float*)d_in[6];
    const float* imp_W2 = (const float*)d_in[7];
    const float* imp_b2 = (const float*)d_in[8];
    const float* gamma  = (const float*)d_in[9];
    const float* mbias  = (const float*)d_in[10];
    const float* constr = (const float*)d_in[11];
    float* out = (float*)d_out;

    // 1) y = x @ proj_W^T (split-K 4) + grid-sync + LN/ReLU
    k1_gemm1_ln<<<dim3(8, NSPL, MM), 256>>>(x, proj_W, proj_b, ln_g, ln_b);
    // 2) HA = relu(proj @ W1^T + b1)
    gemm_hidden_kernel<<<dim3(16, MM), 128>>>(imp_W1, imp_b1);
    // 3) CW = HA @ W2^T fused with wf epilogue
    gemm_cw_wf_kernel<<<dim3(16, MM), 256>>>(imp_W2, imp_b2);
    // 4) merged attention, deferred smem reductions (profiled slot)
    attn_kernel<<<dim3(128, MM), 256>>>(gamma, mbias, constr);
    // 5) combine
    combine_kernel<<<64, 512>>>(out, gamma, out_size);
}

// round 8
// speedup vs baseline: 2.0936x; 1.0443x over previous
#include <cuda_runtime.h>
#include <cstdint>

#define FULLMASK 0xffffffffu
#define MM 3
#define BB 64
#define DD 512
#define DQ 128
#define L2E 1.4426950408889634f
#define INV_SCALE 0.044194173824159216f   /* 1/sqrt(512) */
#define NSPL 4
#define K1_BLOCKS (8 * NSPL * MM)   /* 96 <= 148, co-resident */

typedef unsigned long long u64t;

#define PK2(out, lo, hi)  asm("mov.b64 %0, {%1, %2};" : "=l"(out) : "f"(lo), "f"(hi))
#define UPK2(lo, hi, in)  asm("mov.b64 {%0, %1}, %2;" : "=f"(lo), "=f"(hi) : "l"(in))
#define MUL2(out, a, b)   asm("mul.rn.f32x2 %0, %1, %2;" : "=l"(out) : "l"(a), "l"(b))
#define ADD2(out, a, b)   asm("add.rn.f32x2 %0, %1, %2;" : "=l"(out) : "l"(a), "l"(b))
#define FMA2(out, a, b, c) asm("fma.rn.f32x2 %0, %1, %2, %3;" : "=l"(out) : "l"(a), "l"(b), "l"(c))

// ---------------- scratch ----------------
__device__ float g_Y4[NSPL * MM * BB * DD];
__device__ float g_P [MM * BB * DD];
__device__ float g_HA[MM * BB * DQ];
__device__ float g_WF[MM * BB * DD];
__device__ float g_WFT[MM * DD * BB];
__device__ float g_S [MM * BB];
__device__ float g_A1[MM * BB * DD];
__device__ float g_A2[MM * BB * DD];
__device__ unsigned g_bar1;

__device__ __forceinline__ float ex2f_(float x) {
    float r; asm("ex2.approx.ftz.f32 %0, %1;" : "=f"(r) : "f"(x)); return r;
}
__device__ __forceinline__ float frcp_(float x) {
    float r; asm("rcp.approx.ftz.f32 %0, %1;" : "=f"(r) : "f"(x)); return r;
}
__device__ __forceinline__ float sigm_(float x) {
    return frcp_(1.0f + ex2f_(-x * L2E));
}

// ================= K1: gemm1 (split-K 4) + grid barrier + LN/ReLU =================
__global__ void k1_gemm1_ln(const float* __restrict__ X, const float* __restrict__ W,
                            const float* __restrict__ pb, const float* __restrict__ lg,
                            const float* __restrict__ lb)
{
    __shared__ float As[16][64];
    __shared__ float Bs[16][64];
    __shared__ float red[18];

    const int i  = blockIdx.z;
    const int n0 = blockIdx.x * 64;
    const int k0 = blockIdx.y * 128;
    const int tid = threadIdx.x;
    const int tx = tid & 15, ty = tid >> 4;

    const float* Xb = X + (size_t)i * BB * DD;
    const float* Wb = W + (size_t)i * DD * DD;

    float acc[4][4] = {};
    for (int kk = 0; kk < 128; kk += 16) {
        {
            int r  = tid >> 2;
            int c4 = (tid & 3) * 4;
            float4 xa = *(const float4*)&Xb[(size_t)r * DD + k0 + kk + c4];
            As[c4+0][r] = xa.x; As[c4+1][r] = xa.y; As[c4+2][r] = xa.z; As[c4+3][r] = xa.w;
            float4 wa = *(const float4*)&Wb[(size_t)(n0 + r) * DD + k0 + kk + c4];
            Bs[c4+0][r] = wa.x; Bs[c4+1][r] = wa.y; Bs[c4+2][r] = wa.z; Bs[c4+3][r] = wa.w;
        }
        __syncthreads();
        #pragma unroll
        for (int p = 0; p < 16; ++p) {
            float4 a4 = *(const float4*)&As[p][ty * 4];
            float4 b4 = *(const float4*)&Bs[p][tx * 4];
            float av[4] = {a4.x, a4.y, a4.z, a4.w};
            float bv[4] = {b4.x, b4.y, b4.z, b4.w};
            #pragma unroll
            for (int m2 = 0; m2 < 4; ++m2)
                #pragma unroll
                for (int n2 = 0; n2 < 4; ++n2)
                    acc[m2][n2] = fmaf(av[m2], bv[n2], acc[m2][n2]);
        }
        __syncthreads();
    }
    {
        float* Cout = g_Y4 + (size_t)blockIdx.y * (MM * BB * DD) + (size_t)i * BB * DD;
        #pragma unroll
        for (int m2 = 0; m2 < 4; ++m2) {
            int b = ty * 4 + m2;
            float4 v = make_float4(acc[m2][0], acc[m2][1], acc[m2][2], acc[m2][3]);
            *(float4*)&Cout[(size_t)b * DD + n0 + tx * 4] = v;
        }
    }

    __threadfence();
    __syncthreads();
    if (tid == 0) {
        unsigned old = atomicAdd(&g_bar1, 1u);
        unsigned target = (old / K1_BLOCKS + 1u) * K1_BLOCKS;
        while ((int)(*(volatile unsigned*)&g_bar1 - target) < 0) {
            __nanosleep(32);
        }
    }
    __syncthreads();

    const int flat = (blockIdx.z * NSPL + blockIdx.y) * 8 + blockIdx.x;
    const int warp = tid >> 5, lane = tid & 31;
    if (flat == 0 && tid < MM * BB) g_S[tid] = 0.0f;

    #pragma unroll
    for (int rr = 0; rr < 2; ++rr) {
        const int row = flat * 2 + rr;
        const int i2  = row >> 6;
        const size_t base = (size_t)row * DD;
        const int e0 = tid, e1 = tid + 256;

        float y0 = pb[i2 * DD + e0];
        float y1 = pb[i2 * DD + e1];
        #pragma unroll
        for (int s = 0; s < NSPL; ++s) {
            y0 += g_Y4[(size_t)s * MM * BB * DD + base + e0];
            y1 += g_Y4[(size_t)s * MM * BB * DD + base + e1];
        }
        float s = y0 + y1, q = y0 * y0 + y1 * y1;
        #pragma unroll
        for (int off = 16; off; off >>= 1) {
            s += __shfl_xor_sync(FULLMASK, s, off);
            q += __shfl_xor_sync(FULLMASK, q, off);
        }
        if (lane == 0) { red[warp] = s; red[8 + warp] = q; }
        __syncthreads();
        if (warp == 0) {
            float s2 = red[lane & 7], q2 = red[8 + (lane & 7)];
            #pragma unroll
            for (int off = 4; off; off >>= 1) {
                s2 += __shfl_xor_sync(FULLMASK, s2, off);
                q2 += __shfl_xor_sync(FULLMASK, q2, off);
            }
            if (lane == 0) { red[16] = s2; red[17] = q2; }
        }
        __syncthreads();
        float mu  = red[16] * (1.0f / DD);
        float var = red[17] * (1.0f / DD) - mu * mu;
        float rs  = rsqrtf(var + 1e-5f);
        float p0 = (y0 - mu) * rs * lg[i2 * DD + e0] + lb[i2 * DD + e0];
        float p1 = (y1 - mu) * rs * lg[i2 * DD + e1] + lb[i2 * DD + e1];
        g_P[base + e0] = fmaxf(p0, 0.0f);
        g_P[base + e1] = fmaxf(p1, 0.0f);
        __syncthreads();
    }
}

// ================= K2: HA = relu(P @ W1^T + b1) =================
__global__ void gemm_hidden_kernel(const float* __restrict__ W1, const float* __restrict__ b1)
{
    const int i  = blockIdx.y;
    const int b0 = (blockIdx.x & 7) * 8;
    const int n0 = (blockIdx.x >> 3) * 64;
    const int tid = threadIdx.x;
    const int tx = tid & 15, ty = tid >> 4;

    __shared__ __align__(16) float As[32][8];
    __shared__ __align__(16) float Bs[32][64];

    const float* Pb = g_P + (size_t)i * BB * DD;
    const float* Wb = W1 + (size_t)i * DQ * DD;

    float acc[4] = {};
    for (int k0 = 0; k0 < DD; k0 += 32) {
        if (tid < 64) {
            int r = tid >> 3, q = tid & 7;
            float4 v = *(const float4*)&Pb[(size_t)(b0 + r) * DD + k0 + q * 4];
            As[q*4+0][r] = v.x; As[q*4+1][r] = v.y; As[q*4+2][r] = v.z; As[q*4+3][r] = v.w;
        }
        #pragma unroll
        for (int q = 0; q < 4; ++q) {
            int idx = tid * 4 + q;
            int nr = idx >> 3, kq = idx & 7;
            float4 v = *(const float4*)&Wb[(size_t)(n0 + nr) * DD + k0 + kq * 4];
            Bs[kq*4+0][nr] = v.x; Bs[kq*4+1][nr] = v.y; Bs[kq*4+2][nr] = v.z; Bs[kq*4+3][nr] = v.w;
        }
        __syncthreads();
        #pragma unroll
        for (int k = 0; k < 32; ++k) {
            float a = As[k][ty];
            float4 w4 = *(const float4*)&Bs[k][tx * 4];
            acc[0] = fmaf(a, w4.x, acc[0]);
            acc[1] = fmaf(a, w4.y, acc[1]);
            acc[2] = fmaf(a, w4.z, acc[2]);
            acc[3] = fmaf(a, w4.w, acc[3]);
        }
        __syncthreads();
    }
    float4 o;
    o.x = fmaxf(acc[0] + b1[i*DQ + n0 + tx*4 + 0], 0.0f);
    o.y = fmaxf(acc[1] + b1[i*DQ + n0 + tx*4 + 1], 0.0f);
    o.z = fmaxf(acc[2] + b1[i*DQ + n0 + tx*4 + 2], 0.0f);
    o.w = fmaxf(acc[3] + b1[i*DQ + n0 + tx*4 + 3], 0.0f);
    *(float4*)&g_HA[((size_t)i * BB + b0 + ty) * DQ + n0 + tx * 4] = o;
}

// ================= K3: CW = HA @ W2^T + fused wf epilogue =================
__global__ void gemm_cw_wf_kernel(const float* __restrict__ W2,
                                  const float* __restrict__ b2v)
{
    const int i  = blockIdx.y;
    const int n0 = blockIdx.x * 32;
    const int tid = threadIdx.x;
    const int tx = tid & 7, ty = tid >> 3;

    __shared__ __align__(16) float As2[64][DQ];
    __shared__ __align__(16) float Bs[DQ][36];

    #pragma unroll
    for (int q = 0; q < 8; ++q) {
        int idx = tid + q * 256;
        int b = idx >> 5, kq = idx & 31;
        float4 v = *(const float4*)&g_HA[((size_t)i * BB + b) * DQ + kq * 4];
        *(float4*)&As2[b][kq * 4] = v;
    }
    #pragma unroll
    for (int q = 0; q < 4; ++q) {
        int idx = tid + q * 256;
        int nr = idx >> 5, kq = idx & 31;
        float4 v = *(const float4*)&W2[((size_t)i * DD + n0 + nr) * DQ + kq * 4];
        Bs[kq*4+0][nr] = v.x; Bs[kq*4+1][nr] = v.y; Bs[kq*4+2][nr] = v.z; Bs[kq*4+3][nr] = v.w;
    }
    __syncthreads();

    float acc[2][4] = {};
    #pragma unroll 8
    for (int k4 = 0; k4 < 32; ++k4) {
        float4 a0 = *(const float4*)&As2[ty][k4 * 4];
        float4 a1 = *(const float4*)&As2[ty + 32][k4 * 4];
        float av0[4] = {a0.x, a0.y, a0.z, a0.w};
        float av1[4] = {a1.x, a1.y, a1.z, a1.w};
        #pragma unroll
        for (int q = 0; q < 4; ++q) {
            float4 b4 = *(const float4*)&Bs[k4 * 4 + q][tx * 4];
            float bv[4] = {b4.x, b4.y, b4.z, b4.w};
            #pragma unroll
            for (int n2 = 0; n2 < 4; ++n2) {
                acc[0][n2] = fmaf(av0[q], bv[n2], acc[0][n2]);
                acc[1][n2] = fmaf(av1[q], bv[n2], acc[1][n2]);
            }
        }
    }

    #pragma unroll
    for (int rr = 0; rr < 2; ++rr) {
        int b = ty + rr * 32;
        int n = n0 + tx * 4;
        float4 p4 = *(const float4*)&g_P[((size_t)i * BB + b) * DD + n];
        float pv[4] = {p4.x, p4.y, p4.z, p4.w};
        float w[4], srow = 0.0f;
        #pragma unroll
        for (int q = 0; q < 4; ++q) {
            float pre = acc[rr][q] + b2v[i * DD + n + q];
            w[q] = pv[q] * sigm_(pre);
            srow += w[q];
            g_WFT[((size_t)i * DD + n + q) * BB + b] = w[q];
        }
        *(float4*)&g_WF[((size_t)i * BB + b) * DD + n] = make_float4(w[0], w[1], w[2], w[3]);
        #pragma unroll
        for (int off = 4; off; off >>= 1)
            srow += __shfl_xor_sync(FULLMASK, srow, off);
        if (tx == 0) atomicAdd(&g_S[i * BB + b], srow);
    }
}

// ================= K4: merged pairwise attention, f32x2 packed =================
// block 256 = 8 warps: warp = d_local*2 + bhalf.  grid (128, MM).

template<int PASS>
__device__ __forceinline__ void run_pass(float4 (*sv)[8][128],
                                         float (*pw)[36],
                                         int j, int d, int lane, int warp, int bhalf,
                                         float a0, u64t (&hrp)[8],
                                         float cL, float isc, float g, float mb,
                                         float* __restrict__ accout)
{
    const int tid = warp * 32 + lane;
    const int bs = bhalf * 32;
    const float* wfj = g_WF + (size_t)j * BB * DD;
    const float isc8 = isc * 0.8f, isc2 = isc * 0.2f, cL8 = cL * 0.8f;

    u64t k02p, k08p, hnp[8];
    if (PASS == 1) {
        PK2(k02p, 0.2f, 0.2f);
        PK2(k08p, 0.8f, 0.8f);
        u64t kn1; PK2(kn1, -1.0f, -1.0f);
        #pragma unroll
        for (int q = 0; q < 8; ++q) MUL2(hnp[q], hrp[q], kn1);
    }

    // prologue: stage chunk 0
    #pragma unroll
    for (int q = 0; q < 4; ++q) {
        int idx = tid + q * 256;
        int rl = idx >> 7, col = idx & 127;
        int grow = (rl >> 2) * 32 + (rl & 3);
        sv[0][rl][col] = *(const float4*)&wfj[(size_t)grow * DD + col * 4];
    }
    __syncthreads();

    for (int c = 0; c < 8; ++c) {
        const int buf = c & 1;
        float4 nx[4];
        if (c < 7) {
            #pragma unroll
            for (int q = 0; q < 4; ++q) {
                int idx = tid + q * 256;
                int rl = idx >> 7, col = idx & 127;
                int grow = (rl >> 2) * 32 + (c + 1) * 4 + (rl & 3);
                nx[q] = *(const float4*)&wfj[(size_t)grow * DD + col * 4];
            }
        }
        #pragma unroll
        for (int bi = 0; bi < 4; ++bi) {
            const int bl = c * 4 + bi;
            float a  = __shfl_sync(FULLMASK, a0, bl);

            u64t sep, dotp;
            { float z = 0.0f; PK2(sep, z, z); PK2(dotp, z, z); }
            const float4* vr = sv[buf][bhalf * 4 + bi];

            if (PASS == 0) {
                u64t ap8p, ap2p;
                { float a8 = a * isc8, a2 = a * isc2; PK2(ap8p, a8, a8); PK2(ap2p, a2, a2); }
                #pragma unroll
                for (int k = 0; k < 4; ++k) {
                    float4 v = vr[k * 32 + lane];
                    u64t vp[2]; PK2(vp[0], v.x, v.y); PK2(vp[1], v.z, v.w);
                    #pragma unroll
                    for (int h2 = 0; h2 < 2; ++h2) {
                        u64t cur; MUL2(cur, ap8p, vp[h2]);
                        float c0, c1; UPK2(c0, c1, cur);
                        float m0 = fminf(fmaxf(c0, -cL8), cL8);
                        float m1 = fminf(fmaxf(c1, -cL8), cL8);
                        u64t mp; PK2(mp, m0, m1);
                        u64t f; FMA2(f, ap2p, vp[h2], mp);
                        ADD2(hrp[k*2+h2], hrp[k*2+h2], f);
                        float f0, f1; UPK2(f0, f1, f);
                        float e0 = ex2f_(f0), e1 = ex2f_(f1);
                        u64t ep; PK2(ep, e0, e1);
                        ADD2(sep, sep, ep);
                        FMA2(dotp, ep, vp[h2], dotp);
                    }
                }
            } else {
                u64t app;
                { float av = a * isc; PK2(app, av, av); }
                #pragma unroll
                for (int k = 0; k < 4; ++k) {
                    float4 v = vr[k * 32 + lane];
                    u64t vp[2]; PK2(vp[0], v.x, v.y); PK2(vp[1], v.z, v.w);
                    #pragma unroll
                    for (int h2 = 0; h2 < 2; ++h2) {
                        u64t u_; FMA2(u_, app, vp[h2], hnp[k*2+h2]);
                        float u0, u1; UPK2(u0, u1, u_);
                        float m0 = fminf(fmaxf(u0, -cL), cL);
                        float m1 = fminf(fmaxf(u1, -cL), cL);
                        u64t mp; PK2(mp, m0, m1);
                        u64t t; FMA2(t, k02p, u_, hrp[k*2+h2]);
                        u64t f; FMA2(f, k08p, mp, t);
                        float f0, f1; UPK2(f0, f1, f);
                        float e0 = ex2f_(f0), e1 = ex2f_(f1);
                        u64t ep; PK2(ep, e0, e1);
                        ADD2(sep, sep, ep);
                        FMA2(dotp, ep, vp[h2], dotp);
                    }
                }
            }
            float sl, sh, dl, dh;
            UPK2(sl, sh, sep); UPK2(dl, dh, dotp);
            pw[bi * 2 + 0][lane] = sl + sh;
            pw[bi * 2 + 1][lane] = dl + dh;
        }
        __syncwarp();
        if (lane < 8) {
            const float4* pr = (const float4*)pw[lane];
            float4 p0 = pr[0], p1 = pr[1], p2 = pr[2], p3 = pr[3];
            float4 p4 = pr[4], p5 = pr[5], p6 = pr[6], p7 = pr[7];
            p0.x += p1.x; p0.y += p1.y; p0.z += p1.z; p0.w += p1.w;
            p2.x += p3.x; p2.y += p3.y; p2.z += p3.z; p2.w += p3.w;
            p4.x += p5.x; p4.y += p5.y; p4.z += p5.z; p4.w += p5.w;
            p6.x += p7.x; p6.y += p7.y; p6.z += p7.z; p6.w += p7.w;
            p0.x += p2.x; p0.y += p2.y; p0.z += p2.z; p0.w += p2.w;
            p4.x += p6.x; p4.y += p6.y; p4.z += p6.z; p4.w += p6.w;
            float val = (p0.x + p4.x) + (p0.y + p4.y) + (p0.z + p4.z) + (p0.w + p4.w);
            float sev = __shfl_sync(0xFFu, val, lane & ~1);
            if (lane & 1) {
                int bl = c * 4 + (lane >> 1);
                float sj = __ldg(&g_S[j * BB + bs + bl]);
                accout[(size_t)(bs + bl) * DD + d] = g * (val * frcp_(sev) + mb * sj);
            }
        }
        if (c < 7) {
            #pragma unroll
            for (int q = 0; q < 4; ++q) {
                int idx = tid + q * 256;
                int rl = idx >> 7, col = idx & 127;
                sv[buf ^ 1][rl][col] = nx[q];
            }
        }
        __syncthreads();
    }
}

__global__ __launch_bounds__(256) void attn_kernel(const float* __restrict__ gamma,
                            const float* __restrict__ mbias,
                            const float* __restrict__ constraint)
{
    __shared__ __align__(16) float4 sv[2][8][128];      // 32 KB staging
    __shared__ __align__(16) float s_part[8][8][36];    // 9 KB partials
    const int i     = blockIdx.y;
    const int warp  = threadIdx.x >> 5;
    const int lane  = threadIdx.x & 31;
    const int bhalf = warp & 1;
    const int d     = blockIdx.x * 4 + (warp >> 1);
    const int j1 = (i == 0) ? 1 : 0;
    const int j2 = (i == 2) ? 1 : 2;

    const float cL  = constraint[i] * L2E;
    const float isc = INV_SCALE * L2E;
    const float a0 = __ldg(&g_WFT[((size_t)i * DD + d) * BB + bhalf * 32 + lane]);

    u64t hrp[8];
    { float z = 0.0f; u64t zp; PK2(zp, z, z);
      #pragma unroll
      for (int q = 0; q < 8; ++q) hrp[q] = zp; }

    {
        const float g1 = sigm_(gamma[i * MM + j1]);
        const float m1 = mbias[i * MM + j1];
        run_pass<0>(sv, s_part[warp], j1, d, lane, warp, bhalf, a0, hrp, cL, isc, g1, m1,
                    g_A1 + (size_t)i * BB * DD);
    }

    // ---- exchange hr across the warp pair (reuse sv buffer) ----
    __syncthreads();
    u64t* hx = (u64t*)sv;                     // 8 warps x 256 u64 = 16 KB
    #pragma unroll
    for (int k = 0; k < 4; ++k) {
        // store 2 u64 (one float4) per k
        float4* dst = (float4*)&hx[warp * 256 + (k * 32 + lane) * 2];
        float h0, h1, h2, h3;
        UPK2(h0, h1, hrp[k*2+0]); UPK2(h2, h3, hrp[k*2+1]);
        *dst = make_float4(h0, h1, h2, h3);
    }
    __syncthreads();
    {
        const int p = warp ^ 1;
        u64t k320; PK2(k320, (1.0f/320.0f), (1.0f/320.0f));
        #pragma unroll
        for (int k = 0; k < 4; ++k) {
            float4 hp = *(const float4*)&hx[p * 256 + (k * 32 + lane) * 2];
            u64t hp0, hp1; PK2(hp0, hp.x, hp.y); PK2(hp1, hp.z, hp.w);
            u64t s0, s1;
            ADD2(s0, hrp[k*2+0], hp0);
            ADD2(s1, hrp[k*2+1], hp1);
            MUL2(hrp[k*2+0], s0, k320);
            MUL2(hrp[k*2+1], s1, k320);
        }
    }
    __syncthreads();

    {
        const float g2 = sigm_(gamma[i * MM + j2]);
        const float m2 = mbias[i * MM + j2];
        run_pass<1>(sv, s_part[warp], j2, d, lane, warp, bhalf, a0, hrp, cL, isc, g2, m2,
                    g_A2 + (size_t)i * BB * DD);
    }
}

// ================= K5: combine + attention weights =================
__global__ void combine_kernel(float* __restrict__ out,
                               const float* __restrict__ gamma,
                               int out_size)
{
    int idx = blockIdx.x * blockDim.x + threadIdx.x;
    const int NBD = BB * DD;
    float w = (g_WF[idx] + g_WF[NBD + idx] + g_WF[2*NBD + idx]) * (1.0f / 3.0f);
    float a = g_A1[idx] + g_A1[NBD + idx] + g_A1[2*NBD + idx]
            + g_A2[idx] + g_A2[NBD + idx] + g_A2[2*NBD + idx];
    out[idx] = w + a * (1.0f / 6.0f);

    if (idx < MM && out_size >= NBD + MM) {
        float sc[MM];
        #pragma unroll
        for (int ii = 0; ii < MM; ++ii) {
            int j1 = (ii == 0) ? 1 : 0;
            int j2 = (ii == 2) ? 1 : 2;
            sc[ii] = 0.5f * (sigm_(gamma[ii * MM + j1]) + sigm_(gamma[ii * MM + j2]));
        }
        float mx = fmaxf(sc[0], fmaxf(sc[1], sc[2]));
        float e0 = ex2f_((sc[0] - mx) * L2E);
        float e1 = ex2f_((sc[1] - mx) * L2E);
        float e2 = ex2f_((sc[2] - mx) * L2E);
        float inv = frcp_(e0 + e1 + e2);
        float ei = (idx == 0) ? e0 : ((idx == 1) ? e1 : e2);
        out[NBD + idx] = ei * inv;
    }
}

// ================= launch =================
extern "C" void kernel_launch(void* const* d_in, const int* in_sizes, int n_in,
                              void* d_out, int out_size)
{
    const float* x      = (const float*)d_in[0];
    const float* proj_W = (const float*)d_in[1];
    const float* proj_b = (const float*)d_in[2];
    const float* ln_g   = (const float*)d_in[3];
    const float* ln_b   = (const float*)d_in[4];
    const float* imp_W1 = (const float*)d_in[5];
    const float* imp_b1 = (const float*)d_in[6];
    const float* imp_W2 = (const float*)d_in[7];
    const float* imp_b2 = (const float*)d_in[8];
    const float* gamma  = (const float*)d_in[9];
    const float* mbias  = (const float*)d_in[10];
    const float* constr = (const float*)d_in[11];
    float* out = (float*)d_out;

    k1_gemm1_ln<<<dim3(8, NSPL, MM), 256>>>(x, proj_W, proj_b, ln_g, ln_b);
    gemm_hidden_kernel<<<dim3(16, MM), 128>>>(imp_W1, imp_b1);
    gemm_cw_wf_kernel<<<dim3(16, MM), 256>>>(imp_W2, imp_b2);
    attn_kernel<<<dim3(128, MM), 256>>>(gamma, mbias, constr);
    combine_kernel<<<64, 512>>>(out, gamma, out_size);
}

// round 9
// speedup vs baseline: 2.0983x; 1.0023x over previous
#include <cuda_runtime.h>
#include <cstdint>
#include <cstring>

#define FULLMASK 0xffffffffu
#define MM 3
#define BB 64
#define DD 512
#define DQ 128
#define L2E 1.4426950408889634f
#define INV_SCALE 0.044194173824159216f   /* 1/sqrt(512) */
#define NSPL 8
#define K1_BLOCKS (8 * NSPL * MM)   /* 192; 2-per-SM co-resident */

typedef unsigned long long u64t;

#define MUL2(out, a, b)   asm("mul.rn.f32x2 %0, %1, %2;" : "=l"(out) : "l"(a), "l"(b))
#define ADD2(out, a, b)   asm("add.rn.f32x2 %0, %1, %2;" : "=l"(out) : "l"(a), "l"(b))
#define FMA2(out, a, b, c) asm("fma.rn.f32x2 %0, %1, %2, %3;" : "=l"(out) : "l"(a), "l"(b), "l"(c))
#define GBAR(g) asm volatile("bar.sync %0, 128;" :: "r"((g) + 1) : "memory")

__device__ __forceinline__ u64t pk2f(float lo, float hi) {
    float2 t = make_float2(lo, hi); u64t r; memcpy(&r, &t, 8); return r;
}
__device__ __forceinline__ float2 upk2f(u64t v) {
    float2 t; memcpy(&t, &v, 8); return t;
}

// ---------------- scratch ----------------
__device__ float g_Y4[NSPL * MM * BB * DD];
__device__ float g_P [MM * BB * DD];
__device__ float g_HA[MM * BB * DQ];
__device__ float g_WF[MM * BB * DD];
__device__ float g_WFT[MM * DD * BB];
__device__ float g_S [MM * BB];
__device__ float g_A1[MM * BB * DD];
__device__ float g_A2[MM * BB * DD];
__device__ unsigned g_bar1;

__device__ __forceinline__ float ex2f_(float x) {
    float r; asm("ex2.approx.ftz.f32 %0, %1;" : "=f"(r) : "f"(x)); return r;
}
__device__ __forceinline__ float frcp_(float x) {
    float r; asm("rcp.approx.ftz.f32 %0, %1;" : "=f"(r) : "f"(x)); return r;
}
__device__ __forceinline__ float sigm_(float x) {
    return frcp_(1.0f + ex2f_(-x * L2E));
}

// ================= K1: gemm1 (split-K 8) + grid barrier + LN/ReLU =================
// grid dim3(8, NSPL, MM) = 192 blocks, 256 threads.
__global__ __launch_bounds__(256, 2) void k1_gemm1_ln(
    const float* __restrict__ X, const float* __restrict__ W,
    const float* __restrict__ pb, const float* __restrict__ lg,
    const float* __restrict__ lb)
{
    __shared__ float As[16][64];
    __shared__ float Bs[16][64];
    __shared__ float red[18];

    const int i  = blockIdx.z;
    const int n0 = blockIdx.x * 64;
    const int k0 = blockIdx.y * 64;
    const int tid = threadIdx.x;
    const int tx = tid & 15, ty = tid >> 4;

    const float* Xb = X + (size_t)i * BB * DD;
    const float* Wb = W + (size_t)i * DD * DD;

    float acc[4][4] = {};
    for (int kk = 0; kk < 64; kk += 16) {
        {
            int r  = tid >> 2;
            int c4 = (tid & 3) * 4;
            float4 xa = *(const float4*)&Xb[(size_t)r * DD + k0 + kk + c4];
            As[c4+0][r] = xa.x; As[c4+1][r] = xa.y; As[c4+2][r] = xa.z; As[c4+3][r] = xa.w;
            float4 wa = *(const float4*)&Wb[(size_t)(n0 + r) * DD + k0 + kk + c4];
            Bs[c4+0][r] = wa.x; Bs[c4+1][r] = wa.y; Bs[c4+2][r] = wa.z; Bs[c4+3][r] = wa.w;
        }
        __syncthreads();
        #pragma unroll
        for (int p = 0; p < 16; ++p) {
            float4 a4 = *(const float4*)&As[p][ty * 4];
            float4 b4 = *(const float4*)&Bs[p][tx * 4];
            float av[4] = {a4.x, a4.y, a4.z, a4.w};
            float bv[4] = {b4.x, b4.y, b4.z, b4.w};
            #pragma unroll
            for (int m2 = 0; m2 < 4; ++m2)
                #pragma unroll
                for (int n2 = 0; n2 < 4; ++n2)
                    acc[m2][n2] = fmaf(av[m2], bv[n2], acc[m2][n2]);
        }
        __syncthreads();
    }
    {
        float* Cout = g_Y4 + (size_t)blockIdx.y * (MM * BB * DD) + (size_t)i * BB * DD;
        #pragma unroll
        for (int m2 = 0; m2 < 4; ++m2) {
            int b = ty * 4 + m2;
            float4 v = make_float4(acc[m2][0], acc[m2][1], acc[m2][2], acc[m2][3]);
            *(float4*)&Cout[(size_t)b * DD + n0 + tx * 4] = v;
        }
    }

    __threadfence();
    __syncthreads();
    if (tid == 0) {
        unsigned old = atomicAdd(&g_bar1, 1u);
        unsigned target = (old / K1_BLOCKS + 1u) * K1_BLOCKS;
        while ((int)(*(volatile unsigned*)&g_bar1 - target) < 0) {
            __nanosleep(32);
        }
    }
    __syncthreads();

    // ---- phase 2: LN + ReLU, 1 row per block ----
    const int flat = (blockIdx.z * NSPL + blockIdx.y) * 8 + blockIdx.x;  // 0..191
    const int warp = tid >> 5, lane = tid & 31;
    if (flat == 0 && tid < MM * BB) g_S[tid] = 0.0f;

    const int row = flat;
    const int i2  = row >> 6;
    const size_t base = (size_t)row * DD;
    const int e0 = tid, e1 = tid + 256;

    float y0 = pb[i2 * DD + e0];
    float y1 = pb[i2 * DD + e1];
    #pragma unroll
    for (int s = 0; s < NSPL; ++s) {
        y0 += g_Y4[(size_t)s * MM * BB * DD + base + e0];
        y1 += g_Y4[(size_t)s * MM * BB * DD + base + e1];
    }
    float s = y0 + y1, q = y0 * y0 + y1 * y1;
    #pragma unroll
    for (int off = 16; off; off >>= 1) {
        s += __shfl_xor_sync(FULLMASK, s, off);
        q += __shfl_xor_sync(FULLMASK, q, off);
    }
    if (lane == 0) { red[warp] = s; red[8 + warp] = q; }
    __syncthreads();
    if (warp == 0) {
        float s2 = red[lane & 7], q2 = red[8 + (lane & 7)];
        #pragma unroll
        for (int off = 4; off; off >>= 1) {
            s2 += __shfl_xor_sync(FULLMASK, s2, off);
            q2 += __shfl_xor_sync(FULLMASK, q2, off);
        }
        if (lane == 0) { red[16] = s2; red[17] = q2; }
    }
    __syncthreads();
    float mu  = red[16] * (1.0f / DD);
    float var = red[17] * (1.0f / DD) - mu * mu;
    float rs  = rsqrtf(var + 1e-5f);
    float p0 = (y0 - mu) * rs * lg[i2 * DD + e0] + lb[i2 * DD + e0];
    float p1 = (y1 - mu) * rs * lg[i2 * DD + e1] + lb[i2 * DD + e1];
    g_P[base + e0] = fmaxf(p0, 0.0f);
    g_P[base + e1] = fmaxf(p1, 0.0f);
}

// ================= K2: HA = relu(P @ W1^T + b1) =================
__global__ void gemm_hidden_kernel(const float* __restrict__ W1, const float* __restrict__ b1)
{
    const int i  = blockIdx.y;
    const int b0 = (blockIdx.x & 7) * 8;
    const int n0 = (blockIdx.x >> 3) * 64;
    const int tid = threadIdx.x;
    const int tx = tid & 15, ty = tid >> 4;

    __shared__ __align__(16) float As[32][8];
    __shared__ __align__(16) float Bs[32][64];

    const float* Pb = g_P + (size_t)i * BB * DD;
    const float* Wb = W1 + (size_t)i * DQ * DD;

    float acc[4] = {};
    for (int k0 = 0; k0 < DD; k0 += 32) {
        if (tid < 64) {
            int r = tid >> 3, q = tid & 7;
            float4 v = *(const float4*)&Pb[(size_t)(b0 + r) * DD + k0 + q * 4];
            As[q*4+0][r] = v.x; As[q*4+1][r] = v.y; As[q*4+2][r] = v.z; As[q*4+3][r] = v.w;
        }
        #pragma unroll
        for (int q = 0; q < 4; ++q) {
            int idx = tid * 4 + q;
            int nr = idx >> 3, kq = idx & 7;
            float4 v = *(const float4*)&Wb[(size_t)(n0 + nr) * DD + k0 + kq * 4];
            Bs[kq*4+0][nr] = v.x; Bs[kq*4+1][nr] = v.y; Bs[kq*4+2][nr] = v.z; Bs[kq*4+3][nr] = v.w;
        }
        __syncthreads();
        #pragma unroll
        for (int k = 0; k < 32; ++k) {
            float a = As[k][ty];
            float4 w4 = *(const float4*)&Bs[k][tx * 4];
            acc[0] = fmaf(a, w4.x, acc[0]);
            acc[1] = fmaf(a, w4.y, acc[1]);
            acc[2] = fmaf(a, w4.z, acc[2]);
            acc[3] = fmaf(a, w4.w, acc[3]);
        }
        __syncthreads();
    }
    float4 o;
    o.x = fmaxf(acc[0] + b1[i*DQ + n0 + tx*4 + 0], 0.0f);
    o.y = fmaxf(acc[1] + b1[i*DQ + n0 + tx*4 + 1], 0.0f);
    o.z = fmaxf(acc[2] + b1[i*DQ + n0 + tx*4 + 2], 0.0f);
    o.w = fmaxf(acc[3] + b1[i*DQ + n0 + tx*4 + 3], 0.0f);
    *(float4*)&g_HA[((size_t)i * BB + b0 + ty) * DQ + n0 + tx * 4] = o;
}

// ================= K3: CW = HA @ W2^T + fused wf epilogue =================
__global__ void gemm_cw_wf_kernel(const float* __restrict__ W2,
                                  const float* __restrict__ b2v)
{
    const int i  = blockIdx.y;
    const int n0 = blockIdx.x * 32;
    const int tid = threadIdx.x;
    const int tx = tid & 7, ty = tid >> 3;

    __shared__ __align__(16) float As2[64][DQ];
    __shared__ __align__(16) float Bs[DQ][36];

    #pragma unroll
    for (int q = 0; q < 8; ++q) {
        int idx = tid + q * 256;
        int b = idx >> 5, kq = idx & 31;
        float4 v = *(const float4*)&g_HA[((size_t)i * BB + b) * DQ + kq * 4];
        *(float4*)&As2[b][kq * 4] = v;
    }
    #pragma unroll
    for (int q = 0; q < 4; ++q) {
        int idx = tid + q * 256;
        int nr = idx >> 5, kq = idx & 31;
        float4 v = *(const float4*)&W2[((size_t)i * DD + n0 + nr) * DQ + kq * 4];
        Bs[kq*4+0][nr] = v.x; Bs[kq*4+1][nr] = v.y; Bs[kq*4+2][nr] = v.z; Bs[kq*4+3][nr] = v.w;
    }
    __syncthreads();

    float acc[2][4] = {};
    #pragma unroll 8
    for (int k4 = 0; k4 < 32; ++k4) {
        float4 a0 = *(const float4*)&As2[ty][k4 * 4];
        float4 a1 = *(const float4*)&As2[ty + 32][k4 * 4];
        float av0[4] = {a0.x, a0.y, a0.z, a0.w};
        float av1[4] = {a1.x, a1.y, a1.z, a1.w};
        #pragma unroll
        for (int q = 0; q < 4; ++q) {
            float4 b4 = *(const float4*)&Bs[k4 * 4 + q][tx * 4];
            float bv[4] = {b4.x, b4.y, b4.z, b4.w};
            #pragma unroll
            for (int n2 = 0; n2 < 4; ++n2) {
                acc[0][n2] = fmaf(av0[q], bv[n2], acc[0][n2]);
                acc[1][n2] = fmaf(av1[q], bv[n2], acc[1][n2]);
            }
        }
    }

    #pragma unroll
    for (int rr = 0; rr < 2; ++rr) {
        int b = ty + rr * 32;
        int n = n0 + tx * 4;
        float4 p4 = *(const float4*)&g_P[((size_t)i * BB + b) * DD + n];
        float pv[4] = {p4.x, p4.y, p4.z, p4.w};
        float w[4], srow = 0.0f;
        #pragma unroll
        for (int q = 0; q < 4; ++q) {
            float pre = acc[rr][q] + b2v[i * DD + n + q];
            w[q] = pv[q] * sigm_(pre);
            srow += w[q];
            g_WFT[((size_t)i * DD + n + q) * BB + b] = w[q];
        }
        *(float4*)&g_WF[((size_t)i * BB + b) * DD + n] = make_float4(w[0], w[1], w[2], w[3]);
        #pragma unroll
        for (int off = 4; off; off >>= 1)
            srow += __shfl_xor_sync(FULLMASK, srow, off);
        if (tx == 0) atomicAdd(&g_S[i * BB + b], srow);
    }
}

// ================= K4: merged pairwise attention, f32x2 + group barriers =================
// block 256 = 8 warps: warp = d_local*2 + bhalf.  grid (128, MM).
// Each 4-warp bhalf-group stages only its own rows; group-scoped bar.sync.

template<int PASS>
__device__ __forceinline__ void run_pass(float4 (*sv)[8][128],
                                         float (*pw)[36],
                                         int j, int d, int lane, int warp, int bhalf,
                                         float a0, u64t (&hrp)[8],
                                         float cL, float isc, float g, float mb,
                                         float* __restrict__ accout)
{
    const int gtid = ((warp >> 1) << 5) + lane;   // 0..127 within group
    const int bs = bhalf * 32;
    const float* wfj = g_WF + (size_t)j * BB * DD;
    const float isc8 = isc * 0.8f, isc2 = isc * 0.2f, cL8 = cL * 0.8f;

    u64t k02p = 0, k08p = 0, hnp[8];
    if (PASS == 1) {
        k02p = pk2f(0.2f, 0.2f);
        k08p = pk2f(0.8f, 0.8f);
        u64t kn1 = pk2f(-1.0f, -1.0f);
        #pragma unroll
        for (int q = 0; q < 8; ++q) MUL2(hnp[q], hrp[q], kn1);
    }

    // prologue: this group stages its 4 rows of chunk 0
    #pragma unroll
    for (int q = 0; q < 4; ++q) {
        int idx = gtid + q * 128;            // 0..511
        int rl = idx >> 7, col = idx & 127;
        sv[0][bhalf * 4 + rl][col] = *(const float4*)&wfj[(size_t)(bs + rl) * DD + col * 4];
    }
    GBAR(bhalf);

    for (int c = 0; c < 8; ++c) {
        const int buf = c & 1;
        float4 nx[4];
        if (c < 7) {
            #pragma unroll
            for (int q = 0; q < 4; ++q) {
                int idx = gtid + q * 128;
                int rl = idx >> 7, col = idx & 127;
                nx[q] = *(const float4*)&wfj[(size_t)(bs + (c + 1) * 4 + rl) * DD + col * 4];
            }
        }
        float av[4];
        #pragma unroll
        for (int bi = 0; bi < 4; ++bi)
            av[bi] = __shfl_sync(FULLMASK, a0, c * 4 + bi);

        #pragma unroll
        for (int bi = 0; bi < 4; ++bi) {
            u64t sep = pk2f(0.0f, 0.0f), dotp = pk2f(0.0f, 0.0f);
            const float4* vr = sv[buf][bhalf * 4 + bi];

            if (PASS == 0) {
                const float a8 = av[bi] * isc8, a2 = av[bi] * isc2;
                const u64t ap8p = pk2f(a8, a8), ap2p = pk2f(a2, a2);
                #pragma unroll
                for (int k = 0; k < 4; ++k) {
                    float4 v = vr[k * 32 + lane];
                    u64t vp[2] = { pk2f(v.x, v.y), pk2f(v.z, v.w) };
                    #pragma unroll
                    for (int h2 = 0; h2 < 2; ++h2) {
                        u64t cur; MUL2(cur, ap8p, vp[h2]);
                        float2 cf = upk2f(cur);
                        float m0 = fminf(fmaxf(cf.x, -cL8), cL8);
                        float m1 = fminf(fmaxf(cf.y, -cL8), cL8);
                        u64t mp = pk2f(m0, m1);
                        u64t f; FMA2(f, ap2p, vp[h2], mp);
                        ADD2(hrp[k*2+h2], hrp[k*2+h2], f);
                        float2 ff = upk2f(f);
                        float e0 = ex2f_(ff.x), e1 = ex2f_(ff.y);
                        u64t ep = pk2f(e0, e1);
                        ADD2(sep, sep, ep);
                        FMA2(dotp, ep, vp[h2], dotp);
                    }
                }
            } else {
                const float avv = av[bi] * isc;
                const u64t app = pk2f(avv, avv);
                #pragma unroll
                for (int k = 0; k < 4; ++k) {
                    float4 v = vr[k * 32 + lane];
                    u64t vp[2] = { pk2f(v.x, v.y), pk2f(v.z, v.w) };
                    #pragma unroll
                    for (int h2 = 0; h2 < 2; ++h2) {
                        u64t u_; FMA2(u_, app, vp[h2], hnp[k*2+h2]);
                        float2 uf = upk2f(u_);
                        float m0 = fminf(fmaxf(uf.x, -cL), cL);
                        float m1 = fminf(fmaxf(uf.y, -cL), cL);
                        u64t mp = pk2f(m0, m1);
                        u64t t; FMA2(t, k02p, u_, hrp[k*2+h2]);
                        u64t f; FMA2(f, k08p, mp, t);
                        float2 ff = upk2f(f);
                        float e0 = ex2f_(ff.x), e1 = ex2f_(ff.y);
                        u64t ep = pk2f(e0, e1);
                        ADD2(sep, sep, ep);
                        FMA2(dotp, ep, vp[h2], dotp);
                    }
                }
            }
            float2 sf = upk2f(sep), df = upk2f(dotp);
            pw[bi * 2 + 0][lane] = sf.x + sf.y;
            pw[bi * 2 + 1][lane] = df.x + df.y;
        }
        __syncwarp();
        if (lane < 8) {
            const float4* pr = (const float4*)pw[lane];
            float4 p0 = pr[0], p1 = pr[1], p2 = pr[2], p3 = pr[3];
            float4 p4 = pr[4], p5 = pr[5], p6 = pr[6], p7 = pr[7];
            p0.x += p1.x; p0.y += p1.y; p0.z += p1.z; p0.w += p1.w;
            p2.x += p3.x; p2.y += p3.y; p2.z += p3.z; p2.w += p3.w;
            p4.x += p5.x; p4.y += p5.y; p4.z += p5.z; p4.w += p5.w;
            p6.x += p7.x; p6.y += p7.y; p6.z += p7.z; p6.w += p7.w;
            p0.x += p2.x; p0.y += p2.y; p0.z += p2.z; p0.w += p2.w;
            p4.x += p6.x; p4.y += p6.y; p4.z += p6.z; p4.w += p6.w;
            float val = (p0.x + p4.x) + (p0.y + p4.y) + (p0.z + p4.z) + (p0.w + p4.w);
            float sev = __shfl_sync(0xFFu, val, lane & ~1);
            if (lane & 1) {
                int bl = c * 4 + (lane >> 1);
                float sj = __ldg(&g_S[j * BB + bs + bl]);
                accout[(size_t)(bs + bl) * DD + d] = g * (val * frcp_(sev) + mb * sj);
            }
        }
        if (c < 7) {
            #pragma unroll
            for (int q = 0; q < 4; ++q) {
                int idx = gtid + q * 128;
                int rl = idx >> 7, col = idx & 127;
                sv[buf ^ 1][bhalf * 4 + rl][col] = nx[q];
            }
        }
        GBAR(bhalf);
    }
}

__global__ __launch_bounds__(256) void attn_kernel(const float* __restrict__ gamma,
                            const float* __restrict__ mbias,
                            const float* __restrict__ constraint)
{
    __shared__ __align__(16) float4 sv[2][8][128];      // 32 KB staging
    __shared__ __align__(16) float s_part[8][8][36];    // 9 KB partials
    const int i     = blockIdx.y;
    const int warp  = threadIdx.x >> 5;
    const int lane  = threadIdx.x & 31;
    const int bhalf = warp & 1;
    const int d     = blockIdx.x * 4 + (warp >> 1);
    const int j1 = (i == 0) ? 1 : 0;
    const int j2 = (i == 2) ? 1 : 2;

    const float cL  = constraint[i] * L2E;
    const float isc = INV_SCALE * L2E;
    const float a0 = __ldg(&g_WFT[((size_t)i * DD + d) * BB + bhalf * 32 + lane]);

    u64t hrp[8];
    {
        u64t zp = pk2f(0.0f, 0.0f);
        #pragma unroll
        for (int q = 0; q < 8; ++q) hrp[q] = zp;
    }

    {
        const float g1 = sigm_(gamma[i * MM + j1]);
        const float m1 = mbias[i * MM + j1];
        run_pass<0>(sv, s_part[warp], j1, d, lane, warp, bhalf, a0, hrp, cL, isc, g1, m1,
                    g_A1 + (size_t)i * BB * DD);
    }

    // ---- exchange hr across the warp pair (reuse sv buffer) ----
    __syncthreads();
    u64t* hx = (u64t*)sv;
    #pragma unroll
    for (int k = 0; k < 4; ++k) {
        float4* dst = (float4*)&hx[warp * 256 + (k * 32 + lane) * 2];
        float2 h01 = upk2f(hrp[k*2+0]), h23 = upk2f(hrp[k*2+1]);
        *dst = make_float4(h01.x, h01.y, h23.x, h23.y);
    }
    __syncthreads();
    {
        const int p = warp ^ 1;
        u64t k320 = pk2f(1.0f/320.0f, 1.0f/320.0f);
        #pragma unroll
        for (int k = 0; k < 4; ++k) {
            float4 hp = *(const float4*)&hx[p * 256 + (k * 32 + lane) * 2];
            u64t hp0 = pk2f(hp.x, hp.y), hp1 = pk2f(hp.z, hp.w);
            u64t s0, s1;
            ADD2(s0, hrp[k*2+0], hp0);
            ADD2(s1, hrp[k*2+1], hp1);
            MUL2(hrp[k*2+0], s0, k320);
            MUL2(hrp[k*2+1], s1, k320);
        }
    }
    __syncthreads();

    {
        const float g2 = sigm_(gamma[i * MM + j2]);
        const float m2 = mbias[i * MM + j2];
        run_pass<1>(sv, s_part[warp], j2, d, lane, warp, bhalf, a0, hrp, cL, isc, g2, m2,
                    g_A2 + (size_t)i * BB * DD);
    }
}

// ================= K5: combine + attention weights =================
__global__ void combine_kernel(float* __restrict__ out,
                               const float* __restrict__ gamma,
                               int out_size)
{
    int idx = blockIdx.x * blockDim.x + threadIdx.x;
    const int NBD = BB * DD;
    float w = (g_WF[idx] + g_WF[NBD + idx] + g_WF[2*NBD + idx]) * (1.0f / 3.0f);
    float a = g_A1[idx] + g_A1[NBD + idx] + g_A1[2*NBD + idx]
            + g_A2[idx] + g_A2[NBD + idx] + g_A2[2*NBD + idx];
    out[idx] = w + a * (1.0f / 6.0f);

    if (idx < MM && out_size >= NBD + MM) {
        float sc[MM];
        #pragma unroll
        for (int ii = 0; ii < MM; ++ii) {
            int j1 = (ii == 0) ? 1 : 0;
            int j2 = (ii == 2) ? 1 : 2;
            sc[ii] = 0.5f * (sigm_(gamma[ii * MM + j1]) + sigm_(gamma[ii * MM + j2]));
        }
        float mx = fmaxf(sc[0], fmaxf(sc[1], sc[2]));
        float e0 = ex2f_((sc[0] - mx) * L2E);
        float e1 = ex2f_((sc[1] - mx) * L2E);
        float e2 = ex2f_((sc[2] - mx) * L2E);
        float inv = frcp_(e0 + e1 + e2);
        float ei = (idx == 0) ? e0 : ((idx == 1) ? e1 : e2);
        out[NBD + idx] = ei * inv;
    }
}

// ================= launch =================
extern "C" void kernel_launch(void* const* d_in, const int* in_sizes, int n_in,
                              void* d_out, int out_size)
{
    const float* x      = (const float*)d_in[0];
    const float* proj_W = (const float*)d_in[1];
    const float* proj_b = (const float*)d_in[2];
    const float* ln_g   = (const float*)d_in[3];
    const float* ln_b   = (const float*)d_in[4];
    const float* imp_W1 = (const float*)d_in[5];
    const float* imp_b1 = (const float*)d_in[6];
    const float* imp_W2 = (const float*)d_in[7];
    const float* imp_b2 = (const float*)d_in[8];
    const float* gamma  = (const float*)d_in[9];
    const float* mbias  = (const float*)d_in[10];
    const float* constr = (const float*)d_in[11];
    float* out = (float*)d_out;

    // 1) y = x @ proj_W^T (split-K 8, 192 blocks, 2/SM co-resident) + grid-sync + LN
    k1_gemm1_ln<<<dim3(8, NSPL, MM), 256>>>(x, proj_W, proj_b, ln_g, ln_b);
    // 2) HA = relu(proj @ W1^T + b1)
    gemm_hidden_kernel<<<dim3(16, MM), 128>>>(imp_W1, imp_b1);
    // 3) CW = HA @ W2^T fused with wf epilogue
    gemm_cw_wf_kernel<<<dim3(16, MM), 256>>>(imp_W2, imp_b2);
    // 4) merged attention (profiled slot)
    attn_kernel<<<dim3(128, MM), 256>>>(gamma, mbias, constr);
    // 5) combine
    combine_kernel<<<64, 512>>>(out, gamma, out_size);
}

// round 10
// speedup vs baseline: 2.2413x; 1.0681x over previous
#include <cuda_runtime.h>
#include <cstdint>

#define FULLMASK 0xffffffffu
#define MM 3
#define BB 64
#define DD 512
#define DQ 128
#define L2E 1.4426950408889634f
#define INV_SCALE 0.044194173824159216f   /* 1/sqrt(512) */
#define NSPL 8
#define K1_BLOCKS (8 * NSPL * MM)   /* 192; 2-per-SM co-resident */
#define K4_BLOCKS (128 * MM)        /* 384; 3-per-SM via launch_bounds */

typedef unsigned long long u64t;

#define PK2(out, lo, hi)  asm("mov.b64 %0, {%1, %2};" : "=l"(out) : "f"(lo), "f"(hi))
#define UPK2(lo, hi, in)  asm("mov.b64 {%0, %1}, %2;" : "=f"(lo), "=f"(hi) : "l"(in))
#define MUL2(out, a, b)   asm("mul.rn.f32x2 %0, %1, %2;" : "=l"(out) : "l"(a), "l"(b))
#define ADD2(out, a, b)   asm("add.rn.f32x2 %0, %1, %2;" : "=l"(out) : "l"(a), "l"(b))
#define FMA2(out, a, b, c) asm("fma.rn.f32x2 %0, %1, %2, %3;" : "=l"(out) : "l"(a), "l"(b), "l"(c))

// ---------------- scratch ----------------
__device__ float g_Y4[NSPL * MM * BB * DD];
__device__ float g_P [MM * BB * DD];
__device__ float g_HA[MM * BB * DQ];
__device__ float g_WF[MM * BB * DD];
__device__ float g_WFT[MM * DD * BB];
__device__ float g_S [MM * BB];
__device__ float g_A1[MM * BB * DD];
__device__ float g_A2[MM * BB * DD];
__device__ unsigned g_bar1;
__device__ unsigned g_bar2;

__device__ __forceinline__ float ex2f_(float x) {
    float r; asm("ex2.approx.ftz.f32 %0, %1;" : "=f"(r) : "f"(x)); return r;
}
__device__ __forceinline__ float frcp_(float x) {
    float r; asm("rcp.approx.ftz.f32 %0, %1;" : "=f"(r) : "f"(x)); return r;
}
__device__ __forceinline__ float sigm_(float x) {
    return frcp_(1.0f + ex2f_(-x * L2E));
}

// ================= K1: gemm1 (split-K 8) + grid barrier + LN/ReLU =================
__global__ __launch_bounds__(256, 2) void k1_gemm1_ln(
    const float* __restrict__ X, const float* __restrict__ W,
    const float* __restrict__ pb, const float* __restrict__ lg,
    const float* __restrict__ lb)
{
    __shared__ float As[16][64];
    __shared__ float Bs[16][64];
    __shared__ float red[18];

    const int i  = blockIdx.z;
    const int n0 = blockIdx.x * 64;
    const int k0 = blockIdx.y * 64;
    const int tid = threadIdx.x;
    const int tx = tid & 15, ty = tid >> 4;

    const float* Xb = X + (size_t)i * BB * DD;
    const float* Wb = W + (size_t)i * DD * DD;

    float acc[4][4] = {};
    for (int kk = 0; kk < 64; kk += 16) {
        {
            int r  = tid >> 2;
            int c4 = (tid & 3) * 4;
            float4 xa = *(const float4*)&Xb[(size_t)r * DD + k0 + kk + c4];
            As[c4+0][r] = xa.x; As[c4+1][r] = xa.y; As[c4+2][r] = xa.z; As[c4+3][r] = xa.w;
            float4 wa = *(const float4*)&Wb[(size_t)(n0 + r) * DD + k0 + kk + c4];
            Bs[c4+0][r] = wa.x; Bs[c4+1][r] = wa.y; Bs[c4+2][r] = wa.z; Bs[c4+3][r] = wa.w;
        }
        __syncthreads();
        #pragma unroll
        for (int p = 0; p < 16; ++p) {
            float4 a4 = *(const float4*)&As[p][ty * 4];
            float4 b4 = *(const float4*)&Bs[p][tx * 4];
            float av[4] = {a4.x, a4.y, a4.z, a4.w};
            float bv[4] = {b4.x, b4.y, b4.z, b4.w};
            #pragma unroll
            for (int m2 = 0; m2 < 4; ++m2)
                #pragma unroll
                for (int n2 = 0; n2 < 4; ++n2)
                    acc[m2][n2] = fmaf(av[m2], bv[n2], acc[m2][n2]);
        }
        __syncthreads();
    }
    {
        float* Cout = g_Y4 + (size_t)blockIdx.y * (MM * BB * DD) + (size_t)i * BB * DD;
        #pragma unroll
        for (int m2 = 0; m2 < 4; ++m2) {
            int b = ty * 4 + m2;
            float4 v = make_float4(acc[m2][0], acc[m2][1], acc[m2][2], acc[m2][3]);
            *(float4*)&Cout[(size_t)b * DD + n0 + tx * 4] = v;
        }
    }

    __threadfence();
    __syncthreads();
    if (tid == 0) {
        unsigned old = atomicAdd(&g_bar1, 1u);
        unsigned target = (old / K1_BLOCKS + 1u) * K1_BLOCKS;
        while ((int)(*(volatile unsigned*)&g_bar1 - target) < 0) {
            __nanosleep(32);
        }
    }
    __syncthreads();

    const int flat = (blockIdx.z * NSPL + blockIdx.y) * 8 + blockIdx.x;  // 0..191
    const int warp = tid >> 5, lane = tid & 31;
    if (flat == 0 && tid < MM * BB) g_S[tid] = 0.0f;

    const int row = flat;
    const int i2  = row >> 6;
    const size_t base = (size_t)row * DD;
    const int e0 = tid, e1 = tid + 256;

    float y0 = pb[i2 * DD + e0];
    float y1 = pb[i2 * DD + e1];
    #pragma unroll
    for (int s = 0; s < NSPL; ++s) {
        y0 += g_Y4[(size_t)s * MM * BB * DD + base + e0];
        y1 += g_Y4[(size_t)s * MM * BB * DD + base + e1];
    }
    float s = y0 + y1, q = y0 * y0 + y1 * y1;
    #pragma unroll
    for (int off = 16; off; off >>= 1) {
        s += __shfl_xor_sync(FULLMASK, s, off);
        q += __shfl_xor_sync(FULLMASK, q, off);
    }
    if (lane == 0) { red[warp] = s; red[8 + warp] = q; }
    __syncthreads();
    if (warp == 0) {
        float s2 = red[lane & 7], q2 = red[8 + (lane & 7)];
        #pragma unroll
        for (int off = 4; off; off >>= 1) {
            s2 += __shfl_xor_sync(FULLMASK, s2, off);
            q2 += __shfl_xor_sync(FULLMASK, q2, off);
        }
        if (lane == 0) { red[16] = s2; red[17] = q2; }
    }
    __syncthreads();
    float mu  = red[16] * (1.0f / DD);
    float var = red[17] * (1.0f / DD) - mu * mu;
    float rs  = rsqrtf(var + 1e-5f);
    float p0 = (y0 - mu) * rs * lg[i2 * DD + e0] + lb[i2 * DD + e0];
    float p1 = (y1 - mu) * rs * lg[i2 * DD + e1] + lb[i2 * DD + e1];
    g_P[base + e0] = fmaxf(p0, 0.0f);
    g_P[base + e1] = fmaxf(p1, 0.0f);
}

// ================= K2: HA = relu(P @ W1^T + b1) =================
__global__ void gemm_hidden_kernel(const float* __restrict__ W1, const float* __restrict__ b1)
{
    const int i  = blockIdx.y;
    const int b0 = (blockIdx.x & 7) * 8;
    const int n0 = (blockIdx.x >> 3) * 64;
    const int tid = threadIdx.x;
    const int tx = tid & 15, ty = tid >> 4;

    __shared__ __align__(16) float As[32][8];
    __shared__ __align__(16) float Bs[32][64];

    const float* Pb = g_P + (size_t)i * BB * DD;
    const float* Wb = W1 + (size_t)i * DQ * DD;

    float acc[4] = {};
    for (int k0 = 0; k0 < DD; k0 += 32) {
        if (tid < 64) {
            int r = tid >> 3, q = tid & 7;
            float4 v = *(const float4*)&Pb[(size_t)(b0 + r) * DD + k0 + q * 4];
            As[q*4+0][r] = v.x; As[q*4+1][r] = v.y; As[q*4+2][r] = v.z; As[q*4+3][r] = v.w;
        }
        #pragma unroll
        for (int q = 0; q < 4; ++q) {
            int idx = tid * 4 + q;
            int nr = idx >> 3, kq = idx & 7;
            float4 v = *(const float4*)&Wb[(size_t)(n0 + nr) * DD + k0 + kq * 4];
            Bs[kq*4+0][nr] = v.x; Bs[kq*4+1][nr] = v.y; Bs[kq*4+2][nr] = v.z; Bs[kq*4+3][nr] = v.w;
        }
        __syncthreads();
        #pragma unroll
        for (int k = 0; k < 32; ++k) {
            float a = As[k][ty];
            float4 w4 = *(const float4*)&Bs[k][tx * 4];
            acc[0] = fmaf(a, w4.x, acc[0]);
            acc[1] = fmaf(a, w4.y, acc[1]);
            acc[2] = fmaf(a, w4.z, acc[2]);
            acc[3] = fmaf(a, w4.w, acc[3]);
        }
        __syncthreads();
    }
    float4 o;
    o.x = fmaxf(acc[0] + b1[i*DQ + n0 + tx*4 + 0], 0.0f);
    o.y = fmaxf(acc[1] + b1[i*DQ + n0 + tx*4 + 1], 0.0f);
    o.z = fmaxf(acc[2] + b1[i*DQ + n0 + tx*4 + 2], 0.0f);
    o.w = fmaxf(acc[3] + b1[i*DQ + n0 + tx*4 + 3], 0.0f);
    *(float4*)&g_HA[((size_t)i * BB + b0 + ty) * DQ + n0 + tx * 4] = o;
}

// ================= K3: CW = HA @ W2^T + fused wf epilogue =================
__global__ void gemm_cw_wf_kernel(const float* __restrict__ W2,
                                  const float* __restrict__ b2v)
{
    const int i  = blockIdx.y;
    const int n0 = blockIdx.x * 32;
    const int tid = threadIdx.x;
    const int tx = tid & 7, ty = tid >> 3;

    __shared__ __align__(16) float As2[64][DQ];
    __shared__ __align__(16) float Bs[DQ][36];

    #pragma unroll
    for (int q = 0; q < 8; ++q) {
        int idx = tid + q * 256;
        int b = idx >> 5, kq = idx & 31;
        float4 v = *(const float4*)&g_HA[((size_t)i * BB + b) * DQ + kq * 4];
        *(float4*)&As2[b][kq * 4] = v;
    }
    #pragma unroll
    for (int q = 0; q < 4; ++q) {
        int idx = tid + q * 256;
        int nr = idx >> 5, kq = idx & 31;
        float4 v = *(const float4*)&W2[((size_t)i * DD + n0 + nr) * DQ + kq * 4];
        Bs[kq*4+0][nr] = v.x; Bs[kq*4+1][nr] = v.y; Bs[kq*4+2][nr] = v.z; Bs[kq*4+3][nr] = v.w;
    }
    __syncthreads();

    float acc[2][4] = {};
    #pragma unroll 8
    for (int k4 = 0; k4 < 32; ++k4) {
        float4 a0 = *(const float4*)&As2[ty][k4 * 4];
        float4 a1 = *(const float4*)&As2[ty + 32][k4 * 4];
        float av0[4] = {a0.x, a0.y, a0.z, a0.w};
        float av1[4] = {a1.x, a1.y, a1.z, a1.w};
        #pragma unroll
        for (int q = 0; q < 4; ++q) {
            float4 b4 = *(const float4*)&Bs[k4 * 4 + q][tx * 4];
            float bv[4] = {b4.x, b4.y, b4.z, b4.w};
            #pragma unroll
            for (int n2 = 0; n2 < 4; ++n2) {
                acc[0][n2] = fmaf(av0[q], bv[n2], acc[0][n2]);
                acc[1][n2] = fmaf(av1[q], bv[n2], acc[1][n2]);
            }
        }
    }

    #pragma unroll
    for (int rr = 0; rr < 2; ++rr) {
        int b = ty + rr * 32;
        int n = n0 + tx * 4;
        float4 p4 = *(const float4*)&g_P[((size_t)i * BB + b) * DD + n];
        float pv[4] = {p4.x, p4.y, p4.z, p4.w};
        float w[4], srow = 0.0f;
        #pragma unroll
        for (int q = 0; q < 4; ++q) {
            float pre = acc[rr][q] + b2v[i * DD + n + q];
            w[q] = pv[q] * sigm_(pre);
            srow += w[q];
            g_WFT[((size_t)i * DD + n + q) * BB + b] = w[q];
        }
        *(float4*)&g_WF[((size_t)i * BB + b) * DD + n] = make_float4(w[0], w[1], w[2], w[3]);
        #pragma unroll
        for (int off = 4; off; off >>= 1)
            srow += __shfl_xor_sync(FULLMASK, srow, off);
        if (tx == 0) atomicAdd(&g_S[i * BB + b], srow);
    }
}

// ================= K4: merged pairwise attention + combine (R8 structure) =================
// block 256 = 8 warps: warp = d_local*2 + bhalf.  grid (128, MM) = 384, 3/SM single wave.

template<int PASS>
__device__ __forceinline__ void run_pass(float4 (*sv)[8][128],
                                         float (*pw)[36],
                                         int j, int d, int lane, int warp, int bhalf,
                                         float a0, u64t (&hrp)[8],
                                         float cL, float isc, float g, float mb,
                                         float* __restrict__ accout)
{
    const int tid = warp * 32 + lane;
    const int bs = bhalf * 32;
    const float* wfj = g_WF + (size_t)j * BB * DD;
    const float isc8 = isc * 0.8f, isc2 = isc * 0.2f, cL8 = cL * 0.8f;

    u64t k02p, k08p, hnp[8];
    if (PASS == 1) {
        PK2(k02p, 0.2f, 0.2f);
        PK2(k08p, 0.8f, 0.8f);
        u64t kn1; PK2(kn1, -1.0f, -1.0f);
        #pragma unroll
        for (int q = 0; q < 8; ++q) MUL2(hnp[q], hrp[q], kn1);
    }

    #pragma unroll
    for (int q = 0; q < 4; ++q) {
        int idx = tid + q * 256;
        int rl = idx >> 7, col = idx & 127;
        int grow = (rl >> 2) * 32 + (rl & 3);
        sv[0][rl][col] = *(const float4*)&wfj[(size_t)grow * DD + col * 4];
    }
    __syncthreads();

    for (int c = 0; c < 8; ++c) {
        const int buf = c & 1;
        float4 nx[4];
        if (c < 7) {
            #pragma unroll
            for (int q = 0; q < 4; ++q) {
                int idx = tid + q * 256;
                int rl = idx >> 7, col = idx & 127;
                int grow = (rl >> 2) * 32 + (c + 1) * 4 + (rl & 3);
                nx[q] = *(const float4*)&wfj[(size_t)grow * DD + col * 4];
            }
        }
        #pragma unroll
        for (int bi = 0; bi < 4; ++bi) {
            const int bl = c * 4 + bi;
            float a  = __shfl_sync(FULLMASK, a0, bl);

            u64t sep, dotp;
            { float z = 0.0f; PK2(sep, z, z); PK2(dotp, z, z); }
            const float4* vr = sv[buf][bhalf * 4 + bi];

            if (PASS == 0) {
                u64t ap8p, ap2p;
                { float a8 = a * isc8, a2 = a * isc2; PK2(ap8p, a8, a8); PK2(ap2p, a2, a2); }
                #pragma unroll
                for (int k = 0; k < 4; ++k) {
                    float4 v = vr[k * 32 + lane];
                    u64t vp[2]; PK2(vp[0], v.x, v.y); PK2(vp[1], v.z, v.w);
                    #pragma unroll
                    for (int h2 = 0; h2 < 2; ++h2) {
                        u64t cur; MUL2(cur, ap8p, vp[h2]);
                        float c0, c1; UPK2(c0, c1, cur);
                        float m0 = fminf(fmaxf(c0, -cL8), cL8);
                        float m1 = fminf(fmaxf(c1, -cL8), cL8);
                        u64t mp; PK2(mp, m0, m1);
                        u64t f; FMA2(f, ap2p, vp[h2], mp);
                        ADD2(hrp[k*2+h2], hrp[k*2+h2], f);
                        float f0, f1; UPK2(f0, f1, f);
                        float e0 = ex2f_(f0), e1 = ex2f_(f1);
                        u64t ep; PK2(ep, e0, e1);
                        ADD2(sep, sep, ep);
                        FMA2(dotp, ep, vp[h2], dotp);
                    }
                }
            } else {
                u64t app;
                { float av = a * isc; PK2(app, av, av); }
                #pragma unroll
                for (int k = 0; k < 4; ++k) {
                    float4 v = vr[k * 32 + lane];
                    u64t vp[2]; PK2(vp[0], v.x, v.y); PK2(vp[1], v.z, v.w);
                    #pragma unroll
                    for (int h2 = 0; h2 < 2; ++h2) {
                        u64t u_; FMA2(u_, app, vp[h2], hnp[k*2+h2]);
                        float u0, u1; UPK2(u0, u1, u_);
                        float m0 = fminf(fmaxf(u0, -cL), cL);
                        float m1 = fminf(fmaxf(u1, -cL), cL);
                        u64t mp; PK2(mp, m0, m1);
                        u64t t; FMA2(t, k02p, u_, hrp[k*2+h2]);
                        u64t f; FMA2(f, k08p, mp, t);
                        float f0, f1; UPK2(f0, f1, f);
                        float e0 = ex2f_(f0), e1 = ex2f_(f1);
                        u64t ep; PK2(ep, e0, e1);
                        ADD2(sep, sep, ep);
                        FMA2(dotp, ep, vp[h2], dotp);
                    }
                }
            }
            float sl, sh, dl, dh;
            UPK2(sl, sh, sep); UPK2(dl, dh, dotp);
            pw[bi * 2 + 0][lane] = sl + sh;
            pw[bi * 2 + 1][lane] = dl + dh;
        }
        __syncwarp();
        if (lane < 8) {
            const float4* pr = (const float4*)pw[lane];
            float4 p0 = pr[0], p1 = pr[1], p2 = pr[2], p3 = pr[3];
            float4 p4 = pr[4], p5 = pr[5], p6 = pr[6], p7 = pr[7];
            p0.x += p1.x; p0.y += p1.y; p0.z += p1.z; p0.w += p1.w;
            p2.x += p3.x; p2.y += p3.y; p2.z += p3.z; p2.w += p3.w;
            p4.x += p5.x; p4.y += p5.y; p4.z += p5.z; p4.w += p5.w;
            p6.x += p7.x; p6.y += p7.y; p6.z += p7.z; p6.w += p7.w;
            p0.x += p2.x; p0.y += p2.y; p0.z += p2.z; p0.w += p2.w;
            p4.x += p6.x; p4.y += p6.y; p4.z += p6.z; p4.w += p6.w;
            float val = (p0.x + p4.x) + (p0.y + p4.y) + (p0.z + p4.z) + (p0.w + p4.w);
            float sev = __shfl_sync(0xFFu, val, lane & ~1);
            if (lane & 1) {
                int bl = c * 4 + (lane >> 1);
                float sj = __ldg(&g_S[j * BB + bs + bl]);
                accout[(size_t)(bs + bl) * DD + d] = g * (val * frcp_(sev) + mb * sj);
            }
        }
        if (c < 7) {
            #pragma unroll
            for (int q = 0; q < 4; ++q) {
                int idx = tid + q * 256;
                int rl = idx >> 7, col = idx & 127;
                sv[buf ^ 1][rl][col] = nx[q];
            }
        }
        __syncthreads();
    }
}

__global__ __launch_bounds__(256, 3) void attn_combine_kernel(
    const float* __restrict__ gamma,
    const float* __restrict__ mbias,
    const float* __restrict__ constraint,
    float* __restrict__ out, int out_size)
{
    __shared__ __align__(16) float4 sv[2][8][128];      // 32 KB staging
    __shared__ __align__(16) float s_part[8][8][36];    // 9 KB partials
    const int i     = blockIdx.y;
    const int warp  = threadIdx.x >> 5;
    const int lane  = threadIdx.x & 31;
    const int bhalf = warp & 1;
    const int d     = blockIdx.x * 4 + (warp >> 1);
    const int tid   = threadIdx.x;
    const int j1 = (i == 0) ? 1 : 0;
    const int j2 = (i == 2) ? 1 : 2;

    const float cL  = constraint[i] * L2E;
    const float isc = INV_SCALE * L2E;
    const float a0 = __ldg(&g_WFT[((size_t)i * DD + d) * BB + bhalf * 32 + lane]);

    u64t hrp[8];
    { float z = 0.0f; u64t zp; PK2(zp, z, z);
      #pragma unroll
      for (int q = 0; q < 8; ++q) hrp[q] = zp; }

    {
        const float g1 = sigm_(gamma[i * MM + j1]);
        const float m1 = mbias[i * MM + j1];
        run_pass<0>(sv, s_part[warp], j1, d, lane, warp, bhalf, a0, hrp, cL, isc, g1, m1,
                    g_A1 + (size_t)i * BB * DD);
    }

    // ---- exchange hr across the warp pair (reuse sv buffer) ----
    __syncthreads();
    u64t* hx = (u64t*)sv;
    #pragma unroll
    for (int k = 0; k < 4; ++k) {
        float4* dst = (float4*)&hx[warp * 256 + (k * 32 + lane) * 2];
        float h0, h1, h2, h3;
        UPK2(h0, h1, hrp[k*2+0]); UPK2(h2, h3, hrp[k*2+1]);
        *dst = make_float4(h0, h1, h2, h3);
    }
    __syncthreads();
    {
        const int p = warp ^ 1;
        u64t k320; PK2(k320, (1.0f/320.0f), (1.0f/320.0f));
        #pragma unroll
        for (int k = 0; k < 4; ++k) {
            float4 hp = *(const float4*)&hx[p * 256 + (k * 32 + lane) * 2];
            u64t hp0, hp1; PK2(hp0, hp.x, hp.y); PK2(hp1, hp.z, hp.w);
            u64t s0, s1;
            ADD2(s0, hrp[k*2+0], hp0);
            ADD2(s1, hrp[k*2+1], hp1);
            MUL2(hrp[k*2+0], s0, k320);
            MUL2(hrp[k*2+1], s1, k320);
        }
    }
    __syncthreads();

    {
        const float g2 = sigm_(gamma[i * MM + j2]);
        const float m2 = mbias[i * MM + j2];
        run_pass<1>(sv, s_part[warp], j2, d, lane, warp, bhalf, a0, hrp, cL, isc, g2, m2,
                    g_A2 + (size_t)i * BB * DD);
    }

    // ---- grid barrier over all 384 blocks (3/SM co-resident by launch_bounds) ----
    __threadfence();
    __syncthreads();
    if (tid == 0) {
        unsigned old = atomicAdd(&g_bar2, 1u);
        unsigned target = (old / K4_BLOCKS + 1u) * K4_BLOCKS;
        while ((int)(*(volatile unsigned*)&g_bar2 - target) < 0) {
            __nanosleep(32);
        }
    }
    __syncthreads();

    // ---- combine phase: mode-0 blocks write the output ----
    if (i == 0) {
        const int idx = blockIdx.x * 256 + tid;   // 0..32767
        const int NBD = BB * DD;
        float w = (g_WF[idx] + g_WF[NBD + idx] + g_WF[2*NBD + idx]) * (1.0f / 3.0f);
        float a = g_A1[idx] + g_A1[NBD + idx] + g_A1[2*NBD + idx]
                + g_A2[idx] + g_A2[NBD + idx] + g_A2[2*NBD + idx];
        out[idx] = w + a * (1.0f / 6.0f);

        if (blockIdx.x == 0 && tid < MM && out_size >= NBD + MM) {
            float sc[MM];
            #pragma unroll
            for (int ii = 0; ii < MM; ++ii) {
                int ja = (ii == 0) ? 1 : 0;
                int jb = (ii == 2) ? 1 : 2;
                sc[ii] = 0.5f * (sigm_(gamma[ii * MM + ja]) + sigm_(gamma[ii * MM + jb]));
            }
            float mx = fmaxf(sc[0], fmaxf(sc[1], sc[2]));
            float e0 = ex2f_((sc[0] - mx) * L2E);
            float e1 = ex2f_((sc[1] - mx) * L2E);
            float e2 = ex2f_((sc[2] - mx) * L2E);
            float inv = frcp_(e0 + e1 + e2);
            float ei = (tid == 0) ? e0 : ((tid == 1) ? e1 : e2);
            out[NBD + tid] = ei * inv;
        }
    }
}

// ================= launch =================
extern "C" void kernel_launch(void* const* d_in, const int* in_sizes, int n_in,
                              void* d_out, int out_size)
{
    const float* x      = (const float*)d_in[0];
    const float* proj_W = (const float*)d_in[1];
    const float* proj_b = (const float*)d_in[2];
    const float* ln_g   = (const float*)d_in[3];
    const float* ln_b   = (const float*)d_in[4];
    const float* imp_W1 = (const float*)d_in[5];
    const float* imp_b1 = (const float*)d_in[6];
    const float* imp_W2 = (const float*)d_in[7];
    const float* imp_b2 = (const float*)d_in[8];
    const float* gamma  = (const float*)d_in[9];
    const float* mbias  = (const float*)d_in[10];
    const float* constr = (const float*)d_in[11];
    float* out = (float*)d_out;

    // 1) y = x @ proj_W^T (split-K 8) + grid-sync + LN/ReLU
    k1_gemm1_ln<<<dim3(8, NSPL, MM), 256>>>(x, proj_W, proj_b, ln_g, ln_b);
    // 2) HA = relu(proj @ W1^T + b1)
    gemm_hidden_kernel<<<dim3(16, MM), 128>>>(imp_W1, imp_b1);
    // 3) CW = HA @ W2^T fused with wf epilogue
    gemm_cw_wf_kernel<<<dim3(16, MM), 256>>>(imp_W2, imp_b2);
    // 4) merged attention + grid barrier + combine (single wave, 3/SM)
    attn_combine_kernel<<<dim3(128, MM), 256>>>(gamma, mbias, constr, out, out_size);
}